// round 1
// baseline (speedup 1.0000x reference)
#include <cuda_runtime.h>
#include <math.h>

#define B_ 4
#define N_ 2048
#define D_ 768
#define H_ 12
#define HD_ 64
#define SCALE_ 0.125f
#define FS 68  // flash smem row stride (68*4 bytes = 272 = 17*16 -> float4 aligned)

// Scratch (allocation-free: __device__ globals)
__device__ float g_Q[(size_t)B_*H_*N_*HD_];
__device__ float g_K[(size_t)B_*H_*N_*HD_];
__device__ float g_V[(size_t)B_*H_*N_*HD_];
__device__ float g_AO[(size_t)B_*N_*D_];

// ---------------------------------------------------------------------------
// Tiled SGEMM: C(M,Nn) = A(M,Kd) @ B(Kd,Nn). BM=BN=128, BK=16, 256 thr, 8x8/thr.
// EPI==1: A=x, scatter output into head-major g_Q/g_K/g_V.
// EPI==0: A=g_AO (attention out), add bias, write row-major C.
// ---------------------------------------------------------------------------
template<int EPI>
__global__ void __launch_bounds__(256)
sgemm_kernel(const float* __restrict__ A_in, const float* __restrict__ Bm,
             const float* __restrict__ bias, float* __restrict__ C,
             int M, int Kd, int Nn)
{
    const float* A = (EPI == 0) ? (const float*)g_AO : A_in;
    __shared__ float As[16][128];   // transposed A tile
    __shared__ float Bs[16][128];
    const int tid = threadIdx.x;
    const int tx = tid & 15, ty = tid >> 4;
    const int row0 = blockIdx.y * 128, col0 = blockIdx.x * 128;

    float acc[8][8];
#pragma unroll
    for (int i = 0; i < 8; i++)
#pragma unroll
        for (int j = 0; j < 8; j++) acc[i][j] = 0.f;

    const int a_row = tid >> 2;   // 0..63
    const int a_c4  = tid & 3;
    const int b_row = tid >> 5;   // 0..7
    const int b_c4  = tid & 31;

    for (int k0 = 0; k0 < Kd; k0 += 16) {
#pragma unroll
        for (int r = 0; r < 2; r++) {
            int ar = a_row + r * 64;
            float4 v = *(const float4*)&A[(size_t)(row0 + ar) * Kd + k0 + a_c4 * 4];
            As[a_c4 * 4 + 0][ar] = v.x;
            As[a_c4 * 4 + 1][ar] = v.y;
            As[a_c4 * 4 + 2][ar] = v.z;
            As[a_c4 * 4 + 3][ar] = v.w;
        }
#pragma unroll
        for (int r = 0; r < 2; r++) {
            int br = b_row + r * 8;
            *(float4*)&Bs[br][b_c4 * 4] =
                *(const float4*)&Bm[(size_t)(k0 + br) * Nn + col0 + b_c4 * 4];
        }
        __syncthreads();
#pragma unroll
        for (int kk = 0; kk < 16; kk++) {
            float af[8], bf[8];
            *(float4*)&af[0] = *(float4*)&As[kk][ty * 4];
            *(float4*)&af[4] = *(float4*)&As[kk][64 + ty * 4];
            *(float4*)&bf[0] = *(float4*)&Bs[kk][tx * 4];
            *(float4*)&bf[4] = *(float4*)&Bs[kk][64 + tx * 4];
#pragma unroll
            for (int i = 0; i < 8; i++)
#pragma unroll
                for (int j = 0; j < 8; j++) acc[i][j] += af[i] * bf[j];
        }
        __syncthreads();
    }

    // epilogue
#pragma unroll
    for (int i = 0; i < 8; i++) {
        int gr = row0 + ((i < 4) ? (ty * 4 + i) : (64 + ty * 4 + i - 4));
#pragma unroll
        for (int jg = 0; jg < 2; jg++) {
            int gc = col0 + jg * 64 + tx * 4;
            float4 v;
            v.x = acc[i][jg * 4 + 0]; v.y = acc[i][jg * 4 + 1];
            v.z = acc[i][jg * 4 + 2]; v.w = acc[i][jg * 4 + 3];
            if (EPI == 0) {
                v.x += bias[gc + 0]; v.y += bias[gc + 1];
                v.z += bias[gc + 2]; v.w += bias[gc + 3];
                *(float4*)&C[(size_t)gr * Nn + gc] = v;
            } else {
                int bb = gr >> 11;        // gr / 2048
                int ntok = gr & 2047;
                int which = gc / D_;
                int rem = gc - which * D_;
                int hh = rem >> 6;
                int hd = rem & 63;
                float* dst = (which == 0) ? g_Q : (which == 1) ? g_K : g_V;
                *(float4*)&dst[(((size_t)(bb * H_ + hh)) * N_ + ntok) * HD_ + hd] = v;
            }
        }
    }
}

// ---------------------------------------------------------------------------
// Flash attention: one (b,h,q-tile of 64) per block. Br=Bc=64, HD=64.
// Online softmax; O accumulated 4x4 per thread (16x16 thread grid).
// ---------------------------------------------------------------------------
__global__ void __launch_bounds__(256)
flash_kernel()
{
    extern __shared__ float sm[];
    float* Qt   = sm;              // [64][FS] transposed: Qt[k][r]
    float* Kt   = Qt + 64 * FS;    // [64][FS] transposed: Kt[k][c]
    float* Vs   = Kt + 64 * FS;    // [64][FS] natural:    Vs[c][d]
    float* Ps   = Vs + 64 * FS;    // [64][FS] probs:      Ps[r][c]
    float* sm_m = Ps + 64 * FS;    // [64]
    float* sm_l = sm_m + 64;       // [64]
    float* sm_a = sm_l + 64;       // [64]

    const int tid = threadIdx.x;
    const int tx = tid & 15, ty = tid >> 4;
    const int bh = blockIdx.y;
    const int qt = blockIdx.x;
    const float* Qg = g_Q + ((size_t)bh * N_ + qt * 64) * HD_;
    const float* Kg = g_K + (size_t)bh * N_ * HD_;
    const float* Vg = g_V + (size_t)bh * N_ * HD_;

    // load Q tile transposed
#pragma unroll
    for (int it = 0; it < 4; it++) {
        int idx = tid + it * 256;
        int n = idx >> 4, c4 = idx & 15;
        float4 v = *(const float4*)&Qg[n * HD_ + c4 * 4];
        Qt[(c4 * 4 + 0) * FS + n] = v.x;
        Qt[(c4 * 4 + 1) * FS + n] = v.y;
        Qt[(c4 * 4 + 2) * FS + n] = v.z;
        Qt[(c4 * 4 + 3) * FS + n] = v.w;
    }
    if (tid < 64) { sm_m[tid] = -INFINITY; sm_l[tid] = 0.f; }

    float o[4][4];
#pragma unroll
    for (int i = 0; i < 4; i++)
#pragma unroll
        for (int j = 0; j < 4; j++) o[i][j] = 0.f;

    for (int kt = 0; kt < N_ / 64; kt++) {
        __syncthreads();   // Kt/Vs/Ps from prev iter fully consumed
        // load K transposed + V natural
#pragma unroll
        for (int it = 0; it < 4; it++) {
            int idx = tid + it * 256;
            int n = idx >> 4, c4 = idx & 15;
            float4 v = *(const float4*)&Kg[(kt * 64 + n) * HD_ + c4 * 4];
            Kt[(c4 * 4 + 0) * FS + n] = v.x;
            Kt[(c4 * 4 + 1) * FS + n] = v.y;
            Kt[(c4 * 4 + 2) * FS + n] = v.z;
            Kt[(c4 * 4 + 3) * FS + n] = v.w;
            float4 w = *(const float4*)&Vg[(kt * 64 + n) * HD_ + c4 * 4];
            *(float4*)&Vs[n * FS + c4 * 4] = w;
        }
        __syncthreads();

        // S = (Q K^T) * scale  (outer product over k)
        float s[4][4];
#pragma unroll
        for (int i = 0; i < 4; i++)
#pragma unroll
            for (int j = 0; j < 4; j++) s[i][j] = 0.f;
#pragma unroll 16
        for (int k = 0; k < 64; k++) {
            float4 qv = *(float4*)&Qt[k * FS + ty * 4];
            float4 kv = *(float4*)&Kt[k * FS + tx * 4];
            float qa[4] = {qv.x, qv.y, qv.z, qv.w};
            float ka[4] = {kv.x, kv.y, kv.z, kv.w};
#pragma unroll
            for (int i = 0; i < 4; i++)
#pragma unroll
                for (int j = 0; j < 4; j++) s[i][j] += qa[i] * ka[j];
        }
#pragma unroll
        for (int i = 0; i < 4; i++) {
            float4 v;
            v.x = s[i][0] * SCALE_; v.y = s[i][1] * SCALE_;
            v.z = s[i][2] * SCALE_; v.w = s[i][3] * SCALE_;
            *(float4*)&Ps[(ty * 4 + i) * FS + tx * 4] = v;
        }
        __syncthreads();

        // online softmax: 4 lanes per row (lanes are consecutive within a warp)
        {
            int rr = tid >> 2, q4 = tid & 3;
            float mx = -INFINITY;
#pragma unroll
            for (int c = 0; c < 16; c++)
                mx = fmaxf(mx, Ps[rr * FS + q4 * 16 + c]);
            mx = fmaxf(mx, __shfl_xor_sync(0xffffffffu, mx, 1));
            mx = fmaxf(mx, __shfl_xor_sync(0xffffffffu, mx, 2));
            float m_old = sm_m[rr];
            float m_new = fmaxf(m_old, mx);
            float sum = 0.f;
#pragma unroll
            for (int c = 0; c < 16; c++) {
                float p = __expf(Ps[rr * FS + q4 * 16 + c] - m_new);
                Ps[rr * FS + q4 * 16 + c] = p;
                sum += p;
            }
            sum += __shfl_xor_sync(0xffffffffu, sum, 1);
            sum += __shfl_xor_sync(0xffffffffu, sum, 2);
            if (q4 == 0) {
                float a = __expf(m_old - m_new);  // first iter: exp(-inf)=0
                sm_a[rr] = a;
                sm_l[rr] = sm_l[rr] * a + sum;
                sm_m[rr] = m_new;
            }
        }
        __syncthreads();

        // O = O*alpha + P @ V
        float al[4];
#pragma unroll
        for (int i = 0; i < 4; i++) al[i] = sm_a[ty * 4 + i];
#pragma unroll
        for (int i = 0; i < 4; i++)
#pragma unroll
            for (int j = 0; j < 4; j++) o[i][j] *= al[i];
#pragma unroll 4
        for (int c4 = 0; c4 < 16; c4++) {
            float pr[4][4];
#pragma unroll
            for (int i = 0; i < 4; i++)
                *(float4*)&pr[i][0] = *(float4*)&Ps[(ty * 4 + i) * FS + c4 * 4];
#pragma unroll
            for (int cc = 0; cc < 4; cc++) {
                float4 vv = *(float4*)&Vs[(c4 * 4 + cc) * FS + tx * 4];
#pragma unroll
                for (int i = 0; i < 4; i++) {
                    o[i][0] += pr[i][cc] * vv.x;
                    o[i][1] += pr[i][cc] * vv.y;
                    o[i][2] += pr[i][cc] * vv.z;
                    o[i][3] += pr[i][cc] * vv.w;
                }
            }
        }
    }

    // normalize + write in (b, n, h*HD+hd) layout for the proj GEMM
    const int bb = bh / H_, hh = bh - bb * H_;
#pragma unroll
    for (int i = 0; i < 4; i++) {
        float inv = 1.f / sm_l[ty * 4 + i];
        int ntok = qt * 64 + ty * 4 + i;
        float4 v;
        v.x = o[i][0] * inv; v.y = o[i][1] * inv;
        v.z = o[i][2] * inv; v.w = o[i][3] * inv;
        *(float4*)&g_AO[((size_t)(bb * N_ + ntok)) * D_ + hh * HD_ + tx * 4] = v;
    }
}

// ---------------------------------------------------------------------------
// q_attn: exact softmax row for q=0 of each (b,h). 48 blocks x 256 threads.
// ---------------------------------------------------------------------------
__global__ void __launch_bounds__(256)
qattn_kernel(float* __restrict__ out1)
{
    const int bh = blockIdx.x;
    __shared__ float q0[64];
    __shared__ float red[256];
    const int tid = threadIdx.x;
    if (tid < 64) q0[tid] = g_Q[((size_t)bh * N_) * HD_ + tid];
    __syncthreads();

    float sv[8];
    float mx = -INFINITY;
#pragma unroll
    for (int it = 0; it < 8; it++) {
        int j = tid + it * 256;
        const float* kp = g_K + ((size_t)bh * N_ + j) * HD_;
        float s = 0.f;
#pragma unroll
        for (int k = 0; k < 64; k++) s += q0[k] * kp[k];
        s *= SCALE_;
        sv[it] = s;
        mx = fmaxf(mx, s);
    }
    red[tid] = mx; __syncthreads();
    for (int off = 128; off > 0; off >>= 1) {
        if (tid < off) red[tid] = fmaxf(red[tid], red[tid + off]);
        __syncthreads();
    }
    mx = red[0];
    __syncthreads();

    float sum = 0.f;
#pragma unroll
    for (int it = 0; it < 8; it++) { sv[it] = __expf(sv[it] - mx); sum += sv[it]; }
    red[tid] = sum; __syncthreads();
    for (int off = 128; off > 0; off >>= 1) {
        if (tid < off) red[tid] += red[tid + off];
        __syncthreads();
    }
    float inv = 1.f / red[0];
#pragma unroll
    for (int it = 0; it < 8; it++)
        out1[(size_t)bh * N_ + tid + it * 256] = sv[it] * inv;
}

// ---------------------------------------------------------------------------
extern "C" void kernel_launch(void* const* d_in, const int* in_sizes, int n_in,
                              void* d_out, int out_size)
{
    const float* x      = (const float*)d_in[0];
    const float* w_qkv  = (const float*)d_in[1];
    const float* w_proj = (const float*)d_in[2];
    const float* b_proj = (const float*)d_in[3];
    float* out = (float*)d_out;
    float* out_qattn = out + ((size_t)out_size - (size_t)B_ * H_ * N_);

    const int flash_smem = (4 * 64 * FS + 3 * 64) * (int)sizeof(float);  // 70400 B
    cudaFuncSetAttribute(flash_kernel,
                         cudaFuncAttributeMaxDynamicSharedMemorySize, flash_smem);

    // 1) QKV GEMM: (B*N, D) @ (D, 3D) -> scatter into g_Q/g_K/g_V
    {
        dim3 grid((3 * D_) / 128, (B_ * N_) / 128);
        sgemm_kernel<1><<<grid, 256>>>(x, w_qkv, nullptr, nullptr,
                                       B_ * N_, D_, 3 * D_);
    }
    // 2) Flash attention -> g_AO in (b, n, d) layout
    {
        dim3 grid(N_ / 64, B_ * H_);
        flash_kernel<<<grid, 256, flash_smem>>>();
    }
    // 3) q=0 attention row (second output)
    qattn_kernel<<<B_ * H_, 256>>>(out_qattn);
    // 4) Projection GEMM + bias -> first output
    {
        dim3 grid(D_ / 128, (B_ * N_) / 128);
        sgemm_kernel<0><<<grid, 256>>>(nullptr, w_proj, b_proj, out,
                                       B_ * N_, D_, D_);
    }
}

// round 4
// speedup vs baseline: 1.3085x; 1.3085x over previous
#include <cuda_runtime.h>
#include <math.h>
#include <stdint.h>

#define B_ 4
#define N_ 2048
#define D_ 768
#define H_ 12
#define HD_ 64
// 0.125 * log2(e): fold softmax scale + base-2 conversion into Q
#define QS_ 0.18033688011112042f
#define FS 68    // flash smem row stride (floats)
#define SA 36    // GEMM A-tile smem stride (floats): bank=(4*gid+tg)%32 distinct
#define SB 136   // GEMM B-tile smem stride (floats): [k][n] rows of 128 + 8 pad

// Scratch (allocation-free: __device__ globals)
__device__ float g_Q[(size_t)B_*H_*N_*HD_];
__device__ float g_K[(size_t)B_*H_*N_*HD_];
__device__ float g_V[(size_t)B_*H_*N_*HD_];
__device__ float g_AO[(size_t)B_*N_*D_];

// ============================ helpers ======================================
__device__ __forceinline__ uint32_t to_tf32(float x) {
    uint32_t r;
    asm("cvt.rna.tf32.f32 %0, %1;" : "=r"(r) : "f"(x));
    return r;
}
__device__ __forceinline__ void mma_tf32(float c[4], const uint32_t a[4],
                                         const uint32_t b[2]) {
    asm volatile(
        "mma.sync.aligned.m16n8k8.row.col.f32.tf32.tf32.f32 "
        "{%0,%1,%2,%3}, {%4,%5,%6,%7}, {%8,%9}, {%0,%1,%2,%3};"
        : "+f"(c[0]), "+f"(c[1]), "+f"(c[2]), "+f"(c[3])
        : "r"(a[0]), "r"(a[1]), "r"(a[2]), "r"(a[3]), "r"(b[0]), "r"(b[1]));
}

// FMA-pipe exp2 (Taylor deg-5 on [-0.5,0.5], rel err ~2.4e-6). |x| < ~30.
__device__ __forceinline__ float exp2f_fast(float x) {
    float k = rintf(x);
    float f = x - k;
    float p = 1.33335581464e-3f;
    p = fmaf(p, f, 9.61812910763e-3f);
    p = fmaf(p, f, 5.55041086648e-2f);
    p = fmaf(p, f, 2.40226506959e-1f);
    p = fmaf(p, f, 6.93147180560e-1f);
    p = fmaf(p, f, 1.0f);
    int ik = (int)k;
    return p * __int_as_float((ik + 127) << 23);
}

// ===========================================================================
// tf32 mma.sync GEMM: C(M,Nn) = A(M,768) @ W(768,Nn). 128x128 tile, BK=32.
// 256 thr = 8 warps (4 m x 2 n), warp tile 32x64 = 2x8 m16n8k8 fragments.
// EPI==1: A=x, scatter into head-major g_Q/g_K/g_V. EPI==0: A=g_AO, +bias.
// ===========================================================================
template<int EPI>
__global__ void __launch_bounds__(256)
mma_gemm(const float* __restrict__ A_in, const float* __restrict__ Bw,
         const float* __restrict__ bias, float* __restrict__ C,
         int M, int Kd, int Nn)
{
    const float* A = (EPI == 0) ? (const float*)g_AO : A_in;
    __shared__ float As[128 * SA];   // [m][k] tf32-rounded, 18432 B
    __shared__ float Bs[32 * SB];    // [k][n] tf32-rounded, 17408 B
    const int tid = threadIdx.x;
    const int wid = tid >> 5, lane = tid & 31;
    const int gid = lane >> 2, tg = lane & 3;
    const int warp_m = wid & 3, warp_n = wid >> 2;
    const int m0 = blockIdx.y * 128, n0 = blockIdx.x * 128;

    float c[2][8][4];
#pragma unroll
    for (int mt = 0; mt < 2; mt++)
#pragma unroll
        for (int nt = 0; nt < 8; nt++)
#pragma unroll
            for (int j = 0; j < 4; j++) c[mt][nt][j] = 0.f;

#pragma unroll 1
    for (int k0 = 0; k0 < Kd; k0 += 32) {
        // A tile: 128 m x 32 k. float4 along k.
#pragma unroll
        for (int it = 0; it < 4; it++) {
            int idx = tid + it * 256;
            int m = idx >> 3, k4 = idx & 7;
            float4 v = *(const float4*)&A[(size_t)(m0 + m) * Kd + k0 + k4 * 4];
            float* d = &As[m * SA + k4 * 4];
            d[0] = __uint_as_float(to_tf32(v.x));
            d[1] = __uint_as_float(to_tf32(v.y));
            d[2] = __uint_as_float(to_tf32(v.z));
            d[3] = __uint_as_float(to_tf32(v.w));
        }
        // B tile: 32 k x 128 n. float4 along n (coalesced).
#pragma unroll
        for (int it = 0; it < 4; it++) {
            int idx = tid + it * 256;
            int k = idx >> 5, n4 = idx & 31;
            float4 v = *(const float4*)&Bw[(size_t)(k0 + k) * Nn + n0 + n4 * 4];
            float* d = &Bs[k * SB + n4 * 4];
            d[0] = __uint_as_float(to_tf32(v.x));
            d[1] = __uint_as_float(to_tf32(v.y));
            d[2] = __uint_as_float(to_tf32(v.z));
            d[3] = __uint_as_float(to_tf32(v.w));
        }
        __syncthreads();

#pragma unroll
        for (int ks = 0; ks < 4; ks++) {
            const int kk = ks * 8;
            uint32_t a[2][4];
#pragma unroll
            for (int mt = 0; mt < 2; mt++) {
                int row = warp_m * 32 + mt * 16;
                a[mt][0] = __float_as_uint(As[(row + gid)     * SA + kk + tg]);
                a[mt][1] = __float_as_uint(As[(row + gid + 8) * SA + kk + tg]);
                a[mt][2] = __float_as_uint(As[(row + gid)     * SA + kk + tg + 4]);
                a[mt][3] = __float_as_uint(As[(row + gid + 8) * SA + kk + tg + 4]);
            }
            uint32_t b[8][2];
#pragma unroll
            for (int nt = 0; nt < 8; nt++) {
                int col = warp_n * 64 + nt * 8 + gid;
                b[nt][0] = __float_as_uint(Bs[(kk + tg)     * SB + col]);
                b[nt][1] = __float_as_uint(Bs[(kk + tg + 4) * SB + col]);
            }
#pragma unroll
            for (int mt = 0; mt < 2; mt++)
#pragma unroll
                for (int nt = 0; nt < 8; nt++)
                    mma_tf32(c[mt][nt], a[mt], b[nt]);
        }
        __syncthreads();
    }

    // epilogue: thread owns rows (r, r+8), col pair (col, col+1) per fragment
#pragma unroll
    for (int mt = 0; mt < 2; mt++) {
#pragma unroll
        for (int nt = 0; nt < 8; nt++) {
            int r0 = m0 + warp_m * 32 + mt * 16 + gid;
            int col = n0 + warp_n * 64 + nt * 8 + tg * 2;
#pragma unroll
            for (int h = 0; h < 2; h++) {
                int r = r0 + h * 8;
                float2 v;
                v.x = c[mt][nt][h * 2 + 0];
                v.y = c[mt][nt][h * 2 + 1];
                if (EPI == 0) {
                    v.x += bias[col + 0];
                    v.y += bias[col + 1];
                    *(float2*)&C[(size_t)r * Nn + col] = v;
                } else {
                    int bb = r >> 11, tok = r & 2047;
                    int which = col / D_;
                    int rem = col - which * D_;
                    int hh = rem >> 6, hd = rem & 63;
                    float* dst = (which == 0) ? g_Q : (which == 1) ? g_K : g_V;
                    *(float2*)&dst[(((size_t)(bb * H_ + hh)) * N_ + tok) * HD_ + hd] = v;
                }
            }
        }
    }
}

// ===========================================================================
// Flash attention (fp32 FFMA, no-max softmax, FMA-pipe exp2).
// One (b,h,q-tile of 64) per block. Scale+log2e folded into Q.
// ===========================================================================
__global__ void __launch_bounds__(256)
flash_kernel()
{
    extern __shared__ float sm[];
    float* Qt   = sm;              // [64][FS] transposed: Qt[k][r]  (pre-scaled)
    float* Kt   = Qt + 64 * FS;    // [64][FS] transposed: Kt[k][c]
    float* Vs   = Kt + 64 * FS;    // [64][FS] natural:    Vs[c][d]
    float* Ps   = Vs + 64 * FS;    // [64][FS] probs:      Ps[r][c]
    float* sm_l = Ps + 64 * FS;    // [64] row sums

    const int tid = threadIdx.x;
    const int tx = tid & 15, ty = tid >> 4;
    const int bh = blockIdx.y;
    const int qt = blockIdx.x;
    const float* Qg = g_Q + ((size_t)bh * N_ + qt * 64) * HD_;
    const float* Kg = g_K + (size_t)bh * N_ * HD_;
    const float* Vg = g_V + (size_t)bh * N_ * HD_;

    // load Q tile transposed, folding in scale * log2(e)
#pragma unroll
    for (int it = 0; it < 4; it++) {
        int idx = tid + it * 256;
        int n = idx >> 4, c4 = idx & 15;
        float4 v = *(const float4*)&Qg[n * HD_ + c4 * 4];
        Qt[(c4 * 4 + 0) * FS + n] = v.x * QS_;
        Qt[(c4 * 4 + 1) * FS + n] = v.y * QS_;
        Qt[(c4 * 4 + 2) * FS + n] = v.z * QS_;
        Qt[(c4 * 4 + 3) * FS + n] = v.w * QS_;
    }
    if (tid < 64) sm_l[tid] = 0.f;

    float o[4][4];
#pragma unroll
    for (int i = 0; i < 4; i++)
#pragma unroll
        for (int j = 0; j < 4; j++) o[i][j] = 0.f;

    for (int kt = 0; kt < N_ / 64; kt++) {
        __syncthreads();
#pragma unroll
        for (int it = 0; it < 4; it++) {
            int idx = tid + it * 256;
            int n = idx >> 4, c4 = idx & 15;
            float4 v = *(const float4*)&Kg[(kt * 64 + n) * HD_ + c4 * 4];
            Kt[(c4 * 4 + 0) * FS + n] = v.x;
            Kt[(c4 * 4 + 1) * FS + n] = v.y;
            Kt[(c4 * 4 + 2) * FS + n] = v.z;
            Kt[(c4 * 4 + 3) * FS + n] = v.w;
            float4 w = *(const float4*)&Vg[(kt * 64 + n) * HD_ + c4 * 4];
            *(float4*)&Vs[n * FS + c4 * 4] = w;
        }
        __syncthreads();

        // S = Q K^T (log2-domain logits: scale already in Q)
        float s[4][4];
#pragma unroll
        for (int i = 0; i < 4; i++)
#pragma unroll
            for (int j = 0; j < 4; j++) s[i][j] = 0.f;
#pragma unroll 16
        for (int k = 0; k < 64; k++) {
            float4 qv = *(float4*)&Qt[k * FS + ty * 4];
            float4 kv = *(float4*)&Kt[k * FS + tx * 4];
            float qa[4] = {qv.x, qv.y, qv.z, qv.w};
            float ka[4] = {kv.x, kv.y, kv.z, kv.w};
#pragma unroll
            for (int i = 0; i < 4; i++)
#pragma unroll
                for (int j = 0; j < 4; j++) s[i][j] += qa[i] * ka[j];
        }

        // P = exp2(S) on registers; accumulate row sums (no max subtraction)
        float rs[4];
#pragma unroll
        for (int i = 0; i < 4; i++) {
            rs[i] = 0.f;
#pragma unroll
            for (int j = 0; j < 4; j++) {
                float p = exp2f_fast(s[i][j]);
                s[i][j] = p;
                rs[i] += p;
            }
        }
#pragma unroll
        for (int i = 0; i < 4; i++) {
            float v = rs[i];
            v += __shfl_xor_sync(0xffffffffu, v, 1);
            v += __shfl_xor_sync(0xffffffffu, v, 2);
            v += __shfl_xor_sync(0xffffffffu, v, 4);
            v += __shfl_xor_sync(0xffffffffu, v, 8);
            if (tx == 0) sm_l[ty * 4 + i] += v;
        }
#pragma unroll
        for (int i = 0; i < 4; i++) {
            float4 v;
            v.x = s[i][0]; v.y = s[i][1]; v.z = s[i][2]; v.w = s[i][3];
            *(float4*)&Ps[(ty * 4 + i) * FS + tx * 4] = v;
        }
        __syncthreads();

        // O += P @ V
#pragma unroll 4
        for (int c4 = 0; c4 < 16; c4++) {
            float pr[4][4];
#pragma unroll
            for (int i = 0; i < 4; i++)
                *(float4*)&pr[i][0] = *(float4*)&Ps[(ty * 4 + i) * FS + c4 * 4];
#pragma unroll
            for (int cc = 0; cc < 4; cc++) {
                float4 vv = *(float4*)&Vs[(c4 * 4 + cc) * FS + tx * 4];
#pragma unroll
                for (int i = 0; i < 4; i++) {
                    o[i][0] += pr[i][cc] * vv.x;
                    o[i][1] += pr[i][cc] * vv.y;
                    o[i][2] += pr[i][cc] * vv.z;
                    o[i][3] += pr[i][cc] * vv.w;
                }
            }
        }
    }

    const int bb = bh / H_, hh = bh - bb * H_;
#pragma unroll
    for (int i = 0; i < 4; i++) {
        float inv = 1.f / sm_l[ty * 4 + i];
        int ntok = qt * 64 + ty * 4 + i;
        float4 v;
        v.x = o[i][0] * inv; v.y = o[i][1] * inv;
        v.z = o[i][2] * inv; v.w = o[i][3] * inv;
        *(float4*)&g_AO[((size_t)(bb * N_ + ntok)) * D_ + hh * HD_ + tx * 4] = v;
    }
}

// ---------------------------------------------------------------------------
// q_attn: exact softmax row for q=0 of each (b,h). No max pass needed.
// ---------------------------------------------------------------------------
__global__ void __launch_bounds__(256)
qattn_kernel(float* __restrict__ out1)
{
    const int bh = blockIdx.x;
    __shared__ float q0[64];
    __shared__ float red[256];
    const int tid = threadIdx.x;
    if (tid < 64) q0[tid] = g_Q[((size_t)bh * N_) * HD_ + tid] * QS_;
    __syncthreads();

    float sv[8];
    float sum = 0.f;
#pragma unroll
    for (int it = 0; it < 8; it++) {
        int j = tid + it * 256;
        const float* kp = g_K + ((size_t)bh * N_ + j) * HD_;
        float s = 0.f;
#pragma unroll
        for (int k = 0; k < 64; k++) s += q0[k] * kp[k];
        sv[it] = exp2f_fast(s);
        sum += sv[it];
    }
    red[tid] = sum; __syncthreads();
    for (int off = 128; off > 0; off >>= 1) {
        if (tid < off) red[tid] += red[tid + off];
        __syncthreads();
    }
    float inv = 1.f / red[0];
#pragma unroll
    for (int it = 0; it < 8; it++)
        out1[(size_t)bh * N_ + tid + it * 256] = sv[it] * inv;
}

// ---------------------------------------------------------------------------
extern "C" void kernel_launch(void* const* d_in, const int* in_sizes, int n_in,
                              void* d_out, int out_size)
{
    const float* x      = (const float*)d_in[0];
    const float* w_qkv  = (const float*)d_in[1];
    const float* w_proj = (const float*)d_in[2];
    const float* b_proj = (const float*)d_in[3];
    float* out = (float*)d_out;
    float* out_qattn = out + ((size_t)out_size - (size_t)B_ * H_ * N_);

    const int flash_smem = (4 * 64 * FS + 64) * (int)sizeof(float);  // 69888 B
    cudaFuncSetAttribute(flash_kernel,
                         cudaFuncAttributeMaxDynamicSharedMemorySize, flash_smem);

    // 1) QKV GEMM (tf32 mma.sync): (8192,768)@(768,2304) -> g_Q/g_K/g_V
    {
        dim3 grid((3 * D_) / 128, (B_ * N_) / 128);
        mma_gemm<1><<<grid, 256>>>(x, w_qkv, nullptr, nullptr,
                                   B_ * N_, D_, 3 * D_);
    }
    // 2) Flash attention -> g_AO
    {
        dim3 grid(N_ / 64, B_ * H_);
        flash_kernel<<<grid, 256, flash_smem>>>();
    }
    // 3) q=0 attention row
    qattn_kernel<<<B_ * H_, 256>>>(out_qattn);
    // 4) Projection GEMM + bias (tf32 mma.sync)
    {
        dim3 grid(D_ / 128, (B_ * N_) / 128);
        mma_gemm<0><<<grid, 256>>>(nullptr, w_proj, b_proj, out,
                                   B_ * N_, D_, D_);
    }
}

// round 5
// speedup vs baseline: 3.0745x; 2.3497x over previous
#include <cuda_runtime.h>
#include <math.h>
#include <stdint.h>

#define B_ 4
#define N_ 2048
#define D_ 768
#define H_ 12
#define HD_ 64
// 0.125 * log2(e): fold softmax scale + base-2 conversion into Q
#define QS_ 0.18033688011112042f
#define SA 36    // GEMM A-tile smem stride
#define SB 136   // GEMM B-tile smem stride
#define LQ 68    // flash Q/P smem stride
#define LK 68    // flash K smem stride
#define LV 72    // flash V smem stride

// Scratch (allocation-free: __device__ globals)
__device__ float g_Q[(size_t)B_*H_*N_*HD_];
__device__ float g_K[(size_t)B_*H_*N_*HD_];
__device__ float g_V[(size_t)B_*H_*N_*HD_];
__device__ float g_AO[(size_t)B_*N_*D_];

// ============================ helpers ======================================
__device__ __forceinline__ uint32_t to_tf32(float x) {
    uint32_t r;
    asm("cvt.rna.tf32.f32 %0, %1;" : "=r"(r) : "f"(x));
    return r;
}
__device__ __forceinline__ float tf32r(float x) {
    return __uint_as_float(to_tf32(x));
}
__device__ __forceinline__ void mma_tf32(float c[4], const uint32_t a[4],
                                         const uint32_t b[2]) {
    asm volatile(
        "mma.sync.aligned.m16n8k8.row.col.f32.tf32.tf32.f32 "
        "{%0,%1,%2,%3}, {%4,%5,%6,%7}, {%8,%9}, {%0,%1,%2,%3};"
        : "+f"(c[0]), "+f"(c[1]), "+f"(c[2]), "+f"(c[3])
        : "r"(a[0]), "r"(a[1]), "r"(a[2]), "r"(a[3]), "r"(b[0]), "r"(b[1]));
}

// FMA-pipe exp2 (Taylor deg-5 on [-0.5,0.5], rel err ~2.4e-6). |x| < ~30.
__device__ __forceinline__ float exp2f_fast(float x) {
    float k = rintf(x);
    float f = x - k;
    float p = 1.33335581464e-3f;
    p = fmaf(p, f, 9.61812910763e-3f);
    p = fmaf(p, f, 5.55041086648e-2f);
    p = fmaf(p, f, 2.40226506959e-1f);
    p = fmaf(p, f, 6.93147180560e-1f);
    p = fmaf(p, f, 1.0f);
    int ik = (int)k;
    return p * __int_as_float((ik + 127) << 23);
}

// ===========================================================================
// tf32 mma.sync GEMM (unchanged from round 4, passing)
// ===========================================================================
template<int EPI>
__global__ void __launch_bounds__(256)
mma_gemm(const float* __restrict__ A_in, const float* __restrict__ Bw,
         const float* __restrict__ bias, float* __restrict__ C,
         int M, int Kd, int Nn)
{
    const float* A = (EPI == 0) ? (const float*)g_AO : A_in;
    __shared__ float As[128 * SA];
    __shared__ float Bs[32 * SB];
    const int tid = threadIdx.x;
    const int wid = tid >> 5, lane = tid & 31;
    const int gid = lane >> 2, tg = lane & 3;
    const int warp_m = wid & 3, warp_n = wid >> 2;
    const int m0 = blockIdx.y * 128, n0 = blockIdx.x * 128;

    float c[2][8][4];
#pragma unroll
    for (int mt = 0; mt < 2; mt++)
#pragma unroll
        for (int nt = 0; nt < 8; nt++)
#pragma unroll
            for (int j = 0; j < 4; j++) c[mt][nt][j] = 0.f;

#pragma unroll 1
    for (int k0 = 0; k0 < Kd; k0 += 32) {
#pragma unroll
        for (int it = 0; it < 4; it++) {
            int idx = tid + it * 256;
            int m = idx >> 3, k4 = idx & 7;
            float4 v = *(const float4*)&A[(size_t)(m0 + m) * Kd + k0 + k4 * 4];
            float* d = &As[m * SA + k4 * 4];
            d[0] = tf32r(v.x); d[1] = tf32r(v.y);
            d[2] = tf32r(v.z); d[3] = tf32r(v.w);
        }
#pragma unroll
        for (int it = 0; it < 4; it++) {
            int idx = tid + it * 256;
            int k = idx >> 5, n4 = idx & 31;
            float4 v = *(const float4*)&Bw[(size_t)(k0 + k) * Nn + n0 + n4 * 4];
            float* d = &Bs[k * SB + n4 * 4];
            d[0] = tf32r(v.x); d[1] = tf32r(v.y);
            d[2] = tf32r(v.z); d[3] = tf32r(v.w);
        }
        __syncthreads();

#pragma unroll
        for (int ks = 0; ks < 4; ks++) {
            const int kk = ks * 8;
            uint32_t a[2][4];
#pragma unroll
            for (int mt = 0; mt < 2; mt++) {
                int row = warp_m * 32 + mt * 16;
                a[mt][0] = __float_as_uint(As[(row + gid)     * SA + kk + tg]);
                a[mt][1] = __float_as_uint(As[(row + gid + 8) * SA + kk + tg]);
                a[mt][2] = __float_as_uint(As[(row + gid)     * SA + kk + tg + 4]);
                a[mt][3] = __float_as_uint(As[(row + gid + 8) * SA + kk + tg + 4]);
            }
            uint32_t b[8][2];
#pragma unroll
            for (int nt = 0; nt < 8; nt++) {
                int col = warp_n * 64 + nt * 8 + gid;
                b[nt][0] = __float_as_uint(Bs[(kk + tg)     * SB + col]);
                b[nt][1] = __float_as_uint(Bs[(kk + tg + 4) * SB + col]);
            }
#pragma unroll
            for (int mt = 0; mt < 2; mt++)
#pragma unroll
                for (int nt = 0; nt < 8; nt++)
                    mma_tf32(c[mt][nt], a[mt], b[nt]);
        }
        __syncthreads();
    }

#pragma unroll
    for (int mt = 0; mt < 2; mt++) {
#pragma unroll
        for (int nt = 0; nt < 8; nt++) {
            int r0 = m0 + warp_m * 32 + mt * 16 + gid;
            int col = n0 + warp_n * 64 + nt * 8 + tg * 2;
#pragma unroll
            for (int h = 0; h < 2; h++) {
                int r = r0 + h * 8;
                float2 v;
                v.x = c[mt][nt][h * 2 + 0];
                v.y = c[mt][nt][h * 2 + 1];
                if (EPI == 0) {
                    v.x += bias[col + 0];
                    v.y += bias[col + 1];
                    *(float2*)&C[(size_t)r * Nn + col] = v;
                } else {
                    int bb = r >> 11, tok = r & 2047;
                    int which = col / D_;
                    int rem = col - which * D_;
                    int hh = rem >> 6, hd = rem & 63;
                    float* dst = (which == 0) ? g_Q : (which == 1) ? g_K : g_V;
                    *(float2*)&dst[(((size_t)(bb * H_ + hh)) * N_ + tok) * HD_ + hd] = v;
                }
            }
        }
    }
}

// ===========================================================================
// Flash attention on tensor cores (tf32 mma.sync), no-max softmax.
// Br=128 q-rows/CTA, Bc=64 keys/iter, 8 warps x 16 rows. Q frags in regs;
// Q smem region reused as per-warp P buffer (warp-private rows).
// ===========================================================================
__global__ void __launch_bounds__(256, 2)
flash_mma_kernel()
{
    extern __shared__ float sm[];
    float* QPs = sm;                  // [128][LQ] : Q staging, then P
    float* Ks  = sm + 128 * LQ;       // [64][LK]
    float* Vs  = Ks + 64 * LK;        // [64][LV]

    const int tid = threadIdx.x;
    const int wid = tid >> 5, lane = tid & 31;
    const int gid = lane >> 2, tg = lane & 3;
    const int bh = blockIdx.y, qt = blockIdx.x;
    const int r0 = wid * 16;
    const float* Qg = g_Q + ((size_t)bh * N_ + qt * 128) * HD_;
    const float* Kg = g_K + (size_t)bh * N_ * HD_;
    const float* Vg = g_V + (size_t)bh * N_ * HD_;

    // stage Q (scaled by QS_, tf32-rounded)
#pragma unroll
    for (int it = 0; it < 8; it++) {
        int idx = tid + it * 256;          // 2048 float4
        int r = idx >> 4, c4 = idx & 15;
        float4 v = *(const float4*)&Qg[r * HD_ + c4 * 4];
        float* d = &QPs[r * LQ + c4 * 4];
        d[0] = tf32r(v.x * QS_); d[1] = tf32r(v.y * QS_);
        d[2] = tf32r(v.z * QS_); d[3] = tf32r(v.w * QS_);
    }
    __syncthreads();

    // per-warp Q fragments (held in registers for the whole kernel)
    uint32_t qf[8][4];
#pragma unroll
    for (int ks = 0; ks < 8; ks++) {
        int k = ks * 8;
        qf[ks][0] = __float_as_uint(QPs[(r0 + gid)     * LQ + k + tg]);
        qf[ks][1] = __float_as_uint(QPs[(r0 + gid + 8) * LQ + k + tg]);
        qf[ks][2] = __float_as_uint(QPs[(r0 + gid)     * LQ + k + tg + 4]);
        qf[ks][3] = __float_as_uint(QPs[(r0 + gid + 8) * LQ + k + tg + 4]);
    }

    float o[8][4];
#pragma unroll
    for (int nt = 0; nt < 8; nt++)
#pragma unroll
        for (int j = 0; j < 4; j++) o[nt][j] = 0.f;
    float l0 = 0.f, l1 = 0.f;

#pragma unroll 1
    for (int kt = 0; kt < N_ / 64; kt++) {
        __syncthreads();   // prev iter's Ks/Vs reads done (all warps)
        // load K->Ks, V->Vs (tf32-rounded)
#pragma unroll
        for (int it = 0; it < 4; it++) {
            int idx = tid + it * 256;      // 1024 float4
            int r = idx >> 4, c4 = idx & 15;
            float4 v = *(const float4*)&Kg[(kt * 64 + r) * HD_ + c4 * 4];
            float* d = &Ks[r * LK + c4 * 4];
            d[0] = tf32r(v.x); d[1] = tf32r(v.y);
            d[2] = tf32r(v.z); d[3] = tf32r(v.w);
            float4 w = *(const float4*)&Vg[(kt * 64 + r) * HD_ + c4 * 4];
            float* e = &Vs[r * LV + c4 * 4];
            e[0] = tf32r(w.x); e[1] = tf32r(w.y);
            e[2] = tf32r(w.z); e[3] = tf32r(w.w);
        }
        __syncthreads();

        float rs0 = 0.f, rs1 = 0.f;
        // S = Q K^T in two n32 halves (caps live accumulators at 16)
#pragma unroll
        for (int h = 0; h < 2; h++) {
            float c[4][4];
#pragma unroll
            for (int j = 0; j < 4; j++)
#pragma unroll
                for (int q = 0; q < 4; q++) c[j][q] = 0.f;
#pragma unroll
            for (int ks = 0; ks < 8; ks++) {
                int k = ks * 8;
#pragma unroll
                for (int j = 0; j < 4; j++) {
                    int n = (h * 4 + j) * 8 + gid;
                    uint32_t b[2];
                    b[0] = __float_as_uint(Ks[n * LK + k + tg]);
                    b[1] = __float_as_uint(Ks[n * LK + k + tg + 4]);
                    mma_tf32(c[j], qf[ks], b);
                }
            }
            // P = exp2(S); row partial sums; store P (tf32) into QPs
#pragma unroll
            for (int j = 0; j < 4; j++) {
                float e0 = exp2f_fast(c[j][0]);
                float e1 = exp2f_fast(c[j][1]);
                float e2 = exp2f_fast(c[j][2]);
                float e3 = exp2f_fast(c[j][3]);
                rs0 += e0 + e1;
                rs1 += e2 + e3;
                int colb = (h * 4 + j) * 8 + tg * 2;
                float2 p0; p0.x = tf32r(e0); p0.y = tf32r(e1);
                float2 p1; p1.x = tf32r(e2); p1.y = tf32r(e3);
                *(float2*)&QPs[(r0 + gid)     * LQ + colb] = p0;
                *(float2*)&QPs[(r0 + gid + 8) * LQ + colb] = p1;
            }
        }
        rs0 += __shfl_xor_sync(0xffffffffu, rs0, 1);
        rs0 += __shfl_xor_sync(0xffffffffu, rs0, 2);
        rs1 += __shfl_xor_sync(0xffffffffu, rs1, 1);
        rs1 += __shfl_xor_sync(0xffffffffu, rs1, 2);
        l0 += rs0;
        l1 += rs1;
        __syncwarp();

        // O += P @ V  (P warp-private rows of QPs)
#pragma unroll
        for (int ks = 0; ks < 8; ks++) {
            int k = ks * 8;
            uint32_t a[4];
            a[0] = __float_as_uint(QPs[(r0 + gid)     * LQ + k + tg]);
            a[1] = __float_as_uint(QPs[(r0 + gid + 8) * LQ + k + tg]);
            a[2] = __float_as_uint(QPs[(r0 + gid)     * LQ + k + tg + 4]);
            a[3] = __float_as_uint(QPs[(r0 + gid + 8) * LQ + k + tg + 4]);
#pragma unroll
            for (int nt = 0; nt < 8; nt++) {
                int n = nt * 8 + gid;
                uint32_t b[2];
                b[0] = __float_as_uint(Vs[(k + tg)     * LV + n]);
                b[1] = __float_as_uint(Vs[(k + tg + 4) * LV + n]);
                mma_tf32(o[nt], a, b);
            }
        }
    }

    // epilogue: normalize, write (b, n, h*64+hd) for proj GEMM
    const int bb = bh / H_, hh = bh - bb * H_;
    const float i0 = 1.f / l0, i1 = 1.f / l1;
    const int row_a = qt * 128 + r0 + gid;
    const int row_b = row_a + 8;
#pragma unroll
    for (int nt = 0; nt < 8; nt++) {
        int col = hh * HD_ + nt * 8 + tg * 2;
        float2 va; va.x = o[nt][0] * i0; va.y = o[nt][1] * i0;
        float2 vb; vb.x = o[nt][2] * i1; vb.y = o[nt][3] * i1;
        *(float2*)&g_AO[((size_t)(bb * N_ + row_a)) * D_ + col] = va;
        *(float2*)&g_AO[((size_t)(bb * N_ + row_b)) * D_ + col] = vb;
    }
}

// ---------------------------------------------------------------------------
// q_attn: exact fp32 softmax row for q=0 of each (b,h).
// ---------------------------------------------------------------------------
__global__ void __launch_bounds__(256)
qattn_kernel(float* __restrict__ out1)
{
    const int bh = blockIdx.x;
    __shared__ float q0[64];
    __shared__ float red[256];
    const int tid = threadIdx.x;
    if (tid < 64) q0[tid] = g_Q[((size_t)bh * N_) * HD_ + tid] * QS_;
    __syncthreads();

    float sv[8];
    float sum = 0.f;
#pragma unroll
    for (int it = 0; it < 8; it++) {
        int j = tid + it * 256;
        const float* kp = g_K + ((size_t)bh * N_ + j) * HD_;
        float s = 0.f;
#pragma unroll
        for (int k = 0; k < 64; k++) s += q0[k] * kp[k];
        sv[it] = exp2f_fast(s);
        sum += sv[it];
    }
    red[tid] = sum; __syncthreads();
    for (int off = 128; off > 0; off >>= 1) {
        if (tid < off) red[tid] += red[tid + off];
        __syncthreads();
    }
    float inv = 1.f / red[0];
#pragma unroll
    for (int it = 0; it < 8; it++)
        out1[(size_t)bh * N_ + tid + it * 256] = sv[it] * inv;
}

// ---------------------------------------------------------------------------
extern "C" void kernel_launch(void* const* d_in, const int* in_sizes, int n_in,
                              void* d_out, int out_size)
{
    const float* x      = (const float*)d_in[0];
    const float* w_qkv  = (const float*)d_in[1];
    const float* w_proj = (const float*)d_in[2];
    const float* b_proj = (const float*)d_in[3];
    float* out = (float*)d_out;
    float* out_qattn = out + ((size_t)out_size - (size_t)B_ * H_ * N_);

    const int flash_smem = (128 * LQ + 64 * LK + 64 * LV) * (int)sizeof(float); // 70656
    cudaFuncSetAttribute(flash_mma_kernel,
                         cudaFuncAttributeMaxDynamicSharedMemorySize, flash_smem);

    // 1) QKV GEMM (tf32 mma.sync) -> g_Q/g_K/g_V (head-major)
    {
        dim3 grid((3 * D_) / 128, (B_ * N_) / 128);
        mma_gemm<1><<<grid, 256>>>(x, w_qkv, nullptr, nullptr,
                                   B_ * N_, D_, 3 * D_);
    }
    // 2) Flash attention (tensor cores) -> g_AO
    {
        dim3 grid(N_ / 128, B_ * H_);
        flash_mma_kernel<<<grid, 256, flash_smem>>>();
    }
    // 3) q=0 attention row (fp32 exact)
    qattn_kernel<<<B_ * H_, 256>>>(out_qattn);
    // 4) Projection GEMM + bias (tf32 mma.sync)
    {
        dim3 grid(D_ / 128, (B_ * N_) / 128);
        mma_gemm<0><<<grid, 256>>>(nullptr, w_proj, b_proj, out,
                                   B_ * N_, D_, D_);
    }
}

// round 6
// speedup vs baseline: 3.3224x; 1.0806x over previous
#include <cuda_runtime.h>
#include <math.h>
#include <stdint.h>

#define B_ 4
#define N_ 2048
#define D_ 768
#define H_ 12
#define HD_ 64
// 0.125 * log2(e): fold softmax scale + base-2 conversion into Q
#define QS_ 0.18033688011112042f
#define SA 36    // GEMM A-tile smem stride
#define SB 136   // GEMM B-tile smem stride
#define LQ 68    // flash Q/P smem stride
#define LK 68    // flash K smem stride
#define LV 72    // flash V smem stride

// Scratch (allocation-free: __device__ globals), all tf32-pre-rounded
__device__ float g_X [(size_t)B_*N_*D_];
__device__ float g_Wq[(size_t)D_*3*D_];
__device__ float g_Wp[(size_t)D_*D_];
__device__ float g_Q [(size_t)B_*H_*N_*HD_];   // pre-scaled by QS_
__device__ float g_K [(size_t)B_*H_*N_*HD_];
__device__ float g_V [(size_t)B_*H_*N_*HD_];
__device__ float g_AO[(size_t)B_*N_*D_];

// ============================ helpers ======================================
__device__ __forceinline__ uint32_t to_tf32(float x) {
    uint32_t r;
    asm("cvt.rna.tf32.f32 %0, %1;" : "=r"(r) : "f"(x));
    return r;
}
__device__ __forceinline__ float tf32r(float x) {
    return __uint_as_float(to_tf32(x));
}
__device__ __forceinline__ uint32_t smem_u32(const void* p) {
    uint32_t a;
    asm("{ .reg .u64 t; cvta.to.shared.u64 t, %1; cvt.u32.u64 %0, t; }"
        : "=r"(a) : "l"(p));
    return a;
}
__device__ __forceinline__ void cp16(uint32_t dst, const void* src) {
    asm volatile("cp.async.cg.shared.global [%0], [%1], 16;"
                 :: "r"(dst), "l"(src));
}
__device__ __forceinline__ void cp_commit() {
    asm volatile("cp.async.commit_group;");
}
__device__ __forceinline__ void cp_wait0() {
    asm volatile("cp.async.wait_group 0;");
}
__device__ __forceinline__ void mma_tf32(float c[4], const uint32_t a[4],
                                         const uint32_t b[2]) {
    asm volatile(
        "mma.sync.aligned.m16n8k8.row.col.f32.tf32.tf32.f32 "
        "{%0,%1,%2,%3}, {%4,%5,%6,%7}, {%8,%9}, {%0,%1,%2,%3};"
        : "+f"(c[0]), "+f"(c[1]), "+f"(c[2]), "+f"(c[3])
        : "r"(a[0]), "r"(a[1]), "r"(a[2]), "r"(a[3]), "r"(b[0]), "r"(b[1]));
}

// FMA-pipe exp2 (Taylor deg-5 on [-0.5,0.5], rel err ~2.4e-6). |x| < ~30.
__device__ __forceinline__ float exp2f_fast(float x) {
    float k = rintf(x);
    float f = x - k;
    float p = 1.33335581464e-3f;
    p = fmaf(p, f, 9.61812910763e-3f);
    p = fmaf(p, f, 5.55041086648e-2f);
    p = fmaf(p, f, 2.40226506959e-1f);
    p = fmaf(p, f, 6.93147180560e-1f);
    p = fmaf(p, f, 1.0f);
    int ik = (int)k;
    return p * __int_as_float((ik + 127) << 23);
}

// ===========================================================================
// Pre-pass: tf32-round x, w_qkv, w_proj into device copies (float4 grid-stride)
// ===========================================================================
__global__ void __launch_bounds__(256)
cvt_prepass(const float* __restrict__ x, const float* __restrict__ wq,
            const float* __restrict__ wp)
{
    const int n1 = (B_ * N_ * D_) / 4;        // 1572864
    const int n2 = (D_ * 3 * D_) / 4;         // 442368
    const int n3 = (D_ * D_) / 4;             // 147456
    const int total = n1 + n2 + n3;
    for (int i = blockIdx.x * blockDim.x + threadIdx.x; i < total;
         i += gridDim.x * blockDim.x) {
        const float4* src; float4* dst; int j;
        if (i < n1)           { src = (const float4*)x;  dst = (float4*)g_X;  j = i; }
        else if (i < n1 + n2) { src = (const float4*)wq; dst = (float4*)g_Wq; j = i - n1; }
        else                  { src = (const float4*)wp; dst = (float4*)g_Wp; j = i - n1 - n2; }
        float4 v = src[j];
        v.x = tf32r(v.x); v.y = tf32r(v.y);
        v.z = tf32r(v.z); v.w = tf32r(v.w);
        dst[j] = v;
    }
}

// ===========================================================================
// tf32 mma.sync GEMM, cp.async 2-stage double-buffered. Inputs pre-rounded.
// 128x128 tile, BK=32, 8 warps (4m x 2n), warp tile 32x64.
// EPI==1: A=g_X, B=g_Wq -> scatter Q(xQS_,rounded)/K/V(rounded).
// EPI==0: A=g_AO, B=g_Wp, +bias -> C.
// ===========================================================================
#define GSTG (128 * SA + 32 * SB)   // floats per stage = 8960
template<int EPI>
__global__ void __launch_bounds__(256)
mma_gemm(const float* __restrict__ bias, float* __restrict__ C,
         int M, int Kd, int Nn)
{
    const float* A = (EPI == 0) ? (const float*)g_AO : (const float*)g_X;
    const float* Bw = (EPI == 0) ? (const float*)g_Wp : (const float*)g_Wq;
    extern __shared__ float smg[];
    const uint32_t s_u32 = smem_u32(smg);
    const int tid = threadIdx.x;
    const int wid = tid >> 5, lane = tid & 31;
    const int gid = lane >> 2, tg = lane & 3;
    const int warp_m = wid & 3, warp_n = wid >> 2;
    const int m0 = blockIdx.y * 128, n0 = blockIdx.x * 128;

    // per-thread cp.async indices
    const int am = tid >> 1, ak4 = (tid & 1) * 4;       // A: 2 rows' worth? no:
    // A tile: 128 rows x 32 k = 1024 float4; thread does 4: rows tid>>3? use same as before
    const int a_m = tid >> 3, a_k4 = tid & 7;           // 4 iters of +32 rows
    const int b_k = tid >> 5, b_n4 = tid & 31;          // 4 iters of +8 k

    float c[2][8][4];
#pragma unroll
    for (int mt = 0; mt < 2; mt++)
#pragma unroll
        for (int nt = 0; nt < 8; nt++)
#pragma unroll
            for (int j = 0; j < 4; j++) c[mt][nt][j] = 0.f;

    auto prefetch = [&](int stg, int k0) {
        uint32_t as_u = s_u32 + stg * GSTG * 4;
        uint32_t bs_u = as_u + 128 * SA * 4;
#pragma unroll
        for (int it = 0; it < 4; it++) {
            int m = a_m + it * 32;
            cp16(as_u + (m * SA + a_k4 * 4) * 4,
                 &A[(size_t)(m0 + m) * Kd + k0 + a_k4 * 4]);
        }
#pragma unroll
        for (int it = 0; it < 4; it++) {
            int k = b_k + it * 8;
            cp16(bs_u + (k * SB + b_n4 * 4) * 4,
                 &Bw[(size_t)(k0 + k) * Nn + n0 + b_n4 * 4]);
        }
        cp_commit();
    };

    const int ntiles = Kd / 32;
    prefetch(0, 0);
    int s = 0;
#pragma unroll 1
    for (int t = 0; t < ntiles; t++) {
        cp_wait0();
        __syncthreads();
        if (t + 1 < ntiles) prefetch(s ^ 1, (t + 1) * 32);
        const float* As = smg + s * GSTG;
        const float* Bs = As + 128 * SA;
#pragma unroll
        for (int ks = 0; ks < 4; ks++) {
            const int kk = ks * 8;
            uint32_t a[2][4];
#pragma unroll
            for (int mt = 0; mt < 2; mt++) {
                int row = warp_m * 32 + mt * 16;
                a[mt][0] = __float_as_uint(As[(row + gid)     * SA + kk + tg]);
                a[mt][1] = __float_as_uint(As[(row + gid + 8) * SA + kk + tg]);
                a[mt][2] = __float_as_uint(As[(row + gid)     * SA + kk + tg + 4]);
                a[mt][3] = __float_as_uint(As[(row + gid + 8) * SA + kk + tg + 4]);
            }
            uint32_t b[8][2];
#pragma unroll
            for (int nt = 0; nt < 8; nt++) {
                int col = warp_n * 64 + nt * 8 + gid;
                b[nt][0] = __float_as_uint(Bs[(kk + tg)     * SB + col]);
                b[nt][1] = __float_as_uint(Bs[(kk + tg + 4) * SB + col]);
            }
#pragma unroll
            for (int mt = 0; mt < 2; mt++)
#pragma unroll
                for (int nt = 0; nt < 8; nt++)
                    mma_tf32(c[mt][nt], a[mt], b[nt]);
        }
        s ^= 1;
        __syncthreads();
    }

#pragma unroll
    for (int mt = 0; mt < 2; mt++) {
#pragma unroll
        for (int nt = 0; nt < 8; nt++) {
            int r0 = m0 + warp_m * 32 + mt * 16 + gid;
            int col = n0 + warp_n * 64 + nt * 8 + tg * 2;
#pragma unroll
            for (int h = 0; h < 2; h++) {
                int r = r0 + h * 8;
                float2 v;
                v.x = c[mt][nt][h * 2 + 0];
                v.y = c[mt][nt][h * 2 + 1];
                if (EPI == 0) {
                    v.x += bias[col + 0];
                    v.y += bias[col + 1];
                    *(float2*)&C[(size_t)r * Nn + col] = v;
                } else {
                    int bb = r >> 11, tok = r & 2047;
                    int which = col / D_;
                    int rem = col - which * D_;
                    int hh = rem >> 6, hd = rem & 63;
                    float* dst = (which == 0) ? g_Q : (which == 1) ? g_K : g_V;
                    float sc = (which == 0) ? QS_ : 1.f;
                    v.x = tf32r(v.x * sc);
                    v.y = tf32r(v.y * sc);
                    *(float2*)&dst[(((size_t)(bb * H_ + hh)) * N_ + tok) * HD_ + hd] = v;
                }
            }
        }
    }
}

// ===========================================================================
// Flash attention on tensor cores, cp.async 2-stage K/V, no-max softmax.
// Br=128, Bc=64, 8 warps x 16 rows. Q frags in regs; Q smem reused as P.
// All inputs pre-rounded tf32 (Q pre-scaled).
// ===========================================================================
#define FSTG (64 * LK + 64 * LV)   // floats per K/V stage = 8960
__global__ void __launch_bounds__(256, 2)
flash_mma_kernel()
{
    extern __shared__ float sm[];
    float* QPs = sm;                       // [128][LQ] Q staging, then P
    float* KV0 = sm + 128 * LQ;            // 2 stages of (K [64][LK], V [64][LV])
    const uint32_t qps_u = smem_u32(QPs);
    const uint32_t kv_u  = smem_u32(KV0);

    const int tid = threadIdx.x;
    const int wid = tid >> 5, lane = tid & 31;
    const int gid = lane >> 2, tg = lane & 3;
    const int bh = blockIdx.y, qt = blockIdx.x;
    const int r0 = wid * 16;
    const float* Qg = g_Q + ((size_t)bh * N_ + qt * 128) * HD_;
    const float* Kg = g_K + (size_t)bh * N_ * HD_;
    const float* Vg = g_V + (size_t)bh * N_ * HD_;

    const int l_r = tid >> 4, l_c4 = tid & 15;   // K/V loader: 4 iters of +16 rows

    auto prefetch_kv = [&](int stg, int kt) {
        uint32_t ks_u = kv_u + stg * FSTG * 4;
        uint32_t vs_u = ks_u + 64 * LK * 4;
#pragma unroll
        for (int it = 0; it < 4; it++) {
            int r = l_r + it * 16;
            cp16(ks_u + (r * LK + l_c4 * 4) * 4,
                 &Kg[(size_t)(kt * 64 + r) * HD_ + l_c4 * 4]);
            cp16(vs_u + (r * LV + l_c4 * 4) * 4,
                 &Vg[(size_t)(kt * 64 + r) * HD_ + l_c4 * 4]);
        }
        cp_commit();
    };

    // stage Q via cp.async (already scaled+rounded)
#pragma unroll
    for (int it = 0; it < 8; it++) {
        int idx = tid + it * 256;
        int r = idx >> 4, c4 = idx & 15;
        cp16(qps_u + (r * LQ + c4 * 4) * 4, &Qg[r * HD_ + c4 * 4]);
    }
    cp_commit();
    prefetch_kv(0, 0);
    cp_wait0();
    __syncthreads();

    // per-warp Q fragments (warp-private rows; live whole kernel)
    uint32_t qf[8][4];
#pragma unroll
    for (int ks = 0; ks < 8; ks++) {
        int k = ks * 8;
        qf[ks][0] = __float_as_uint(QPs[(r0 + gid)     * LQ + k + tg]);
        qf[ks][1] = __float_as_uint(QPs[(r0 + gid + 8) * LQ + k + tg]);
        qf[ks][2] = __float_as_uint(QPs[(r0 + gid)     * LQ + k + tg + 4]);
        qf[ks][3] = __float_as_uint(QPs[(r0 + gid + 8) * LQ + k + tg + 4]);
    }

    float o[8][4];
#pragma unroll
    for (int nt = 0; nt < 8; nt++)
#pragma unroll
        for (int j = 0; j < 4; j++) o[nt][j] = 0.f;
    float l0 = 0.f, l1 = 0.f;

    int s = 0;
#pragma unroll 1
    for (int kt = 0; kt < N_ / 64; kt++) {
        if (kt > 0) { cp_wait0(); __syncthreads(); }
        if (kt + 1 < N_ / 64) prefetch_kv(s ^ 1, kt + 1);
        const float* Ks = KV0 + s * FSTG;
        const float* Vs = Ks + 64 * LK;

        float rs0 = 0.f, rs1 = 0.f;
        // S = Q K^T in two n32 halves
#pragma unroll
        for (int h = 0; h < 2; h++) {
            float cc[4][4];
#pragma unroll
            for (int j = 0; j < 4; j++)
#pragma unroll
                for (int q = 0; q < 4; q++) cc[j][q] = 0.f;
#pragma unroll
            for (int ks = 0; ks < 8; ks++) {
                int k = ks * 8;
#pragma unroll
                for (int j = 0; j < 4; j++) {
                    int n = (h * 4 + j) * 8 + gid;
                    uint32_t b[2];
                    b[0] = __float_as_uint(Ks[n * LK + k + tg]);
                    b[1] = __float_as_uint(Ks[n * LK + k + tg + 4]);
                    mma_tf32(cc[j], qf[ks], b);
                }
            }
#pragma unroll
            for (int j = 0; j < 4; j++) {
                float e0 = exp2f_fast(cc[j][0]);
                float e1 = exp2f_fast(cc[j][1]);
                float e2 = exp2f_fast(cc[j][2]);
                float e3 = exp2f_fast(cc[j][3]);
                rs0 += e0 + e1;
                rs1 += e2 + e3;
                int colb = (h * 4 + j) * 8 + tg * 2;
                float2 p0; p0.x = tf32r(e0); p0.y = tf32r(e1);
                float2 p1; p1.x = tf32r(e2); p1.y = tf32r(e3);
                *(float2*)&QPs[(r0 + gid)     * LQ + colb] = p0;
                *(float2*)&QPs[(r0 + gid + 8) * LQ + colb] = p1;
            }
        }
        rs0 += __shfl_xor_sync(0xffffffffu, rs0, 1);
        rs0 += __shfl_xor_sync(0xffffffffu, rs0, 2);
        rs1 += __shfl_xor_sync(0xffffffffu, rs1, 1);
        rs1 += __shfl_xor_sync(0xffffffffu, rs1, 2);
        l0 += rs0;
        l1 += rs1;
        __syncwarp();

        // O += P @ V  (P warp-private rows of QPs)
#pragma unroll
        for (int ks = 0; ks < 8; ks++) {
            int k = ks * 8;
            uint32_t a[4];
            a[0] = __float_as_uint(QPs[(r0 + gid)     * LQ + k + tg]);
            a[1] = __float_as_uint(QPs[(r0 + gid + 8) * LQ + k + tg]);
            a[2] = __float_as_uint(QPs[(r0 + gid)     * LQ + k + tg + 4]);
            a[3] = __float_as_uint(QPs[(r0 + gid + 8) * LQ + k + tg + 4]);
#pragma unroll
            for (int nt = 0; nt < 8; nt++) {
                int n = nt * 8 + gid;
                uint32_t b[2];
                b[0] = __float_as_uint(Vs[(k + tg)     * LV + n]);
                b[1] = __float_as_uint(Vs[(k + tg + 4) * LV + n]);
                mma_tf32(o[nt], a, b);
            }
        }
        s ^= 1;
    }

    // epilogue: normalize, tf32-round, write (b, n, h*64+hd) for proj GEMM
    const int bb = bh / H_, hh = bh - bb * H_;
    const float i0 = 1.f / l0, i1 = 1.f / l1;
    const int row_a = qt * 128 + r0 + gid;
    const int row_b = row_a + 8;
#pragma unroll
    for (int nt = 0; nt < 8; nt++) {
        int col = hh * HD_ + nt * 8 + tg * 2;
        float2 va; va.x = tf32r(o[nt][0] * i0); va.y = tf32r(o[nt][1] * i0);
        float2 vb; vb.x = tf32r(o[nt][2] * i1); vb.y = tf32r(o[nt][3] * i1);
        *(float2*)&g_AO[((size_t)(bb * N_ + row_a)) * D_ + col] = va;
        *(float2*)&g_AO[((size_t)(bb * N_ + row_b)) * D_ + col] = vb;
    }
}

// ---------------------------------------------------------------------------
// q_attn: softmax row for q=0 of each (b,h). g_Q pre-scaled, g_K rounded.
// ---------------------------------------------------------------------------
__global__ void __launch_bounds__(256)
qattn_kernel(float* __restrict__ out1)
{
    const int bh = blockIdx.x;
    __shared__ float q0[64];
    __shared__ float red[256];
    const int tid = threadIdx.x;
    if (tid < 64) q0[tid] = g_Q[((size_t)bh * N_) * HD_ + tid];
    __syncthreads();

    float sv[8];
    float sum = 0.f;
#pragma unroll
    for (int it = 0; it < 8; it++) {
        int j = tid + it * 256;
        const float* kp = g_K + ((size_t)bh * N_ + j) * HD_;
        float s = 0.f;
#pragma unroll
        for (int k = 0; k < 64; k++) s += q0[k] * kp[k];
        sv[it] = exp2f_fast(s);
        sum += sv[it];
    }
    red[tid] = sum; __syncthreads();
    for (int off = 128; off > 0; off >>= 1) {
        if (tid < off) red[tid] += red[tid + off];
        __syncthreads();
    }
    float inv = 1.f / red[0];
#pragma unroll
    for (int it = 0; it < 8; it++)
        out1[(size_t)bh * N_ + tid + it * 256] = sv[it] * inv;
}

// ---------------------------------------------------------------------------
extern "C" void kernel_launch(void* const* d_in, const int* in_sizes, int n_in,
                              void* d_out, int out_size)
{
    const float* x      = (const float*)d_in[0];
    const float* w_qkv  = (const float*)d_in[1];
    const float* w_proj = (const float*)d_in[2];
    const float* b_proj = (const float*)d_in[3];
    float* out = (float*)d_out;
    float* out_qattn = out + ((size_t)out_size - (size_t)B_ * H_ * N_);

    const int gemm_smem  = 2 * GSTG * (int)sizeof(float);            // 71680
    const int flash_smem = (128 * LQ + 2 * FSTG) * (int)sizeof(float); // 106496
    cudaFuncSetAttribute(mma_gemm<1>,
                         cudaFuncAttributeMaxDynamicSharedMemorySize, gemm_smem);
    cudaFuncSetAttribute(mma_gemm<0>,
                         cudaFuncAttributeMaxDynamicSharedMemorySize, gemm_smem);
    cudaFuncSetAttribute(flash_mma_kernel,
                         cudaFuncAttributeMaxDynamicSharedMemorySize, flash_smem);

    // 0) tf32 pre-round inputs
    cvt_prepass<<<2048, 256>>>(x, w_qkv, w_proj);
    // 1) QKV GEMM -> g_Q(xQS_)/g_K/g_V (head-major, tf32-rounded)
    {
        dim3 grid((3 * D_) / 128, (B_ * N_) / 128);
        mma_gemm<1><<<grid, 256, gemm_smem>>>(nullptr, nullptr,
                                              B_ * N_, D_, 3 * D_);
    }
    // 2) Flash attention (tensor cores, double-buffered) -> g_AO
    {
        dim3 grid(N_ / 128, B_ * H_);
        flash_mma_kernel<<<grid, 256, flash_smem>>>();
    }
    // 3) q=0 attention row
    qattn_kernel<<<B_ * H_, 256>>>(out_qattn);
    // 4) Projection GEMM + bias
    {
        dim3 grid(D_ / 128, (B_ * N_) / 128);
        mma_gemm<0><<<grid, 256, gemm_smem>>>(b_proj, out,
                                              B_ * N_, D_, D_);
    }
}

// round 7
// speedup vs baseline: 3.3858x; 1.0191x over previous
#include <cuda_runtime.h>
#include <math.h>
#include <stdint.h>

#define B_ 4
#define N_ 2048
#define D_ 768
#define H_ 12
#define HD_ 64
// 0.125 * log2(e): fold softmax scale + base-2 conversion into Q
#define QS_ 0.18033688011112042f
#define SA 36    // GEMM A-tile smem stride
#define SB 136   // GEMM B-tile smem stride
#define LQ 68    // flash Q/P smem stride
#define LK 68    // flash K smem stride
#define LV 72    // flash V smem stride

// Scratch (allocation-free: __device__ globals), all tf32-pre-rounded
__device__ float g_X [(size_t)B_*N_*D_];
__device__ float g_Wq[(size_t)D_*3*D_];
__device__ float g_Wp[(size_t)D_*D_];
__device__ float g_Q [(size_t)B_*H_*N_*HD_];   // pre-scaled by QS_
__device__ float g_K [(size_t)B_*H_*N_*HD_];
__device__ float g_V [(size_t)B_*H_*N_*HD_];
__device__ float g_AO[(size_t)B_*N_*D_];
__device__ float g_PS[48 * 8];                 // qattn partial sums

// ============================ helpers ======================================
__device__ __forceinline__ uint32_t to_tf32(float x) {
    uint32_t r;
    asm("cvt.rna.tf32.f32 %0, %1;" : "=r"(r) : "f"(x));
    return r;
}
__device__ __forceinline__ float tf32r(float x) {
    return __uint_as_float(to_tf32(x));
}
__device__ __forceinline__ uint32_t smem_u32(const void* p) {
    uint32_t a;
    asm("{ .reg .u64 t; cvta.to.shared.u64 t, %1; cvt.u32.u64 %0, t; }"
        : "=r"(a) : "l"(p));
    return a;
}
__device__ __forceinline__ void cp16(uint32_t dst, const void* src) {
    asm volatile("cp.async.cg.shared.global [%0], [%1], 16;"
                 :: "r"(dst), "l"(src));
}
__device__ __forceinline__ void cp_commit() {
    asm volatile("cp.async.commit_group;");
}
__device__ __forceinline__ void cp_wait0() {
    asm volatile("cp.async.wait_group 0;");
}
__device__ __forceinline__ void mma_tf32(float c[4], const uint32_t a[4],
                                         const uint32_t b[2]) {
    asm volatile(
        "mma.sync.aligned.m16n8k8.row.col.f32.tf32.tf32.f32 "
        "{%0,%1,%2,%3}, {%4,%5,%6,%7}, {%8,%9}, {%0,%1,%2,%3};"
        : "+f"(c[0]), "+f"(c[1]), "+f"(c[2]), "+f"(c[3])
        : "r"(a[0]), "r"(a[1]), "r"(a[2]), "r"(a[3]), "r"(b[0]), "r"(b[1]));
}

// FMA-pipe exp2 (Taylor deg-5 on [-0.5,0.5], rel err ~2.4e-6). |x| < ~30.
__device__ __forceinline__ float exp2f_fast(float x) {
    float k = rintf(x);
    float f = x - k;
    float p = 1.33335581464e-3f;
    p = fmaf(p, f, 9.61812910763e-3f);
    p = fmaf(p, f, 5.55041086648e-2f);
    p = fmaf(p, f, 2.40226506959e-1f);
    p = fmaf(p, f, 6.93147180560e-1f);
    p = fmaf(p, f, 1.0f);
    int ik = (int)k;
    return p * __int_as_float((ik + 127) << 23);
}

// ===========================================================================
// Pre-pass: tf32-round x, w_qkv, w_proj into device copies
// ===========================================================================
__global__ void __launch_bounds__(256)
cvt_prepass(const float* __restrict__ x, const float* __restrict__ wq,
            const float* __restrict__ wp)
{
    const int n1 = (B_ * N_ * D_) / 4;
    const int n2 = (D_ * 3 * D_) / 4;
    const int n3 = (D_ * D_) / 4;
    const int total = n1 + n2 + n3;
    for (int i = blockIdx.x * blockDim.x + threadIdx.x; i < total;
         i += gridDim.x * blockDim.x) {
        const float4* src; float4* dst; int j;
        if (i < n1)           { src = (const float4*)x;  dst = (float4*)g_X;  j = i; }
        else if (i < n1 + n2) { src = (const float4*)wq; dst = (float4*)g_Wq; j = i - n1; }
        else                  { src = (const float4*)wp; dst = (float4*)g_Wp; j = i - n1 - n2; }
        float4 v = src[j];
        v.x = tf32r(v.x); v.y = tf32r(v.y);
        v.z = tf32r(v.z); v.w = tf32r(v.w);
        dst[j] = v;
    }
}

// ===========================================================================
// tf32 mma.sync GEMM, cp.async 2-stage double-buffered (unchanged, passing)
// ===========================================================================
#define GSTG (128 * SA + 32 * SB)   // floats per stage = 8960
template<int EPI>
__global__ void __launch_bounds__(256)
mma_gemm(const float* __restrict__ bias, float* __restrict__ C,
         int M, int Kd, int Nn)
{
    const float* A = (EPI == 0) ? (const float*)g_AO : (const float*)g_X;
    const float* Bw = (EPI == 0) ? (const float*)g_Wp : (const float*)g_Wq;
    extern __shared__ float smg[];
    const uint32_t s_u32 = smem_u32(smg);
    const int tid = threadIdx.x;
    const int wid = tid >> 5, lane = tid & 31;
    const int gid = lane >> 2, tg = lane & 3;
    const int warp_m = wid & 3, warp_n = wid >> 2;
    const int m0 = blockIdx.y * 128, n0 = blockIdx.x * 128;

    const int a_m = tid >> 3, a_k4 = tid & 7;
    const int b_k = tid >> 5, b_n4 = tid & 31;

    float c[2][8][4];
#pragma unroll
    for (int mt = 0; mt < 2; mt++)
#pragma unroll
        for (int nt = 0; nt < 8; nt++)
#pragma unroll
            for (int j = 0; j < 4; j++) c[mt][nt][j] = 0.f;

    auto prefetch = [&](int stg, int k0) {
        uint32_t as_u = s_u32 + stg * GSTG * 4;
        uint32_t bs_u = as_u + 128 * SA * 4;
#pragma unroll
        for (int it = 0; it < 4; it++) {
            int m = a_m + it * 32;
            cp16(as_u + (m * SA + a_k4 * 4) * 4,
                 &A[(size_t)(m0 + m) * Kd + k0 + a_k4 * 4]);
        }
#pragma unroll
        for (int it = 0; it < 4; it++) {
            int k = b_k + it * 8;
            cp16(bs_u + (k * SB + b_n4 * 4) * 4,
                 &Bw[(size_t)(k0 + k) * Nn + n0 + b_n4 * 4]);
        }
        cp_commit();
    };

    const int ntiles = Kd / 32;
    prefetch(0, 0);
    int s = 0;
#pragma unroll 1
    for (int t = 0; t < ntiles; t++) {
        cp_wait0();
        __syncthreads();
        if (t + 1 < ntiles) prefetch(s ^ 1, (t + 1) * 32);
        const float* As = smg + s * GSTG;
        const float* Bs = As + 128 * SA;
#pragma unroll
        for (int ks = 0; ks < 4; ks++) {
            const int kk = ks * 8;
            uint32_t a[2][4];
#pragma unroll
            for (int mt = 0; mt < 2; mt++) {
                int row = warp_m * 32 + mt * 16;
                a[mt][0] = __float_as_uint(As[(row + gid)     * SA + kk + tg]);
                a[mt][1] = __float_as_uint(As[(row + gid + 8) * SA + kk + tg]);
                a[mt][2] = __float_as_uint(As[(row + gid)     * SA + kk + tg + 4]);
                a[mt][3] = __float_as_uint(As[(row + gid + 8) * SA + kk + tg + 4]);
            }
            uint32_t b[8][2];
#pragma unroll
            for (int nt = 0; nt < 8; nt++) {
                int col = warp_n * 64 + nt * 8 + gid;
                b[nt][0] = __float_as_uint(Bs[(kk + tg)     * SB + col]);
                b[nt][1] = __float_as_uint(Bs[(kk + tg + 4) * SB + col]);
            }
#pragma unroll
            for (int mt = 0; mt < 2; mt++)
#pragma unroll
                for (int nt = 0; nt < 8; nt++)
                    mma_tf32(c[mt][nt], a[mt], b[nt]);
        }
        s ^= 1;
        __syncthreads();
    }

#pragma unroll
    for (int mt = 0; mt < 2; mt++) {
#pragma unroll
        for (int nt = 0; nt < 8; nt++) {
            int r0 = m0 + warp_m * 32 + mt * 16 + gid;
            int col = n0 + warp_n * 64 + nt * 8 + tg * 2;
#pragma unroll
            for (int h = 0; h < 2; h++) {
                int r = r0 + h * 8;
                float2 v;
                v.x = c[mt][nt][h * 2 + 0];
                v.y = c[mt][nt][h * 2 + 1];
                if (EPI == 0) {
                    v.x += bias[col + 0];
                    v.y += bias[col + 1];
                    *(float2*)&C[(size_t)r * Nn + col] = v;
                } else {
                    int bb = r >> 11, tok = r & 2047;
                    int which = col / D_;
                    int rem = col - which * D_;
                    int hh = rem >> 6, hd = rem & 63;
                    float* dst = (which == 0) ? g_Q : (which == 1) ? g_K : g_V;
                    float sc = (which == 0) ? QS_ : 1.f;
                    v.x = tf32r(v.x * sc);
                    v.y = tf32r(v.y * sc);
                    *(float2*)&dst[(((size_t)(bb * H_ + hh)) * N_ + tok) * HD_ + hd] = v;
                }
            }
        }
    }
}

// ===========================================================================
// Flash attention, Br=256: halves K/V L2 traffic vs Br=128.
// 8 warps x 32 q-rows (2 row-groups of 16). Q in smem (reloaded per k-tile),
// separate P buffer, cp.async double-buffered K/V. No-max softmax.
// ===========================================================================
#define FSTG (64 * LK + 64 * LV)   // floats per K/V stage = 8960
__global__ void __launch_bounds__(256, 1)
flash_mma_kernel()
{
    extern __shared__ float sm[];
    float* QPs = sm;                       // [256][LQ] Q (pre-scaled tf32)
    float* Ps  = sm + 256 * LQ;            // [256][LQ] P
    float* KV0 = Ps + 256 * LQ;            // 2 stages of (K [64][LK], V [64][LV])
    const uint32_t qps_u = smem_u32(QPs);
    const uint32_t kv_u  = smem_u32(KV0);

    const int tid = threadIdx.x;
    const int wid = tid >> 5, lane = tid & 31;
    const int gid = lane >> 2, tg = lane & 3;
    const int bh = blockIdx.y, qt = blockIdx.x;
    const int r0 = wid * 32;
    const float* Qg = g_Q + ((size_t)bh * N_ + qt * 256) * HD_;
    const float* Kg = g_K + (size_t)bh * N_ * HD_;
    const float* Vg = g_V + (size_t)bh * N_ * HD_;

    const int l_r = tid >> 4, l_c4 = tid & 15;

    auto prefetch_kv = [&](int stg, int kt) {
        uint32_t ks_u = kv_u + stg * FSTG * 4;
        uint32_t vs_u = ks_u + 64 * LK * 4;
#pragma unroll
        for (int it = 0; it < 4; it++) {
            int r = l_r + it * 16;
            cp16(ks_u + (r * LK + l_c4 * 4) * 4,
                 &Kg[(size_t)(kt * 64 + r) * HD_ + l_c4 * 4]);
            cp16(vs_u + (r * LV + l_c4 * 4) * 4,
                 &Vg[(size_t)(kt * 64 + r) * HD_ + l_c4 * 4]);
        }
        cp_commit();
    };

    // stage Q (256 rows) via cp.async
#pragma unroll
    for (int it = 0; it < 16; it++) {
        int idx = tid + it * 256;
        int r = idx >> 4, c4 = idx & 15;
        cp16(qps_u + (r * LQ + c4 * 4) * 4, &Qg[r * HD_ + c4 * 4]);
    }
    cp_commit();
    prefetch_kv(0, 0);
    cp_wait0();
    __syncthreads();

    float o[2][8][4];
#pragma unroll
    for (int mt = 0; mt < 2; mt++)
#pragma unroll
        for (int nt = 0; nt < 8; nt++)
#pragma unroll
            for (int j = 0; j < 4; j++) o[mt][nt][j] = 0.f;
    float lsum[2][2] = {{0.f, 0.f}, {0.f, 0.f}};

    int s = 0;
#pragma unroll 1
    for (int kt = 0; kt < N_ / 64; kt++) {
        if (kt > 0) { cp_wait0(); __syncthreads(); }
        if (kt + 1 < N_ / 64) prefetch_kv(s ^ 1, kt + 1);
        const float* Ks = KV0 + s * FSTG;
        const float* Vs = Ks + 64 * LK;

        // ---- S = Q K^T, exp2, store P, accumulate row sums ----
#pragma unroll
        for (int mt = 0; mt < 2; mt++) {
            const int rb = r0 + mt * 16;
            uint32_t qa[8][4];
#pragma unroll
            for (int ks = 0; ks < 8; ks++) {
                int k = ks * 8;
                qa[ks][0] = __float_as_uint(QPs[(rb + gid)     * LQ + k + tg]);
                qa[ks][1] = __float_as_uint(QPs[(rb + gid + 8) * LQ + k + tg]);
                qa[ks][2] = __float_as_uint(QPs[(rb + gid)     * LQ + k + tg + 4]);
                qa[ks][3] = __float_as_uint(QPs[(rb + gid + 8) * LQ + k + tg + 4]);
            }
            float rs0 = 0.f, rs1 = 0.f;
#pragma unroll
            for (int h = 0; h < 2; h++) {
                float cc[4][4];
#pragma unroll
                for (int j = 0; j < 4; j++)
#pragma unroll
                    for (int q = 0; q < 4; q++) cc[j][q] = 0.f;
#pragma unroll
                for (int ks = 0; ks < 8; ks++) {
                    int k = ks * 8;
#pragma unroll
                    for (int j = 0; j < 4; j++) {
                        int n = (h * 4 + j) * 8 + gid;
                        uint32_t b[2];
                        b[0] = __float_as_uint(Ks[n * LK + k + tg]);
                        b[1] = __float_as_uint(Ks[n * LK + k + tg + 4]);
                        mma_tf32(cc[j], qa[ks], b);
                    }
                }
#pragma unroll
                for (int j = 0; j < 4; j++) {
                    float e0 = exp2f_fast(cc[j][0]);
                    float e1 = exp2f_fast(cc[j][1]);
                    float e2 = exp2f_fast(cc[j][2]);
                    float e3 = exp2f_fast(cc[j][3]);
                    rs0 += e0 + e1;
                    rs1 += e2 + e3;
                    int colb = (h * 4 + j) * 8 + tg * 2;
                    float2 p0; p0.x = tf32r(e0); p0.y = tf32r(e1);
                    float2 p1; p1.x = tf32r(e2); p1.y = tf32r(e3);
                    *(float2*)&Ps[(rb + gid)     * LQ + colb] = p0;
                    *(float2*)&Ps[(rb + gid + 8) * LQ + colb] = p1;
                }
            }
            rs0 += __shfl_xor_sync(0xffffffffu, rs0, 1);
            rs0 += __shfl_xor_sync(0xffffffffu, rs0, 2);
            rs1 += __shfl_xor_sync(0xffffffffu, rs1, 1);
            rs1 += __shfl_xor_sync(0xffffffffu, rs1, 2);
            lsum[mt][0] += rs0;
            lsum[mt][1] += rs1;
        }
        __syncwarp();

        // ---- O += P @ V ----
#pragma unroll
        for (int ks = 0; ks < 8; ks++) {
            int k = ks * 8;
            uint32_t pa[2][4];
#pragma unroll
            for (int mt = 0; mt < 2; mt++) {
                int rb = r0 + mt * 16;
                pa[mt][0] = __float_as_uint(Ps[(rb + gid)     * LQ + k + tg]);
                pa[mt][1] = __float_as_uint(Ps[(rb + gid + 8) * LQ + k + tg]);
                pa[mt][2] = __float_as_uint(Ps[(rb + gid)     * LQ + k + tg + 4]);
                pa[mt][3] = __float_as_uint(Ps[(rb + gid + 8) * LQ + k + tg + 4]);
            }
#pragma unroll
            for (int nt = 0; nt < 8; nt++) {
                int n = nt * 8 + gid;
                uint32_t b[2];
                b[0] = __float_as_uint(Vs[(k + tg)     * LV + n]);
                b[1] = __float_as_uint(Vs[(k + tg + 4) * LV + n]);
                mma_tf32(o[0][nt], pa[0], b);
                mma_tf32(o[1][nt], pa[1], b);
            }
        }
        s ^= 1;
    }

    // epilogue: normalize, tf32-round, write (b, n, h*64+hd) for proj GEMM
    const int bb = bh / H_, hh = bh - bb * H_;
#pragma unroll
    for (int mt = 0; mt < 2; mt++) {
        const float i0 = 1.f / lsum[mt][0], i1 = 1.f / lsum[mt][1];
        const int row_a = qt * 256 + r0 + mt * 16 + gid;
        const int row_b = row_a + 8;
#pragma unroll
        for (int nt = 0; nt < 8; nt++) {
            int col = hh * HD_ + nt * 8 + tg * 2;
            float2 va; va.x = tf32r(o[mt][nt][0] * i0); va.y = tf32r(o[mt][nt][1] * i0);
            float2 vb; vb.x = tf32r(o[mt][nt][2] * i1); vb.y = tf32r(o[mt][nt][3] * i1);
            *(float2*)&g_AO[((size_t)(bb * N_ + row_a)) * D_ + col] = va;
            *(float2*)&g_AO[((size_t)(bb * N_ + row_b)) * D_ + col] = vb;
        }
    }
}

// ---------------------------------------------------------------------------
// q_attn: parallel two-pass. A: one key/thread, 384 blocks -> exp values +
// per-block partial sums. B: 48 blocks normalize.
// ---------------------------------------------------------------------------
__global__ void __launch_bounds__(256)
qattn_partial(float* __restrict__ out1)
{
    const int bh = blockIdx.y, kb = blockIdx.x;
    __shared__ float q0[64];
    __shared__ float red[256];
    const int tid = threadIdx.x;
    if (tid < 64) q0[tid] = g_Q[((size_t)bh * N_) * HD_ + tid];
    __syncthreads();

    const int j = kb * 256 + tid;
    const float4* kp = (const float4*)&g_K[((size_t)bh * N_ + j) * HD_];
    float s = 0.f;
#pragma unroll
    for (int i = 0; i < 16; i++) {
        float4 v = kp[i];
        s += v.x * q0[i * 4 + 0] + v.y * q0[i * 4 + 1]
           + v.z * q0[i * 4 + 2] + v.w * q0[i * 4 + 3];
    }
    float e = exp2f_fast(s);
    out1[(size_t)bh * N_ + j] = e;

    red[tid] = e; __syncthreads();
    for (int off = 128; off > 0; off >>= 1) {
        if (tid < off) red[tid] += red[tid + off];
        __syncthreads();
    }
    if (tid == 0) g_PS[bh * 8 + kb] = red[0];
}

__global__ void __launch_bounds__(256)
qattn_norm(float* __restrict__ out1)
{
    const int bh = blockIdx.x;
    __shared__ float inv_s;
    if (threadIdx.x == 0) {
        float s = 0.f;
#pragma unroll
        for (int i = 0; i < 8; i++) s += g_PS[bh * 8 + i];
        inv_s = 1.f / s;
    }
    __syncthreads();
    const float inv = inv_s;
#pragma unroll
    for (int it = 0; it < 8; it++)
        out1[(size_t)bh * N_ + threadIdx.x + it * 256] *= inv;
}

// ---------------------------------------------------------------------------
extern "C" void kernel_launch(void* const* d_in, const int* in_sizes, int n_in,
                              void* d_out, int out_size)
{
    const float* x      = (const float*)d_in[0];
    const float* w_qkv  = (const float*)d_in[1];
    const float* w_proj = (const float*)d_in[2];
    const float* b_proj = (const float*)d_in[3];
    float* out = (float*)d_out;
    float* out_qattn = out + ((size_t)out_size - (size_t)B_ * H_ * N_);

    const int gemm_smem  = 2 * GSTG * (int)sizeof(float);                  // 71680
    const int flash_smem = (2 * 256 * LQ + 2 * FSTG) * (int)sizeof(float); // 210944
    cudaFuncSetAttribute(mma_gemm<1>,
                         cudaFuncAttributeMaxDynamicSharedMemorySize, gemm_smem);
    cudaFuncSetAttribute(mma_gemm<0>,
                         cudaFuncAttributeMaxDynamicSharedMemorySize, gemm_smem);
    cudaFuncSetAttribute(flash_mma_kernel,
                         cudaFuncAttributeMaxDynamicSharedMemorySize, flash_smem);

    // 0) tf32 pre-round inputs
    cvt_prepass<<<2048, 256>>>(x, w_qkv, w_proj);
    // 1) QKV GEMM -> g_Q(xQS_)/g_K/g_V (head-major, tf32-rounded)
    {
        dim3 grid((3 * D_) / 128, (B_ * N_) / 128);
        mma_gemm<1><<<grid, 256, gemm_smem>>>(nullptr, nullptr,
                                              B_ * N_, D_, 3 * D_);
    }
    // 2) q=0 attention row (parallel two-pass)
    {
        dim3 grid(8, 48);
        qattn_partial<<<grid, 256>>>(out_qattn);
        qattn_norm<<<48, 256>>>(out_qattn);
    }
    // 3) Flash attention (tensor cores, Br=256) -> g_AO
    {
        dim3 grid(N_ / 256, B_ * H_);
        flash_mma_kernel<<<grid, 256, flash_smem>>>();
    }
    // 4) Projection GEMM + bias
    {
        dim3 grid(D_ / 128, (B_ * N_) / 128);
        mma_gemm<0><<<grid, 256, gemm_smem>>>(b_proj, out,
                                              B_ * N_, D_, D_);
    }
}

// round 8
// speedup vs baseline: 3.6086x; 1.0658x over previous
#include <cuda_runtime.h>
#include <math.h>
#include <stdint.h>

#define B_ 4
#define N_ 2048
#define D_ 768
#define H_ 12
#define HD_ 64
#define QS_ 0.18033688011112042f
#define SA 36
#define SB 136
#define LQ 68
#define LK 68
#define LV 72

__device__ float g_X [(size_t)B_*N_*D_];
__device__ float g_Wq[(size_t)D_*3*D_];
__device__ float g_Wp[(size_t)D_*D_];
__device__ float g_Q [(size_t)B_*H_*N_*HD_];   // pre-scaled by QS_
__device__ float g_K [(size_t)B_*H_*N_*HD_];
__device__ float g_V [(size_t)B_*H_*N_*HD_];
__device__ float g_AO[(size_t)B_*N_*D_];
__device__ float g_PS[48 * 8];

__device__ __forceinline__ uint32_t to_tf32(float x) {
    uint32_t r;
    asm("cvt.rna.tf32.f32 %0, %1;" : "=r"(r) : "f"(x));
    return r;
}
__device__ __forceinline__ float tf32r(float x) {
    return __uint_as_float(to_tf32(x));
}
__device__ __forceinline__ uint32_t smem_u32(const void* p) {
    uint32_t a;
    asm("{ .reg .u64 t; cvta.to.shared.u64 t, %1; cvt.u32.u64 %0, t; }"
        : "=r"(a) : "l"(p));
    return a;
}
__device__ __forceinline__ void cp16(uint32_t dst, const void* src) {
    asm volatile("cp.async.cg.shared.global [%0], [%1], 16;"
                 :: "r"(dst), "l"(src));
}
__device__ __forceinline__ void cp_commit() {
    asm volatile("cp.async.commit_group;");
}
__device__ __forceinline__ void cp_wait0() {
    asm volatile("cp.async.wait_group 0;");
}
__device__ __forceinline__ void cp_wait1() {
    asm volatile("cp.async.wait_group 1;");
}
__device__ __forceinline__ void mma_tf32(float c[4], const uint32_t a[4],
                                         const uint32_t b[2]) {
    asm volatile(
        "mma.sync.aligned.m16n8k8.row.col.f32.tf32.tf32.f32 "
        "{%0,%1,%2,%3}, {%4,%5,%6,%7}, {%8,%9}, {%0,%1,%2,%3};"
        : "+f"(c[0]), "+f"(c[1]), "+f"(c[2]), "+f"(c[3])
        : "r"(a[0]), "r"(a[1]), "r"(a[2]), "r"(a[3]), "r"(b[0]), "r"(b[1]));
}
__device__ __forceinline__ float exp2f_fast(float x) {
    float k = rintf(x);
    float f = x - k;
    float p = 1.33335581464e-3f;
    p = fmaf(p, f, 9.61812910763e-3f);
    p = fmaf(p, f, 5.55041086648e-2f);
    p = fmaf(p, f, 2.40226506959e-1f);
    p = fmaf(p, f, 6.93147180560e-1f);
    p = fmaf(p, f, 1.0f);
    int ik = (int)k;
    return p * __int_as_float((ik + 127) << 23);
}

__global__ void __launch_bounds__(256)
cvt_prepass(const float* __restrict__ x, const float* __restrict__ wq,
            const float* __restrict__ wp)
{
    const int n1 = (B_ * N_ * D_) / 4;
    const int n2 = (D_ * 3 * D_) / 4;
    const int n3 = (D_ * D_) / 4;
    const int total = n1 + n2 + n3;
    for (int i = blockIdx.x * blockDim.x + threadIdx.x; i < total;
         i += gridDim.x * blockDim.x) {
        const float4* src; float4* dst; int j;
        if (i < n1)           { src = (const float4*)x;  dst = (float4*)g_X;  j = i; }
        else if (i < n1 + n2) { src = (const float4*)wq; dst = (float4*)g_Wq; j = i - n1; }
        else                  { src = (const float4*)wp; dst = (float4*)g_Wp; j = i - n1 - n2; }
        float4 v = src[j];
        v.x = tf32r(v.x); v.y = tf32r(v.y);
        v.z = tf32r(v.z); v.w = tf32r(v.w);
        dst[j] = v;
    }
}

// ===========================================================================
// tf32 mma.sync GEMM, 3-stage cp.async pipeline, single barrier per k-tile.
// ===========================================================================
#define GSTG (128 * SA + 32 * SB)   // 8960 floats per stage
template<int EPI>
__global__ void __launch_bounds__(256)
mma_gemm(const float* __restrict__ bias, float* __restrict__ C,
         int M, int Kd, int Nn)
{
    const float* A = (EPI == 0) ? (const float*)g_AO : (const float*)g_X;
    const float* Bw = (EPI == 0) ? (const float*)g_Wp : (const float*)g_Wq;
    extern __shared__ float smg[];
    const uint32_t s_u32 = smem_u32(smg);
    const int tid = threadIdx.x;
    const int wid = tid >> 5, lane = tid & 31;
    const int gid = lane >> 2, tg = lane & 3;
    const int warp_m = wid & 3, warp_n = wid >> 2;
    const int m0 = blockIdx.y * 128, n0 = blockIdx.x * 128;

    const int a_m = tid >> 3, a_k4 = tid & 7;
    const int b_k = tid >> 5, b_n4 = tid & 31;

    float c[2][8][4];
#pragma unroll
    for (int mt = 0; mt < 2; mt++)
#pragma unroll
        for (int nt = 0; nt < 8; nt++)
#pragma unroll
            for (int j = 0; j < 4; j++) c[mt][nt][j] = 0.f;

    auto prefetch = [&](int stg, int k0) {
        uint32_t as_u = s_u32 + stg * GSTG * 4;
        uint32_t bs_u = as_u + 128 * SA * 4;
#pragma unroll
        for (int it = 0; it < 4; it++) {
            int m = a_m + it * 32;
            cp16(as_u + (m * SA + a_k4 * 4) * 4,
                 &A[(size_t)(m0 + m) * Kd + k0 + a_k4 * 4]);
        }
#pragma unroll
        for (int it = 0; it < 4; it++) {
            int k = b_k + it * 8;
            cp16(bs_u + (k * SB + b_n4 * 4) * 4,
                 &Bw[(size_t)(k0 + k) * Nn + n0 + b_n4 * 4]);
        }
        cp_commit();
    };

    const int ntiles = Kd / 32;
    prefetch(0, 0);
    prefetch(1, 32);
#pragma unroll 1
    for (int t = 0; t < ntiles; t++) {
        cp_wait1();                 // tile t's group complete (t+1 may fly)
        __syncthreads();            // all warps done reading stage (t-1)%3
        if (t + 2 < ntiles) prefetch((t + 2) % 3, (t + 2) * 32);
        else cp_commit();           // empty group keeps counting sound
        const float* As = smg + (t % 3) * GSTG;
        const float* Bs = As + 128 * SA;
#pragma unroll
        for (int ks = 0; ks < 4; ks++) {
            const int kk = ks * 8;
            uint32_t a[2][4];
#pragma unroll
            for (int mt = 0; mt < 2; mt++) {
                int row = warp_m * 32 + mt * 16;
                a[mt][0] = __float_as_uint(As[(row + gid)     * SA + kk + tg]);
                a[mt][1] = __float_as_uint(As[(row + gid + 8) * SA + kk + tg]);
                a[mt][2] = __float_as_uint(As[(row + gid)     * SA + kk + tg + 4]);
                a[mt][3] = __float_as_uint(As[(row + gid + 8) * SA + kk + tg + 4]);
            }
            uint32_t b[8][2];
#pragma unroll
            for (int nt = 0; nt < 8; nt++) {
                int col = warp_n * 64 + nt * 8 + gid;
                b[nt][0] = __float_as_uint(Bs[(kk + tg)     * SB + col]);
                b[nt][1] = __float_as_uint(Bs[(kk + tg + 4) * SB + col]);
            }
#pragma unroll
            for (int mt = 0; mt < 2; mt++)
#pragma unroll
                for (int nt = 0; nt < 8; nt++)
                    mma_tf32(c[mt][nt], a[mt], b[nt]);
        }
    }

#pragma unroll
    for (int mt = 0; mt < 2; mt++) {
#pragma unroll
        for (int nt = 0; nt < 8; nt++) {
            int r0 = m0 + warp_m * 32 + mt * 16 + gid;
            int col = n0 + warp_n * 64 + nt * 8 + tg * 2;
#pragma unroll
            for (int h = 0; h < 2; h++) {
                int r = r0 + h * 8;
                float2 v;
                v.x = c[mt][nt][h * 2 + 0];
                v.y = c[mt][nt][h * 2 + 1];
                if (EPI == 0) {
                    v.x += bias[col + 0];
                    v.y += bias[col + 1];
                    *(float2*)&C[(size_t)r * Nn + col] = v;
                } else {
                    int bb = r >> 11, tok = r & 2047;
                    int which = col / D_;
                    int rem = col - which * D_;
                    int hh = rem >> 6, hd = rem & 63;
                    float* dst = (which == 0) ? g_Q : (which == 1) ? g_K : g_V;
                    float sc = (which == 0) ? QS_ : 1.f;
                    v.x = tf32r(v.x * sc);
                    v.y = tf32r(v.y * sc);
                    *(float2*)&dst[(((size_t)(bb * H_ + hh)) * N_ + tok) * HD_ + hd] = v;
                }
            }
        }
    }
}

// ===========================================================================
// Flash attention (round-6: Br=128, 2 CTA/SM, Q frags in regs, QPs reuse)
// ===========================================================================
#define FSTG (64 * LK + 64 * LV)
__global__ void __launch_bounds__(256, 2)
flash_mma_kernel()
{
    extern __shared__ float sm[];
    float* QPs = sm;
    float* KV0 = sm + 128 * LQ;
    const uint32_t qps_u = smem_u32(QPs);
    const uint32_t kv_u  = smem_u32(KV0);

    const int tid = threadIdx.x;
    const int wid = tid >> 5, lane = tid & 31;
    const int gid = lane >> 2, tg = lane & 3;
    const int bh = blockIdx.y, qt = blockIdx.x;
    const int r0 = wid * 16;
    const float* Qg = g_Q + ((size_t)bh * N_ + qt * 128) * HD_;
    const float* Kg = g_K + (size_t)bh * N_ * HD_;
    const float* Vg = g_V + (size_t)bh * N_ * HD_;

    const int l_r = tid >> 4, l_c4 = tid & 15;

    auto prefetch_kv = [&](int stg, int kt) {
        uint32_t ks_u = kv_u + stg * FSTG * 4;
        uint32_t vs_u = ks_u + 64 * LK * 4;
#pragma unroll
        for (int it = 0; it < 4; it++) {
            int r = l_r + it * 16;
            cp16(ks_u + (r * LK + l_c4 * 4) * 4,
                 &Kg[(size_t)(kt * 64 + r) * HD_ + l_c4 * 4]);
            cp16(vs_u + (r * LV + l_c4 * 4) * 4,
                 &Vg[(size_t)(kt * 64 + r) * HD_ + l_c4 * 4]);
        }
        cp_commit();
    };

#pragma unroll
    for (int it = 0; it < 8; it++) {
        int idx = tid + it * 256;
        int r = idx >> 4, c4 = idx & 15;
        cp16(qps_u + (r * LQ + c4 * 4) * 4, &Qg[r * HD_ + c4 * 4]);
    }
    cp_commit();
    prefetch_kv(0, 0);
    cp_wait0();
    __syncthreads();

    uint32_t qf[8][4];
#pragma unroll
    for (int ks = 0; ks < 8; ks++) {
        int k = ks * 8;
        qf[ks][0] = __float_as_uint(QPs[(r0 + gid)     * LQ + k + tg]);
        qf[ks][1] = __float_as_uint(QPs[(r0 + gid + 8) * LQ + k + tg]);
        qf[ks][2] = __float_as_uint(QPs[(r0 + gid)     * LQ + k + tg + 4]);
        qf[ks][3] = __float_as_uint(QPs[(r0 + gid + 8) * LQ + k + tg + 4]);
    }

    float o[8][4];
#pragma unroll
    for (int nt = 0; nt < 8; nt++)
#pragma unroll
        for (int j = 0; j < 4; j++) o[nt][j] = 0.f;
    float l0 = 0.f, l1 = 0.f;

    int s = 0;
#pragma unroll 1
    for (int kt = 0; kt < N_ / 64; kt++) {
        if (kt > 0) { cp_wait0(); __syncthreads(); }
        if (kt + 1 < N_ / 64) prefetch_kv(s ^ 1, kt + 1);
        const float* Ks = KV0 + s * FSTG;
        const float* Vs = Ks + 64 * LK;

        float rs0 = 0.f, rs1 = 0.f;
#pragma unroll
        for (int h = 0; h < 2; h++) {
            float cc[4][4];
#pragma unroll
            for (int j = 0; j < 4; j++)
#pragma unroll
                for (int q = 0; q < 4; q++) cc[j][q] = 0.f;
#pragma unroll
            for (int ks = 0; ks < 8; ks++) {
                int k = ks * 8;
#pragma unroll
                for (int j = 0; j < 4; j++) {
                    int n = (h * 4 + j) * 8 + gid;
                    uint32_t b[2];
                    b[0] = __float_as_uint(Ks[n * LK + k + tg]);
                    b[1] = __float_as_uint(Ks[n * LK + k + tg + 4]);
                    mma_tf32(cc[j], qf[ks], b);
                }
            }
#pragma unroll
            for (int j = 0; j < 4; j++) {
                float e0 = exp2f_fast(cc[j][0]);
                float e1 = exp2f_fast(cc[j][1]);
                float e2 = exp2f_fast(cc[j][2]);
                float e3 = exp2f_fast(cc[j][3]);
                rs0 += e0 + e1;
                rs1 += e2 + e3;
                int colb = (h * 4 + j) * 8 + tg * 2;
                float2 p0; p0.x = tf32r(e0); p0.y = tf32r(e1);
                float2 p1; p1.x = tf32r(e2); p1.y = tf32r(e3);
                *(float2*)&QPs[(r0 + gid)     * LQ + colb] = p0;
                *(float2*)&QPs[(r0 + gid + 8) * LQ + colb] = p1;
            }
        }
        rs0 += __shfl_xor_sync(0xffffffffu, rs0, 1);
        rs0 += __shfl_xor_sync(0xffffffffu, rs0, 2);
        rs1 += __shfl_xor_sync(0xffffffffu, rs1, 1);
        rs1 += __shfl_xor_sync(0xffffffffu, rs1, 2);
        l0 += rs0;
        l1 += rs1;
        __syncwarp();

#pragma unroll
        for (int ks = 0; ks < 8; ks++) {
            int k = ks * 8;
            uint32_t a[4];
            a[0] = __float_as_uint(QPs[(r0 + gid)     * LQ + k + tg]);
            a[1] = __float_as_uint(QPs[(r0 + gid + 8) * LQ + k + tg]);
            a[2] = __float_as_uint(QPs[(r0 + gid)     * LQ + k + tg + 4]);
            a[3] = __float_as_uint(QPs[(r0 + gid + 8) * LQ + k + tg + 4]);
#pragma unroll
            for (int nt = 0; nt < 8; nt++) {
                int n = nt * 8 + gid;
                uint32_t b[2];
                b[0] = __float_as_uint(Vs[(k + tg)     * LV + n]);
                b[1] = __float_as_uint(Vs[(k + tg + 4) * LV + n]);
                mma_tf32(o[nt], a, b);
            }
        }
        s ^= 1;
    }

    const int bb = bh / H_, hh = bh - bb * H_;
    const float i0 = 1.f / l0, i1 = 1.f / l1;
    const int row_a = qt * 128 + r0 + gid;
    const int row_b = row_a + 8;
#pragma unroll
    for (int nt = 0; nt < 8; nt++) {
        int col = hh * HD_ + nt * 8 + tg * 2;
        float2 va; va.x = tf32r(o[nt][0] * i0); va.y = tf32r(o[nt][1] * i0);
        float2 vb; vb.x = tf32r(o[nt][2] * i1); vb.y = tf32r(o[nt][3] * i1);
        *(float2*)&g_AO[((size_t)(bb * N_ + row_a)) * D_ + col] = va;
        *(float2*)&g_AO[((size_t)(bb * N_ + row_b)) * D_ + col] = vb;
    }
}

__global__ void __launch_bounds__(256)
qattn_partial(float* __restrict__ out1)
{
    const int bh = blockIdx.y, kb = blockIdx.x;
    __shared__ float q0[64];
    __shared__ float red[256];
    const int tid = threadIdx.x;
    if (tid < 64) q0[tid] = g_Q[((size_t)bh * N_) * HD_ + tid];
    __syncthreads();

    const int j = kb * 256 + tid;
    const float4* kp = (const float4*)&g_K[((size_t)bh * N_ + j) * HD_];
    float s = 0.f;
#pragma unroll
    for (int i = 0; i < 16; i++) {
        float4 v = kp[i];
        s += v.x * q0[i * 4 + 0] + v.y * q0[i * 4 + 1]
           + v.z * q0[i * 4 + 2] + v.w * q0[i * 4 + 3];
    }
    float e = exp2f_fast(s);
    out1[(size_t)bh * N_ + j] = e;

    red[tid] = e; __syncthreads();
    for (int off = 128; off > 0; off >>= 1) {
        if (tid < off) red[tid] += red[tid + off];
        __syncthreads();
    }
    if (tid == 0) g_PS[bh * 8 + kb] = red[0];
}

__global__ void __launch_bounds__(256)
qattn_norm(float* __restrict__ out1)
{
    const int bh = blockIdx.x;
    __shared__ float inv_s;
    if (threadIdx.x == 0) {
        float s = 0.f;
#pragma unroll
        for (int i = 0; i < 8; i++) s += g_PS[bh * 8 + i];
        inv_s = 1.f / s;
    }
    __syncthreads();
    const float inv = inv_s;
#pragma unroll
    for (int it = 0; it < 8; it++)
        out1[(size_t)bh * N_ + threadIdx.x + it * 256] *= inv;
}

extern "C" void kernel_launch(void* const* d_in, const int* in_sizes, int n_in,
                              void* d_out, int out_size)
{
    const float* x      = (const float*)d_in[0];
    const float* w_qkv  = (const float*)d_in[1];
    const float* w_proj = (const float*)d_in[2];
    const float* b_proj = (const float*)d_in[3];
    float* out = (float*)d_out;
    float* out_qattn = out + ((size_t)out_size - (size_t)B_ * H_ * N_);

    const int gemm_smem  = 3 * GSTG * (int)sizeof(float);              // 107520
    const int flash_smem = (128 * LQ + 2 * FSTG) * (int)sizeof(float); // 106496
    cudaFuncSetAttribute(mma_gemm<1>,
                         cudaFuncAttributeMaxDynamicSharedMemorySize, gemm_smem);
    cudaFuncSetAttribute(mma_gemm<0>,
                         cudaFuncAttributeMaxDynamicSharedMemorySize, gemm_smem);
    cudaFuncSetAttribute(flash_mma_kernel,
                         cudaFuncAttributeMaxDynamicSharedMemorySize, flash_smem);

    cvt_prepass<<<2048, 256>>>(x, w_qkv, w_proj);
    {
        dim3 grid((3 * D_) / 128, (B_ * N_) / 128);
        mma_gemm<1><<<grid, 256, gemm_smem>>>(nullptr, nullptr,
                                              B_ * N_, D_, 3 * D_);
    }
    {
        dim3 grid(8, 48);
        qattn_partial<<<grid, 256>>>(out_qattn);
        qattn_norm<<<48, 256>>>(out_qattn);
    }
    {
        dim3 grid(N_ / 128, B_ * H_);
        flash_mma_kernel<<<grid, 256, flash_smem>>>();
    }
    {
        dim3 grid(D_ / 128, (B_ * N_) / 128);
        mma_gemm<0><<<grid, 256, gemm_smem>>>(b_proj, out,
                                              B_ * N_, D_, D_);
    }
}

// round 10
// speedup vs baseline: 3.7065x; 1.0271x over previous
#include <cuda_runtime.h>
#include <math.h>
#include <stdint.h>

#define B_ 4
#define N_ 2048
#define D_ 768
#define H_ 12
#define HD_ 64
#define QS_ 0.18033688011112042f
#define SA 36    // GEMM A smem stride [m][k]
#define SB 36    // GEMM B smem stride [n][k]
#define LQ 68    // flash Q/P stride [m][*]
#define LK 68    // flash K stride [key][hd]
#define LV 68    // flash V^T stride [hd][key]

__device__ float g_X  [(size_t)B_*N_*D_];
__device__ float g_Wqt[(size_t)3*D_*D_];     // W_qkv^T [3D][D]
__device__ float g_Wpt[(size_t)D_*D_];       // W_proj^T [D][D]
__device__ float g_Q  [(size_t)B_*H_*N_*HD_]; // pre-scaled by QS_
__device__ float g_K  [(size_t)B_*H_*N_*HD_];
__device__ float g_Vt [(size_t)B_*H_*HD_*N_]; // V^T per (b,h): [hd][key]
__device__ float g_AO [(size_t)B_*N_*D_];
__device__ float g_PS [48 * 8];

// ============================ helpers ======================================
__device__ __forceinline__ uint32_t to_tf32(float x) {
    uint32_t r;
    asm("cvt.rna.tf32.f32 %0, %1;" : "=r"(r) : "f"(x));
    return r;
}
__device__ __forceinline__ float tf32r(float x) {
    return __uint_as_float(to_tf32(x));
}
__device__ __forceinline__ uint32_t smem_u32(const void* p) {
    uint32_t a;
    asm("{ .reg .u64 t; cvta.to.shared.u64 t, %1; cvt.u32.u64 %0, t; }"
        : "=r"(a) : "l"(p));
    return a;
}
__device__ __forceinline__ void cp16(uint32_t dst, const void* src) {
    asm volatile("cp.async.cg.shared.global [%0], [%1], 16;"
                 :: "r"(dst), "l"(src));
}
__device__ __forceinline__ void cp_commit() {
    asm volatile("cp.async.commit_group;");
}
__device__ __forceinline__ void cp_wait0() {
    asm volatile("cp.async.wait_group 0;");
}
__device__ __forceinline__ void cp_wait1() {
    asm volatile("cp.async.wait_group 1;");
}
__device__ __forceinline__ void ldsm4(uint32_t r[4], uint32_t addr) {
    asm volatile("ldmatrix.sync.aligned.m8n8.x4.shared.b16 {%0,%1,%2,%3}, [%4];"
                 : "=r"(r[0]), "=r"(r[1]), "=r"(r[2]), "=r"(r[3]) : "r"(addr));
}
__device__ __forceinline__ void mma_tf32(float c[4], const uint32_t a[4],
                                         uint32_t b0, uint32_t b1) {
    asm volatile(
        "mma.sync.aligned.m16n8k8.row.col.f32.tf32.tf32.f32 "
        "{%0,%1,%2,%3}, {%4,%5,%6,%7}, {%8,%9}, {%0,%1,%2,%3};"
        : "+f"(c[0]), "+f"(c[1]), "+f"(c[2]), "+f"(c[3])
        : "r"(a[0]), "r"(a[1]), "r"(a[2]), "r"(a[3]), "r"(b0), "r"(b1));
}
__device__ __forceinline__ float exp2f_fast(float x) {
    float k = rintf(x);
    float f = x - k;
    float p = 1.33335581464e-3f;
    p = fmaf(p, f, 9.61812910763e-3f);
    p = fmaf(p, f, 5.55041086648e-2f);
    p = fmaf(p, f, 2.40226506959e-1f);
    p = fmaf(p, f, 6.93147180560e-1f);
    p = fmaf(p, f, 1.0f);
    int ik = (int)k;
    return p * __int_as_float((ik + 127) << 23);
}

// ===========================================================================
// Pre-pass A: tf32-round x (straight copy)
// ===========================================================================
__global__ void __launch_bounds__(256)
round_x(const float* __restrict__ x)
{
    const int total = (B_ * N_ * D_) / 4;
    for (int i = blockIdx.x * blockDim.x + threadIdx.x; i < total;
         i += gridDim.x * blockDim.x) {
        float4 v = ((const float4*)x)[i];
        v.x = tf32r(v.x); v.y = tf32r(v.y);
        v.z = tf32r(v.z); v.w = tf32r(v.w);
        ((float4*)g_X)[i] = v;
    }
}

// ===========================================================================
// Pre-pass B: tf32-round + transpose weights into __device__ globals.
// WQ==1 -> g_Wqt (from w_qkv), WQ==0 -> g_Wpt (from w_proj).
// Destination referenced from DEVICE code only (host cannot pass __device__
// symbols as arguments — that was the round-9 bug).
// ===========================================================================
template<int WQ>
__global__ void __launch_bounds__(256)
transpose_tf32(const float* __restrict__ src, int KD, int ND)
{
    float* __restrict__ dst = WQ ? g_Wqt : g_Wpt;
    __shared__ float t[32][33];
    const int tid = threadIdx.x;
    const int tx = tid & 31, ty = tid >> 5;
    const int bx = blockIdx.x * 32, by = blockIdx.y * 32;
#pragma unroll
    for (int i = 0; i < 4; i++) {
        int k = by + ty + i * 8;
        t[ty + i * 8][tx] = tf32r(src[(size_t)k * ND + bx + tx]);
    }
    __syncthreads();
#pragma unroll
    for (int i = 0; i < 4; i++) {
        int n = bx + ty + i * 8;
        dst[(size_t)n * KD + by + tx] = t[tx][ty + i * 8];
    }
}

// ===========================================================================
// tf32 mma.sync GEMM, 3-stage cp.async, ldmatrix fragment loads.
// A [m][k] from g_X / g_AO; B [n][k] from W^T. 128x128 tile, BK=32.
// ===========================================================================
#define GSTG (128 * SA + 128 * SB)   // 9216 floats per stage
template<int EPI>
__global__ void __launch_bounds__(256)
mma_gemm(const float* __restrict__ bias, float* __restrict__ C,
         int M, int Kd, int Nn)
{
    const float* A  = (EPI == 0) ? (const float*)g_AO : (const float*)g_X;
    const float* Bw = (EPI == 0) ? (const float*)g_Wpt : (const float*)g_Wqt;
    extern __shared__ float smg[];
    const uint32_t s_u32 = smem_u32(smg);
    const int tid = threadIdx.x;
    const int wid = tid >> 5, lane = tid & 31;
    const int gid = lane >> 2, tg = lane & 3;
    const int warp_m = wid & 3, warp_n = wid >> 2;
    const int m0 = blockIdx.y * 128, n0 = blockIdx.x * 128;

    // cp.async loader indices (A and B tiles same shape: 128 x 32)
    const int l_m = tid >> 3, l_k4 = tid & 7;

    // ldmatrix lane offsets
    const int a_row = lane & 15, a_col = (lane >> 4) * 4;
    const int b_row = (lane & 7) + ((lane >> 4) << 3), b_col = ((lane >> 3) & 1) * 4;

    float c[2][8][4];
#pragma unroll
    for (int mt = 0; mt < 2; mt++)
#pragma unroll
        for (int nt = 0; nt < 8; nt++)
#pragma unroll
            for (int j = 0; j < 4; j++) c[mt][nt][j] = 0.f;

    auto prefetch = [&](int stg, int k0) {
        uint32_t as_u = s_u32 + stg * GSTG * 4;
        uint32_t bs_u = as_u + 128 * SA * 4;
#pragma unroll
        for (int it = 0; it < 4; it++) {
            int m = l_m + it * 32;
            cp16(as_u + (m * SA + l_k4 * 4) * 4,
                 &A[(size_t)(m0 + m) * Kd + k0 + l_k4 * 4]);
            cp16(bs_u + (m * SB + l_k4 * 4) * 4,
                 &Bw[(size_t)(n0 + m) * Kd + k0 + l_k4 * 4]);
        }
        cp_commit();
    };

    const int ntiles = Kd / 32;
    prefetch(0, 0);
    prefetch(1, 32);
#pragma unroll 1
    for (int t = 0; t < ntiles; t++) {
        cp_wait1();
        __syncthreads();
        if (t + 2 < ntiles) prefetch((t + 2) % 3, (t + 2) * 32);
        else cp_commit();
        const uint32_t as_u = s_u32 + (t % 3) * GSTG * 4;
        const uint32_t bs_u = as_u + 128 * SA * 4;
        const uint32_t a_base0 = as_u + ((warp_m * 32 + a_row) * SA + a_col) * 4;
        const uint32_t a_base1 = a_base0 + 16 * SA * 4;
        const uint32_t b_base  = bs_u + ((warp_n * 64 + b_row) * SB + b_col) * 4;
#pragma unroll
        for (int ks = 0; ks < 4; ks++) {
            const int kb = ks * 32;   // byte offset for k chunk
            uint32_t a0[4], a1[4];
            ldsm4(a0, a_base0 + kb);
            ldsm4(a1, a_base1 + kb);
#pragma unroll
            for (int j = 0; j < 4; j++) {
                uint32_t bb[4];
                ldsm4(bb, b_base + j * 16 * SB * 4 + kb);
                mma_tf32(c[0][2 * j],     a0, bb[0], bb[1]);
                mma_tf32(c[0][2 * j + 1], a0, bb[2], bb[3]);
                mma_tf32(c[1][2 * j],     a1, bb[0], bb[1]);
                mma_tf32(c[1][2 * j + 1], a1, bb[2], bb[3]);
            }
        }
    }

#pragma unroll
    for (int mt = 0; mt < 2; mt++) {
#pragma unroll
        for (int nt = 0; nt < 8; nt++) {
            int r0 = m0 + warp_m * 32 + mt * 16 + gid;
            int col = n0 + warp_n * 64 + nt * 8 + tg * 2;
#pragma unroll
            for (int h = 0; h < 2; h++) {
                int r = r0 + h * 8;
                float2 v;
                v.x = c[mt][nt][h * 2 + 0];
                v.y = c[mt][nt][h * 2 + 1];
                if (EPI == 0) {
                    v.x += bias[col + 0];
                    v.y += bias[col + 1];
                    *(float2*)&C[(size_t)r * Nn + col] = v;
                } else {
                    int bb = r >> 11, tok = r & 2047;
                    int which = col / D_;
                    int rem = col - which * D_;
                    int hh = rem >> 6, hd = rem & 63;
                    if (which == 2) {   // V^T: [b,h][hd][key]
                        float* dst = g_Vt + (((size_t)(bb * H_ + hh)) * HD_) * N_;
                        dst[(size_t)hd * N_ + tok]       = tf32r(v.x);
                        dst[(size_t)(hd + 1) * N_ + tok] = tf32r(v.y);
                    } else {
                        float* dst = (which == 0) ? g_Q : g_K;
                        float sc = (which == 0) ? QS_ : 1.f;
                        v.x = tf32r(v.x * sc);
                        v.y = tf32r(v.y * sc);
                        *(float2*)&dst[(((size_t)(bb * H_ + hh)) * N_ + tok) * HD_ + hd] = v;
                    }
                }
            }
        }
    }
}

// ===========================================================================
// Flash attention: Br=128, 2 CTA/SM, ldmatrix everywhere, V^T layout.
// ===========================================================================
#define FSTG (64 * LK + 64 * LV)   // 8704 floats per K/V stage
__global__ void __launch_bounds__(256, 2)
flash_mma_kernel()
{
    extern __shared__ float sm[];
    float* QPs = sm;                 // [128][LQ] Q staging, then P
    float* KV0 = sm + 128 * LQ;      // 2 stages of (K [64][LK], V^T [64][LV])
    const uint32_t qps_u = smem_u32(QPs);
    const uint32_t kv_u  = smem_u32(KV0);

    const int tid = threadIdx.x;
    const int wid = tid >> 5, lane = tid & 31;
    const int gid = lane >> 2, tg = lane & 3;
    const int bh = blockIdx.y, qt = blockIdx.x;
    const int r0 = wid * 16;
    const float* Qg  = g_Q + ((size_t)bh * N_ + qt * 128) * HD_;
    const float* Kg  = g_K + (size_t)bh * N_ * HD_;
    const float* Vtg = g_Vt + (size_t)bh * HD_ * N_;

    const int l_r = tid >> 4, l_c4 = tid & 15;
    const int a_row = lane & 15, a_col = (lane >> 4) * 4;
    const int b_row = (lane & 7) + ((lane >> 4) << 3), b_col = ((lane >> 3) & 1) * 4;

    auto prefetch_kv = [&](int stg, int kt) {
        uint32_t ks_u = kv_u + stg * FSTG * 4;
        uint32_t vs_u = ks_u + 64 * LK * 4;
#pragma unroll
        for (int it = 0; it < 4; it++) {
            int r = l_r + it * 16;
            cp16(ks_u + (r * LK + l_c4 * 4) * 4,
                 &Kg[(size_t)(kt * 64 + r) * HD_ + l_c4 * 4]);
            cp16(vs_u + (r * LV + l_c4 * 4) * 4,
                 &Vtg[(size_t)r * N_ + kt * 64 + l_c4 * 4]);
        }
        cp_commit();
    };

    // stage Q
#pragma unroll
    for (int it = 0; it < 8; it++) {
        int idx = tid + it * 256;
        int r = idx >> 4, c4 = idx & 15;
        cp16(qps_u + (r * LQ + c4 * 4) * 4, &Qg[r * HD_ + c4 * 4]);
    }
    cp_commit();
    prefetch_kv(0, 0);
    cp_wait0();
    __syncthreads();

    // per-warp Q fragments via ldmatrix (live whole kernel)
    const uint32_t qa_base = qps_u + ((r0 + a_row) * LQ + a_col) * 4;
    uint32_t qf[8][4];
#pragma unroll
    for (int ks = 0; ks < 8; ks++) ldsm4(qf[ks], qa_base + ks * 32);

    float o[8][4];
#pragma unroll
    for (int nt = 0; nt < 8; nt++)
#pragma unroll
        for (int j = 0; j < 4; j++) o[nt][j] = 0.f;
    float l0 = 0.f, l1 = 0.f;

    int s = 0;
#pragma unroll 1
    for (int kt = 0; kt < N_ / 64; kt++) {
        if (kt > 0) { cp_wait0(); __syncthreads(); }
        if (kt + 1 < N_ / 64) prefetch_kv(s ^ 1, kt + 1);
        const uint32_t ks_u = kv_u + s * FSTG * 4;
        const uint32_t vs_u = ks_u + 64 * LK * 4;
        const uint32_t kb_base = ks_u + (b_row * LK + b_col) * 4;
        const uint32_t vb_base = vs_u + (b_row * LV + b_col) * 4;

        float rs0 = 0.f, rs1 = 0.f;
        // ---- S = Q K^T in two n32 halves ----
#pragma unroll
        for (int h = 0; h < 2; h++) {
            float cc[4][4];
#pragma unroll
            for (int j = 0; j < 4; j++)
#pragma unroll
                for (int q = 0; q < 4; q++) cc[j][q] = 0.f;
#pragma unroll
            for (int ks = 0; ks < 8; ks++) {
                const int kb = ks * 32;
#pragma unroll
                for (int j2 = 0; j2 < 2; j2++) {
                    uint32_t kb4[4];
                    ldsm4(kb4, kb_base + (h * 32 + j2 * 16) * LK * 4 + kb);
                    mma_tf32(cc[2 * j2],     qf[ks], kb4[0], kb4[1]);
                    mma_tf32(cc[2 * j2 + 1], qf[ks], kb4[2], kb4[3]);
                }
            }
#pragma unroll
            for (int j = 0; j < 4; j++) {
                float e0 = exp2f_fast(cc[j][0]);
                float e1 = exp2f_fast(cc[j][1]);
                float e2 = exp2f_fast(cc[j][2]);
                float e3 = exp2f_fast(cc[j][3]);
                rs0 += e0 + e1;
                rs1 += e2 + e3;
                int colb = (h * 4 + j) * 8 + tg * 2;
                float2 p0; p0.x = tf32r(e0); p0.y = tf32r(e1);
                float2 p1; p1.x = tf32r(e2); p1.y = tf32r(e3);
                *(float2*)&QPs[(r0 + gid)     * LQ + colb] = p0;
                *(float2*)&QPs[(r0 + gid + 8) * LQ + colb] = p1;
            }
        }
        rs0 += __shfl_xor_sync(0xffffffffu, rs0, 1);
        rs0 += __shfl_xor_sync(0xffffffffu, rs0, 2);
        rs1 += __shfl_xor_sync(0xffffffffu, rs1, 1);
        rs1 += __shfl_xor_sync(0xffffffffu, rs1, 2);
        l0 += rs0;
        l1 += rs1;
        __syncwarp();

        // ---- O += P @ V (P rows warp-private; V^T b-frags via ldmatrix) ----
#pragma unroll
        for (int ks = 0; ks < 8; ks++) {
            const int kb = ks * 32;
            uint32_t pa[4];
            ldsm4(pa, qa_base + kb);
#pragma unroll
            for (int j2 = 0; j2 < 4; j2++) {
                uint32_t vb[4];
                ldsm4(vb, vb_base + j2 * 16 * LV * 4 + kb);
                mma_tf32(o[2 * j2],     pa, vb[0], vb[1]);
                mma_tf32(o[2 * j2 + 1], pa, vb[2], vb[3]);
            }
        }
        s ^= 1;
    }

    const int bb = bh / H_, hh = bh - bb * H_;
    const float i0 = 1.f / l0, i1 = 1.f / l1;
    const int row_a = qt * 128 + r0 + gid;
    const int row_b = row_a + 8;
#pragma unroll
    for (int nt = 0; nt < 8; nt++) {
        int col = hh * HD_ + nt * 8 + tg * 2;
        float2 va; va.x = tf32r(o[nt][0] * i0); va.y = tf32r(o[nt][1] * i0);
        float2 vb; vb.x = tf32r(o[nt][2] * i1); vb.y = tf32r(o[nt][3] * i1);
        *(float2*)&g_AO[((size_t)(bb * N_ + row_a)) * D_ + col] = va;
        *(float2*)&g_AO[((size_t)(bb * N_ + row_b)) * D_ + col] = vb;
    }
}

// ---------------------------------------------------------------------------
// q_attn: parallel two-pass (passing)
// ---------------------------------------------------------------------------
__global__ void __launch_bounds__(256)
qattn_partial(float* __restrict__ out1)
{
    const int bh = blockIdx.y, kb = blockIdx.x;
    __shared__ float q0[64];
    __shared__ float red[256];
    const int tid = threadIdx.x;
    if (tid < 64) q0[tid] = g_Q[((size_t)bh * N_) * HD_ + tid];
    __syncthreads();

    const int j = kb * 256 + tid;
    const float4* kp = (const float4*)&g_K[((size_t)bh * N_ + j) * HD_];
    float s = 0.f;
#pragma unroll
    for (int i = 0; i < 16; i++) {
        float4 v = kp[i];
        s += v.x * q0[i * 4 + 0] + v.y * q0[i * 4 + 1]
           + v.z * q0[i * 4 + 2] + v.w * q0[i * 4 + 3];
    }
    float e = exp2f_fast(s);
    out1[(size_t)bh * N_ + j] = e;

    red[tid] = e; __syncthreads();
    for (int off = 128; off > 0; off >>= 1) {
        if (tid < off) red[tid] += red[tid + off];
        __syncthreads();
    }
    if (tid == 0) g_PS[bh * 8 + kb] = red[0];
}

__global__ void __launch_bounds__(256)
qattn_norm(float* __restrict__ out1)
{
    const int bh = blockIdx.x;
    __shared__ float inv_s;
    if (threadIdx.x == 0) {
        float s = 0.f;
#pragma unroll
        for (int i = 0; i < 8; i++) s += g_PS[bh * 8 + i];
        inv_s = 1.f / s;
    }
    __syncthreads();
    const float inv = inv_s;
#pragma unroll
    for (int it = 0; it < 8; it++)
        out1[(size_t)bh * N_ + threadIdx.x + it * 256] *= inv;
}

// ---------------------------------------------------------------------------
extern "C" void kernel_launch(void* const* d_in, const int* in_sizes, int n_in,
                              void* d_out, int out_size)
{
    const float* x      = (const float*)d_in[0];
    const float* w_qkv  = (const float*)d_in[1];
    const float* w_proj = (const float*)d_in[2];
    const float* b_proj = (const float*)d_in[3];
    float* out = (float*)d_out;
    float* out_qattn = out + ((size_t)out_size - (size_t)B_ * H_ * N_);

    const int gemm_smem  = 3 * GSTG * (int)sizeof(float);              // 110592
    const int flash_smem = (128 * LQ + 2 * FSTG) * (int)sizeof(float); // 104448
    cudaFuncSetAttribute(mma_gemm<1>,
                         cudaFuncAttributeMaxDynamicSharedMemorySize, gemm_smem);
    cudaFuncSetAttribute(mma_gemm<0>,
                         cudaFuncAttributeMaxDynamicSharedMemorySize, gemm_smem);
    cudaFuncSetAttribute(flash_mma_kernel,
                         cudaFuncAttributeMaxDynamicSharedMemorySize, flash_smem);

    // 0) pre-round x; transpose+round weights (device-global destinations)
    round_x<<<1536, 256>>>(x);
    {
        dim3 g1((3 * D_) / 32, D_ / 32);
        transpose_tf32<1><<<g1, 256>>>(w_qkv, D_, 3 * D_);
        dim3 g2(D_ / 32, D_ / 32);
        transpose_tf32<0><<<g2, 256>>>(w_proj, D_, D_);
    }
    // 1) QKV GEMM -> g_Q(xQS_)/g_K/g_Vt
    {
        dim3 grid((3 * D_) / 128, (B_ * N_) / 128);
        mma_gemm<1><<<grid, 256, gemm_smem>>>(nullptr, nullptr,
                                              B_ * N_, D_, 3 * D_);
    }
    // 2) q=0 attention row
    {
        dim3 grid(8, 48);
        qattn_partial<<<grid, 256>>>(out_qattn);
        qattn_norm<<<48, 256>>>(out_qattn);
    }
    // 3) Flash attention -> g_AO
    {
        dim3 grid(N_ / 128, B_ * H_);
        flash_mma_kernel<<<grid, 256, flash_smem>>>();
    }
    // 4) Projection GEMM + bias
    {
        dim3 grid(D_ / 128, (B_ * N_) / 128);
        mma_gemm<0><<<grid, 256, gemm_smem>>>(b_proj, out,
                                              B_ * N_, D_, D_);
    }
}

// round 11
// speedup vs baseline: 5.7370x; 1.5478x over previous
#include <cuda_runtime.h>
#include <cuda_fp16.h>
#include <math.h>
#include <stdint.h>

#define B_ 4
#define N_ 2048
#define D_ 768
#define H_ 12
#define HD_ 64
#define QS_ 0.18033688011112042f   // 0.125 * log2(e)
#define SAH 40   // GEMM A/B smem stride (halves): 80B rows -> ldsm conflict-free
#define LQH 72   // flash Q/P stride (halves): 144B rows
#define LKH 72
#define LVH 72

// fp16 scratch (allocation-free __device__ globals)
__device__ __half g_Xh [(size_t)B_*N_*D_];
__device__ __half g_Wqh[(size_t)3*D_*D_];     // W_qkv^T [3D][D]
__device__ __half g_Wph[(size_t)D_*D_];       // W_proj^T [D][D]
__device__ __half g_Qh [(size_t)B_*H_*N_*HD_]; // pre-scaled by QS_
__device__ __half g_Kh [(size_t)B_*H_*N_*HD_];
__device__ __half g_Vh [(size_t)B_*H_*N_*HD_]; // natural [key][hd]
__device__ __half g_AOh[(size_t)B_*N_*D_];
__device__ float  g_PS [48 * 8];

// ============================ helpers ======================================
__device__ __forceinline__ uint32_t smem_u32(const void* p) {
    uint32_t a;
    asm("{ .reg .u64 t; cvta.to.shared.u64 t, %1; cvt.u32.u64 %0, t; }"
        : "=r"(a) : "l"(p));
    return a;
}
__device__ __forceinline__ void cp16(uint32_t dst, const void* src) {
    asm volatile("cp.async.cg.shared.global [%0], [%1], 16;"
                 :: "r"(dst), "l"(src));
}
__device__ __forceinline__ void cp_commit() {
    asm volatile("cp.async.commit_group;");
}
__device__ __forceinline__ void cp_wait0() {
    asm volatile("cp.async.wait_group 0;");
}
__device__ __forceinline__ void cp_wait1() {
    asm volatile("cp.async.wait_group 1;");
}
__device__ __forceinline__ void ldsm4(uint32_t r[4], uint32_t addr) {
    asm volatile("ldmatrix.sync.aligned.m8n8.x4.shared.b16 {%0,%1,%2,%3}, [%4];"
                 : "=r"(r[0]), "=r"(r[1]), "=r"(r[2]), "=r"(r[3]) : "r"(addr));
}
__device__ __forceinline__ void ldsm4t(uint32_t r[4], uint32_t addr) {
    asm volatile("ldmatrix.sync.aligned.m8n8.x4.trans.shared.b16 {%0,%1,%2,%3}, [%4];"
                 : "=r"(r[0]), "=r"(r[1]), "=r"(r[2]), "=r"(r[3]) : "r"(addr));
}
__device__ __forceinline__ void mma_f16(float c[4], const uint32_t a[4],
                                        uint32_t b0, uint32_t b1) {
    asm volatile(
        "mma.sync.aligned.m16n8k16.row.col.f32.f16.f16.f32 "
        "{%0,%1,%2,%3}, {%4,%5,%6,%7}, {%8,%9}, {%0,%1,%2,%3};"
        : "+f"(c[0]), "+f"(c[1]), "+f"(c[2]), "+f"(c[3])
        : "r"(a[0]), "r"(a[1]), "r"(a[2]), "r"(a[3]), "r"(b0), "r"(b1));
}
__device__ __forceinline__ float exp2f_fast(float x) {
    float k = rintf(x);
    float f = x - k;
    float p = 1.33335581464e-3f;
    p = fmaf(p, f, 9.61812910763e-3f);
    p = fmaf(p, f, 5.55041086648e-2f);
    p = fmaf(p, f, 2.40226506959e-1f);
    p = fmaf(p, f, 6.93147180560e-1f);
    p = fmaf(p, f, 1.0f);
    int ik = (int)k;
    return p * __int_as_float((ik + 127) << 23);
}

// ===========================================================================
// Pre-pass A: convert x -> fp16
// ===========================================================================
__global__ void __launch_bounds__(256)
round_x(const float* __restrict__ x)
{
    const int total = (B_ * N_ * D_) / 4;
    for (int i = blockIdx.x * blockDim.x + threadIdx.x; i < total;
         i += gridDim.x * blockDim.x) {
        float4 v = ((const float4*)x)[i];
        __half2* d = (__half2*)&g_Xh[(size_t)i * 4];
        d[0] = __floats2half2_rn(v.x, v.y);
        d[1] = __floats2half2_rn(v.z, v.w);
    }
}

// ===========================================================================
// Pre-pass B: transpose + fp16 both weights in one launch.
// z==0: w_qkv [768][2304] -> g_Wqh [2304][768]; z==1: w_proj -> g_Wph.
// ===========================================================================
__global__ void __launch_bounds__(256)
transpose_w(const float* __restrict__ wq, const float* __restrict__ wp)
{
    const int z = blockIdx.z;
    if (z == 1 && blockIdx.x >= D_ / 32) return;
    const float* src = z ? wp : wq;
    __half* dst = z ? g_Wph : g_Wqh;
    const int ND = z ? D_ : 3 * D_;
    __shared__ float t[32][33];
    const int tid = threadIdx.x;
    const int tx = tid & 31, ty = tid >> 5;
    const int bx = blockIdx.x * 32, by = blockIdx.y * 32;
#pragma unroll
    for (int i = 0; i < 4; i++) {
        int k = by + ty + i * 8;
        t[ty + i * 8][tx] = src[(size_t)k * ND + bx + tx];
    }
    __syncthreads();
#pragma unroll
    for (int i = 0; i < 4; i++) {
        int n = bx + ty + i * 8;
        dst[(size_t)n * D_ + by + tx] = __float2half_rn(t[tx][ty + i * 8]);
    }
}

// ===========================================================================
// fp16 mma.sync GEMM (m16n8k16), 3-stage cp.async, ldmatrix frags.
// A [m][k] halves; B [n][k] halves (W^T). 128x128 tile, BK=32 halves.
// EPI==1: A=g_Xh, B=g_Wqh -> Q(xQS_)/K/V (all natural fp16).
// EPI==0: A=g_AOh, B=g_Wph, +bias -> float C.
// ===========================================================================
#define GSTG_B (2 * 128 * SAH * 2)   // stage bytes = 20480 (A 10240 + B 10240)
template<int EPI>
__global__ void __launch_bounds__(256, 2)
mma_gemm(const float* __restrict__ bias, float* __restrict__ C,
         int M, int Kd, int Nn)
{
    const __half* A  = (EPI == 0) ? (const __half*)g_AOh : (const __half*)g_Xh;
    const __half* Bw = (EPI == 0) ? (const __half*)g_Wph : (const __half*)g_Wqh;
    extern __shared__ __half smh[];
    const uint32_t s_u32 = smem_u32(smh);
    const int tid = threadIdx.x;
    const int wid = tid >> 5, lane = tid & 31;
    const int gid = lane >> 2, tg = lane & 3;
    const int warp_m = wid & 3, warp_n = wid >> 2;
    const int m0 = blockIdx.y * 128, n0 = blockIdx.x * 128;

    float c[2][8][4];
#pragma unroll
    for (int mt = 0; mt < 2; mt++)
#pragma unroll
        for (int nt = 0; nt < 8; nt++)
#pragma unroll
            for (int j = 0; j < 4; j++) c[mt][nt][j] = 0.f;

    auto prefetch = [&](int stg, int k0) {   // k0 in halves
        uint32_t as = s_u32 + stg * GSTG_B;
        uint32_t bs = as + 128 * SAH * 2;
#pragma unroll
        for (int it = 0; it < 2; it++) {
            int idx = tid + it * 256;        // 0..511
            int row = idx >> 2, seg = idx & 3;
            cp16(as + (row * SAH + seg * 8) * 2,
                 &A[(size_t)(m0 + row) * Kd + k0 + seg * 8]);
            cp16(bs + (row * SAH + seg * 8) * 2,
                 &Bw[(size_t)(n0 + row) * Kd + k0 + seg * 8]);
        }
        cp_commit();
    };

    const int ntiles = Kd / 32;
    prefetch(0, 0);
    prefetch(1, 32);
#pragma unroll 1
    for (int t = 0; t < ntiles; t++) {
        cp_wait1();
        __syncthreads();
        if (t + 2 < ntiles) prefetch((t + 2) % 3, (t + 2) * 32);
        else cp_commit();
        const uint32_t as_u = s_u32 + (t % 3) * GSTG_B;
        const uint32_t bs_u = as_u + 128 * SAH * 2;
        const uint32_t a_adr = as_u + ((warp_m * 32 + (lane & 15)) * SAH + (lane >> 4) * 8) * 2;
        const uint32_t b_adr = bs_u + ((warp_n * 64 + (lane & 15)) * SAH + (lane >> 4) * 8) * 2;
#pragma unroll
        for (int ks = 0; ks < 2; ks++) {
            const int kb = ks * 32;          // 16 halves
            uint32_t a0[4], a1[4];
            ldsm4(a0, a_adr + kb);
            ldsm4(a1, a_adr + 16 * SAH * 2 + kb);
#pragma unroll
            for (int j = 0; j < 4; j++) {
                uint32_t bb[4];
                ldsm4(bb, b_adr + j * 16 * SAH * 2 + kb);
                mma_f16(c[0][2 * j],     a0, bb[0], bb[2]);
                mma_f16(c[0][2 * j + 1], a0, bb[1], bb[3]);
                mma_f16(c[1][2 * j],     a1, bb[0], bb[2]);
                mma_f16(c[1][2 * j + 1], a1, bb[1], bb[3]);
            }
        }
    }

#pragma unroll
    for (int mt = 0; mt < 2; mt++) {
#pragma unroll
        for (int nt = 0; nt < 8; nt++) {
            int r0 = m0 + warp_m * 32 + mt * 16 + gid;
            int col = n0 + warp_n * 64 + nt * 8 + tg * 2;
#pragma unroll
            for (int h = 0; h < 2; h++) {
                int r = r0 + h * 8;
                float vx = c[mt][nt][h * 2 + 0];
                float vy = c[mt][nt][h * 2 + 1];
                if (EPI == 0) {
                    float2 v; v.x = vx + bias[col]; v.y = vy + bias[col + 1];
                    *(float2*)&C[(size_t)r * Nn + col] = v;
                } else {
                    int bb = r >> 11, tok = r & 2047;
                    int which = col / D_;
                    int rem = col - which * D_;
                    int hh = rem >> 6, hd = rem & 63;
                    __half* dst = (which == 0) ? g_Qh : (which == 1) ? g_Kh : g_Vh;
                    float sc = (which == 0) ? QS_ : 1.f;
                    *(__half2*)&dst[(((size_t)(bb * H_ + hh)) * N_ + tok) * HD_ + hd] =
                        __floats2half2_rn(vx * sc, vy * sc);
                }
            }
        }
    }
}

// ===========================================================================
// Flash attention fp16: Br=128, Bc=64, 2-stage K/V, ldmatrix (V via .trans).
// Q frags in regs; Q smem region reused as P (warp-private rows).
// ===========================================================================
#define FQP_B (128 * LQH * 2)        // 18432 bytes
#define FKV_B (2 * 64 * LKH * 2)     // K+V per stage = 18432 bytes
__global__ void __launch_bounds__(256, 2)
flash_mma_kernel()
{
    extern __shared__ __half smf[];
    __half* QPs = smf;                       // [128][LQH]
    const uint32_t qps_u = smem_u32(smf);
    const uint32_t kv_u  = qps_u + FQP_B;    // 2 stages of (K, V)

    const int tid = threadIdx.x;
    const int wid = tid >> 5, lane = tid & 31;
    const int gid = lane >> 2, tg = lane & 3;
    const int bh = blockIdx.y, qt = blockIdx.x;
    const int r0 = wid * 16;
    const __half* Qg = g_Qh + ((size_t)bh * N_ + qt * 128) * HD_;
    const __half* Kg = g_Kh + (size_t)bh * N_ * HD_;
    const __half* Vg = g_Vh + (size_t)bh * N_ * HD_;

    auto prefetch_kv = [&](int stg, int kt) {
        uint32_t ks = kv_u + stg * FKV_B;
        uint32_t vs = ks + 64 * LKH * 2;
#pragma unroll
        for (int it = 0; it < 2; it++) {
            int idx = tid + it * 256;        // 0..511
            int row = idx >> 3, seg = idx & 7;
            cp16(ks + (row * LKH + seg * 8) * 2,
                 &Kg[(size_t)(kt * 64 + row) * HD_ + seg * 8]);
            cp16(vs + (row * LVH + seg * 8) * 2,
                 &Vg[(size_t)(kt * 64 + row) * HD_ + seg * 8]);
        }
        cp_commit();
    };

    // stage Q (128 rows x 128B)
#pragma unroll
    for (int it = 0; it < 4; it++) {
        int idx = tid + it * 256;            // 0..1023
        int row = idx >> 3, seg = idx & 7;
        cp16(qps_u + (row * LQH + seg * 8) * 2, &Qg[row * HD_ + seg * 8]);
    }
    cp_commit();
    prefetch_kv(0, 0);
    cp_wait0();
    __syncthreads();

    // Q fragments (4 k16 steps), live whole kernel
    const uint32_t qa_adr = qps_u + ((r0 + (lane & 15)) * LQH + (lane >> 4) * 8) * 2;
    uint32_t qf[4][4];
#pragma unroll
    for (int ks = 0; ks < 4; ks++) ldsm4(qf[ks], qa_adr + ks * 32);

    float o[8][4];
#pragma unroll
    for (int nt = 0; nt < 8; nt++)
#pragma unroll
        for (int j = 0; j < 4; j++) o[nt][j] = 0.f;
    float l0 = 0.f, l1 = 0.f;

    int s = 0;
#pragma unroll 1
    for (int kt = 0; kt < N_ / 64; kt++) {
        if (kt > 0) { cp_wait0(); __syncthreads(); }
        if (kt + 1 < N_ / 64) prefetch_kv(s ^ 1, kt + 1);
        const uint32_t ks_u = kv_u + s * FKV_B;
        const uint32_t vs_u = ks_u + 64 * LKH * 2;
        // K b-frags: [key n][hd k] non-trans
        const uint32_t kb_adr = ks_u + ((lane & 15) * LKH + (lane >> 4) * 8) * 2;
        // V b-frags: [key k][hd n] with .trans
        const uint32_t vb_adr = vs_u +
            (((lane & 7) + ((lane >> 3) & 1) * 8) * LVH + ((lane >> 4) & 1) * 8) * 2;

        // ---- S = Q K^T ----
        float cc[8][4];
#pragma unroll
        for (int nt = 0; nt < 8; nt++)
#pragma unroll
            for (int q = 0; q < 4; q++) cc[nt][q] = 0.f;
#pragma unroll
        for (int ks = 0; ks < 4; ks++) {
            const int kb = ks * 32;
#pragma unroll
            for (int g = 0; g < 4; g++) {
                uint32_t kk[4];
                ldsm4(kk, kb_adr + g * 16 * LKH * 2 + kb);
                mma_f16(cc[2 * g],     qf[ks], kk[0], kk[2]);
                mma_f16(cc[2 * g + 1], qf[ks], kk[1], kk[3]);
            }
        }

        // ---- P = exp2(S), row sums, store P (fp16) ----
        float rs0 = 0.f, rs1 = 0.f;
#pragma unroll
        for (int nt = 0; nt < 8; nt++) {
            float e0 = exp2f_fast(cc[nt][0]);
            float e1 = exp2f_fast(cc[nt][1]);
            float e2 = exp2f_fast(cc[nt][2]);
            float e3 = exp2f_fast(cc[nt][3]);
            rs0 += e0 + e1;
            rs1 += e2 + e3;
            *(__half2*)&QPs[(r0 + gid)     * LQH + nt * 8 + tg * 2] = __floats2half2_rn(e0, e1);
            *(__half2*)&QPs[(r0 + gid + 8) * LQH + nt * 8 + tg * 2] = __floats2half2_rn(e2, e3);
        }
        rs0 += __shfl_xor_sync(0xffffffffu, rs0, 1);
        rs0 += __shfl_xor_sync(0xffffffffu, rs0, 2);
        rs1 += __shfl_xor_sync(0xffffffffu, rs1, 1);
        rs1 += __shfl_xor_sync(0xffffffffu, rs1, 2);
        l0 += rs0;
        l1 += rs1;
        __syncwarp();

        // ---- O += P @ V ----
#pragma unroll
        for (int ks = 0; ks < 4; ks++) {     // keys in chunks of 16
            uint32_t pa[4];
            ldsm4(pa, qa_adr + ks * 32);
#pragma unroll
            for (int g = 0; g < 4; g++) {    // hd in chunks of 16
                uint32_t vv[4];
                ldsm4t(vv, vb_adr + ks * 16 * LVH * 2 + g * 32);
                mma_f16(o[2 * g],     pa, vv[0], vv[1]);
                mma_f16(o[2 * g + 1], pa, vv[2], vv[3]);
            }
        }
        s ^= 1;
    }

    // epilogue: normalize, fp16, write (b, n, h*64+hd)
    const int bb = bh / H_, hh = bh - bb * H_;
    const float i0 = 1.f / l0, i1 = 1.f / l1;
    const int row_a = qt * 128 + r0 + gid;
    const int row_b = row_a + 8;
#pragma unroll
    for (int nt = 0; nt < 8; nt++) {
        int col = hh * HD_ + nt * 8 + tg * 2;
        *(__half2*)&g_AOh[((size_t)(bb * N_ + row_a)) * D_ + col] =
            __floats2half2_rn(o[nt][0] * i0, o[nt][1] * i0);
        *(__half2*)&g_AOh[((size_t)(bb * N_ + row_b)) * D_ + col] =
            __floats2half2_rn(o[nt][2] * i1, o[nt][3] * i1);
    }
}

// ---------------------------------------------------------------------------
// q_attn: parallel two-pass, fp32 math on fp16 Q/K.
// ---------------------------------------------------------------------------
__global__ void __launch_bounds__(256)
qattn_partial(float* __restrict__ out1)
{
    const int bh = blockIdx.y, kb = blockIdx.x;
    __shared__ float q0[64];
    __shared__ float red[256];
    const int tid = threadIdx.x;
    if (tid < 64) q0[tid] = __half2float(g_Qh[((size_t)bh * N_) * HD_ + tid]);
    __syncthreads();

    const int j = kb * 256 + tid;
    const __half2* kp = (const __half2*)&g_Kh[((size_t)bh * N_ + j) * HD_];
    float s = 0.f;
#pragma unroll
    for (int i = 0; i < 32; i++) {
        float2 f = __half22float2(kp[i]);
        s += f.x * q0[2 * i] + f.y * q0[2 * i + 1];
    }
    float e = exp2f_fast(s);
    out1[(size_t)bh * N_ + j] = e;

    red[tid] = e; __syncthreads();
    for (int off = 128; off > 0; off >>= 1) {
        if (tid < off) red[tid] += red[tid + off];
        __syncthreads();
    }
    if (tid == 0) g_PS[bh * 8 + kb] = red[0];
}

__global__ void __launch_bounds__(256)
qattn_norm(float* __restrict__ out1)
{
    const int bh = blockIdx.x;
    __shared__ float inv_s;
    if (threadIdx.x == 0) {
        float s = 0.f;
#pragma unroll
        for (int i = 0; i < 8; i++) s += g_PS[bh * 8 + i];
        inv_s = 1.f / s;
    }
    __syncthreads();
    const float inv = inv_s;
#pragma unroll
    for (int it = 0; it < 8; it++)
        out1[(size_t)bh * N_ + threadIdx.x + it * 256] *= inv;
}

// ---------------------------------------------------------------------------
extern "C" void kernel_launch(void* const* d_in, const int* in_sizes, int n_in,
                              void* d_out, int out_size)
{
    const float* x      = (const float*)d_in[0];
    const float* w_qkv  = (const float*)d_in[1];
    const float* w_proj = (const float*)d_in[2];
    const float* b_proj = (const float*)d_in[3];
    float* out = (float*)d_out;
    float* out_qattn = out + ((size_t)out_size - (size_t)B_ * H_ * N_);

    const int gemm_smem  = 3 * GSTG_B;           // 61440
    const int flash_smem = FQP_B + 2 * FKV_B;    // 55296
    cudaFuncSetAttribute(mma_gemm<1>,
                         cudaFuncAttributeMaxDynamicSharedMemorySize, gemm_smem);
    cudaFuncSetAttribute(mma_gemm<0>,
                         cudaFuncAttributeMaxDynamicSharedMemorySize, gemm_smem);
    cudaFuncSetAttribute(flash_mma_kernel,
                         cudaFuncAttributeMaxDynamicSharedMemorySize, flash_smem);

    // 0) fp16 prepass: x convert; weights transpose+convert (one launch)
    round_x<<<1536, 256>>>(x);
    {
        dim3 g((3 * D_) / 32, D_ / 32, 2);
        transpose_w<<<g, 256>>>(w_qkv, w_proj);
    }
    // 1) QKV GEMM -> g_Qh(xQS_)/g_Kh/g_Vh
    {
        dim3 grid((3 * D_) / 128, (B_ * N_) / 128);
        mma_gemm<1><<<grid, 256, gemm_smem>>>(nullptr, nullptr,
                                              B_ * N_, D_, 3 * D_);
    }
    // 2) q=0 attention row
    {
        dim3 grid(8, 48);
        qattn_partial<<<grid, 256>>>(out_qattn);
        qattn_norm<<<48, 256>>>(out_qattn);
    }
    // 3) Flash attention -> g_AOh
    {
        dim3 grid(N_ / 128, B_ * H_);
        flash_mma_kernel<<<grid, 256, flash_smem>>>();
    }
    // 4) Projection GEMM + bias -> float out
    {
        dim3 grid(D_ / 128, (B_ * N_) / 128);
        mma_gemm<0><<<grid, 256, gemm_smem>>>(b_proj, out,
                                              B_ * N_, D_, D_);
    }
}

// round 12
// speedup vs baseline: 6.1050x; 1.0641x over previous
#include <cuda_runtime.h>
#include <cuda_fp16.h>
#include <math.h>
#include <stdint.h>

#define B_ 4
#define N_ 2048
#define D_ 768
#define H_ 12
#define HD_ 64
#define QS_ 0.18033688011112042f   // 0.125 * log2(e)
#define SAH 40   // GEMM A/B smem stride (halves)
#define LQH 72   // flash Q stride (halves)
#define LKH 72
#define LVH 72

// fp16 scratch (allocation-free __device__ globals)
__device__ __half g_Xh [(size_t)B_*N_*D_];
__device__ __half g_Wqh[(size_t)3*D_*D_];     // W_qkv^T [3D][D]
__device__ __half g_Wph[(size_t)D_*D_];       // W_proj^T [D][D]
__device__ __half g_Qh [(size_t)B_*H_*N_*HD_]; // pre-scaled by QS_
__device__ __half g_Kh [(size_t)B_*H_*N_*HD_];
__device__ __half g_Vh [(size_t)B_*H_*N_*HD_]; // natural [key][hd]
__device__ __half g_AOh[(size_t)B_*N_*D_];
__device__ float  g_PS [48 * 8];

// ============================ helpers ======================================
__device__ __forceinline__ uint32_t smem_u32(const void* p) {
    uint32_t a;
    asm("{ .reg .u64 t; cvta.to.shared.u64 t, %1; cvt.u32.u64 %0, t; }"
        : "=r"(a) : "l"(p));
    return a;
}
__device__ __forceinline__ void cp16(uint32_t dst, const void* src) {
    asm volatile("cp.async.cg.shared.global [%0], [%1], 16;"
                 :: "r"(dst), "l"(src));
}
__device__ __forceinline__ void cp_commit() {
    asm volatile("cp.async.commit_group;");
}
__device__ __forceinline__ void cp_wait0() {
    asm volatile("cp.async.wait_group 0;");
}
__device__ __forceinline__ void cp_wait1() {
    asm volatile("cp.async.wait_group 1;");
}
__device__ __forceinline__ void ldsm4(uint32_t r[4], uint32_t addr) {
    asm volatile("ldmatrix.sync.aligned.m8n8.x4.shared.b16 {%0,%1,%2,%3}, [%4];"
                 : "=r"(r[0]), "=r"(r[1]), "=r"(r[2]), "=r"(r[3]) : "r"(addr));
}
__device__ __forceinline__ void ldsm4t(uint32_t r[4], uint32_t addr) {
    asm volatile("ldmatrix.sync.aligned.m8n8.x4.trans.shared.b16 {%0,%1,%2,%3}, [%4];"
                 : "=r"(r[0]), "=r"(r[1]), "=r"(r[2]), "=r"(r[3]) : "r"(addr));
}
__device__ __forceinline__ void mma_f16(float c[4], const uint32_t a[4],
                                        uint32_t b0, uint32_t b1) {
    asm volatile(
        "mma.sync.aligned.m16n8k16.row.col.f32.f16.f16.f32 "
        "{%0,%1,%2,%3}, {%4,%5,%6,%7}, {%8,%9}, {%0,%1,%2,%3};"
        : "+f"(c[0]), "+f"(c[1]), "+f"(c[2]), "+f"(c[3])
        : "r"(a[0]), "r"(a[1]), "r"(a[2]), "r"(a[3]), "r"(b0), "r"(b1));
}
__device__ __forceinline__ float exp2f_fast(float x) {
    float k = rintf(x);
    float f = x - k;
    float p = 1.33335581464e-3f;
    p = fmaf(p, f, 9.61812910763e-3f);
    p = fmaf(p, f, 5.55041086648e-2f);
    p = fmaf(p, f, 2.40226506959e-1f);
    p = fmaf(p, f, 6.93147180560e-1f);
    p = fmaf(p, f, 1.0f);
    int ik = (int)k;
    return p * __int_as_float((ik + 127) << 23);
}
__device__ __forceinline__ uint32_t pack_h2(float a, float b) {
    __half2 h = __floats2half2_rn(a, b);
    return *(uint32_t*)&h;
}

// ===========================================================================
// Pre-pass A: convert x -> fp16
// ===========================================================================
__global__ void __launch_bounds__(256)
round_x(const float* __restrict__ x)
{
    const int total = (B_ * N_ * D_) / 4;
    for (int i = blockIdx.x * blockDim.x + threadIdx.x; i < total;
         i += gridDim.x * blockDim.x) {
        float4 v = ((const float4*)x)[i];
        __half2* d = (__half2*)&g_Xh[(size_t)i * 4];
        d[0] = __floats2half2_rn(v.x, v.y);
        d[1] = __floats2half2_rn(v.z, v.w);
    }
}

// ===========================================================================
// Pre-pass B: transpose + fp16 both weights in one launch.
// ===========================================================================
__global__ void __launch_bounds__(256)
transpose_w(const float* __restrict__ wq, const float* __restrict__ wp)
{
    const int z = blockIdx.z;
    if (z == 1 && blockIdx.x >= D_ / 32) return;
    const float* src = z ? wp : wq;
    __half* dst = z ? g_Wph : g_Wqh;
    const int ND = z ? D_ : 3 * D_;
    __shared__ float t[32][33];
    const int tid = threadIdx.x;
    const int tx = tid & 31, ty = tid >> 5;
    const int bx = blockIdx.x * 32, by = blockIdx.y * 32;
#pragma unroll
    for (int i = 0; i < 4; i++) {
        int k = by + ty + i * 8;
        t[ty + i * 8][tx] = src[(size_t)k * ND + bx + tx];
    }
    __syncthreads();
#pragma unroll
    for (int i = 0; i < 4; i++) {
        int n = bx + ty + i * 8;
        dst[(size_t)n * D_ + by + tx] = __float2half_rn(t[tx][ty + i * 8]);
    }
}

// ===========================================================================
// fp16 mma.sync GEMM (m16n8k16), 3-stage cp.async, ldmatrix frags. (passing)
// ===========================================================================
#define GSTG_B (2 * 128 * SAH * 2)   // stage bytes = 20480
template<int EPI>
__global__ void __launch_bounds__(256, 2)
mma_gemm(const float* __restrict__ bias, float* __restrict__ C,
         int M, int Kd, int Nn)
{
    const __half* A  = (EPI == 0) ? (const __half*)g_AOh : (const __half*)g_Xh;
    const __half* Bw = (EPI == 0) ? (const __half*)g_Wph : (const __half*)g_Wqh;
    extern __shared__ __half smh[];
    const uint32_t s_u32 = smem_u32(smh);
    const int tid = threadIdx.x;
    const int wid = tid >> 5, lane = tid & 31;
    const int gid = lane >> 2, tg = lane & 3;
    const int warp_m = wid & 3, warp_n = wid >> 2;
    const int m0 = blockIdx.y * 128, n0 = blockIdx.x * 128;

    float c[2][8][4];
#pragma unroll
    for (int mt = 0; mt < 2; mt++)
#pragma unroll
        for (int nt = 0; nt < 8; nt++)
#pragma unroll
            for (int j = 0; j < 4; j++) c[mt][nt][j] = 0.f;

    auto prefetch = [&](int stg, int k0) {
        uint32_t as = s_u32 + stg * GSTG_B;
        uint32_t bs = as + 128 * SAH * 2;
#pragma unroll
        for (int it = 0; it < 2; it++) {
            int idx = tid + it * 256;
            int row = idx >> 2, seg = idx & 3;
            cp16(as + (row * SAH + seg * 8) * 2,
                 &A[(size_t)(m0 + row) * Kd + k0 + seg * 8]);
            cp16(bs + (row * SAH + seg * 8) * 2,
                 &Bw[(size_t)(n0 + row) * Kd + k0 + seg * 8]);
        }
        cp_commit();
    };

    const int ntiles = Kd / 32;
    prefetch(0, 0);
    prefetch(1, 32);
#pragma unroll 1
    for (int t = 0; t < ntiles; t++) {
        cp_wait1();
        __syncthreads();
        if (t + 2 < ntiles) prefetch((t + 2) % 3, (t + 2) * 32);
        else cp_commit();
        const uint32_t as_u = s_u32 + (t % 3) * GSTG_B;
        const uint32_t bs_u = as_u + 128 * SAH * 2;
        const uint32_t a_adr = as_u + ((warp_m * 32 + (lane & 15)) * SAH + (lane >> 4) * 8) * 2;
        const uint32_t b_adr = bs_u + ((warp_n * 64 + (lane & 15)) * SAH + (lane >> 4) * 8) * 2;
#pragma unroll
        for (int ks = 0; ks < 2; ks++) {
            const int kb = ks * 32;
            uint32_t a0[4], a1[4];
            ldsm4(a0, a_adr + kb);
            ldsm4(a1, a_adr + 16 * SAH * 2 + kb);
#pragma unroll
            for (int j = 0; j < 4; j++) {
                uint32_t bb[4];
                ldsm4(bb, b_adr + j * 16 * SAH * 2 + kb);
                mma_f16(c[0][2 * j],     a0, bb[0], bb[2]);
                mma_f16(c[0][2 * j + 1], a0, bb[1], bb[3]);
                mma_f16(c[1][2 * j],     a1, bb[0], bb[2]);
                mma_f16(c[1][2 * j + 1], a1, bb[1], bb[3]);
            }
        }
    }

#pragma unroll
    for (int mt = 0; mt < 2; mt++) {
#pragma unroll
        for (int nt = 0; nt < 8; nt++) {
            int r0 = m0 + warp_m * 32 + mt * 16 + gid;
            int col = n0 + warp_n * 64 + nt * 8 + tg * 2;
#pragma unroll
            for (int h = 0; h < 2; h++) {
                int r = r0 + h * 8;
                float vx = c[mt][nt][h * 2 + 0];
                float vy = c[mt][nt][h * 2 + 1];
                if (EPI == 0) {
                    float2 v; v.x = vx + bias[col]; v.y = vy + bias[col + 1];
                    *(float2*)&C[(size_t)r * Nn + col] = v;
                } else {
                    int bb = r >> 11, tok = r & 2047;
                    int which = col / D_;
                    int rem = col - which * D_;
                    int hh = rem >> 6, hd = rem & 63;
                    __half* dst = (which == 0) ? g_Qh : (which == 1) ? g_Kh : g_Vh;
                    float sc = (which == 0) ? QS_ : 1.f;
                    *(__half2*)&dst[(((size_t)(bb * H_ + hh)) * N_ + tok) * HD_ + hd] =
                        __floats2half2_rn(vx * sc, vy * sc);
                }
            }
        }
    }
}

// ===========================================================================
// Flash attention fp16: Br=128, Bc=64, 3-stage K/V, P kept in REGISTERS
// (FA-2 C->A fragment repack; no P smem traffic, no syncwarp).
// ===========================================================================
#define FQP_B (128 * LQH * 2)        // 18432 bytes (Q staging)
#define FKV_B (2 * 64 * LKH * 2)     // K+V per stage = 18432 bytes
__global__ void __launch_bounds__(256, 2)
flash_mma_kernel()
{
    extern __shared__ __half smf[];
    const uint32_t qps_u = smem_u32(smf);
    const uint32_t kv_u  = qps_u + FQP_B;    // 3 stages of (K, V)

    const int tid = threadIdx.x;
    const int wid = tid >> 5, lane = tid & 31;
    const int gid = lane >> 2, tg = lane & 3;
    const int bh = blockIdx.y, qt = blockIdx.x;
    const int r0 = wid * 16;
    const __half* Qg = g_Qh + ((size_t)bh * N_ + qt * 128) * HD_;
    const __half* Kg = g_Kh + (size_t)bh * N_ * HD_;
    const __half* Vg = g_Vh + (size_t)bh * N_ * HD_;

    auto prefetch_kv = [&](int stg, int kt) {
        uint32_t ks = kv_u + stg * FKV_B;
        uint32_t vs = ks + 64 * LKH * 2;
#pragma unroll
        for (int it = 0; it < 2; it++) {
            int idx = tid + it * 256;
            int row = idx >> 3, seg = idx & 7;
            cp16(ks + (row * LKH + seg * 8) * 2,
                 &Kg[(size_t)(kt * 64 + row) * HD_ + seg * 8]);
            cp16(vs + (row * LVH + seg * 8) * 2,
                 &Vg[(size_t)(kt * 64 + row) * HD_ + seg * 8]);
        }
        cp_commit();
    };

    // stage Q
#pragma unroll
    for (int it = 0; it < 4; it++) {
        int idx = tid + it * 256;
        int row = idx >> 3, seg = idx & 7;
        cp16(qps_u + (row * LQH + seg * 8) * 2, &Qg[row * HD_ + seg * 8]);
    }
    cp_commit();
    prefetch_kv(0, 0);
    prefetch_kv(1, 1);
    cp_wait1();            // Q + KV0 complete (KV1 may be in flight)
    __syncthreads();

    // Q fragments (4 k16 steps), live whole kernel
    const uint32_t qa_adr = qps_u + ((r0 + (lane & 15)) * LQH + (lane >> 4) * 8) * 2;
    uint32_t qf[4][4];
#pragma unroll
    for (int ks = 0; ks < 4; ks++) ldsm4(qf[ks], qa_adr + ks * 32);

    float o[8][4];
#pragma unroll
    for (int nt = 0; nt < 8; nt++)
#pragma unroll
        for (int j = 0; j < 4; j++) o[nt][j] = 0.f;
    float l0 = 0.f, l1 = 0.f;

    const int NT = N_ / 64;
#pragma unroll 1
    for (int kt = 0; kt < NT; kt++) {
        if (kt > 0) { cp_wait1(); __syncthreads(); }
        if (kt + 2 < NT) prefetch_kv((kt + 2) % 3, kt + 2);
        else cp_commit();
        const uint32_t ks_u = kv_u + (kt % 3) * FKV_B;
        const uint32_t vs_u = ks_u + 64 * LKH * 2;
        const uint32_t kb_adr = ks_u + ((lane & 15) * LKH + (lane >> 4) * 8) * 2;
        const uint32_t vb_adr = vs_u +
            (((lane & 7) + ((lane >> 3) & 1) * 8) * LVH + ((lane >> 4) & 1) * 8) * 2;

        // ---- S = Q K^T (cc[nt] covers keys [nt*8, nt*8+8)) ----
        float cc[8][4];
#pragma unroll
        for (int nt = 0; nt < 8; nt++)
#pragma unroll
            for (int q = 0; q < 4; q++) cc[nt][q] = 0.f;
#pragma unroll
        for (int ks = 0; ks < 4; ks++) {
            const int kb = ks * 32;
#pragma unroll
            for (int g = 0; g < 4; g++) {
                uint32_t kk[4];
                ldsm4(kk, kb_adr + g * 16 * LKH * 2 + kb);
                mma_f16(cc[2 * g],     qf[ks], kk[0], kk[2]);
                mma_f16(cc[2 * g + 1], qf[ks], kk[1], kk[3]);
            }
        }

        // ---- P = exp2(S): pack directly into A-fragments (FA-2 repack) ----
        uint32_t pa[4][4];
        float rs0 = 0.f, rs1 = 0.f;
#pragma unroll
        for (int nt = 0; nt < 8; nt++) {
            float e0 = exp2f_fast(cc[nt][0]);
            float e1 = exp2f_fast(cc[nt][1]);
            float e2 = exp2f_fast(cc[nt][2]);
            float e3 = exp2f_fast(cc[nt][3]);
            rs0 += e0 + e1;
            rs1 += e2 + e3;
            const int ks = nt >> 1, hf = nt & 1;
            pa[ks][hf * 2 + 0] = pack_h2(e0, e1);   // row gid
            pa[ks][hf * 2 + 1] = pack_h2(e2, e3);   // row gid+8
        }
        rs0 += __shfl_xor_sync(0xffffffffu, rs0, 1);
        rs0 += __shfl_xor_sync(0xffffffffu, rs0, 2);
        rs1 += __shfl_xor_sync(0xffffffffu, rs1, 1);
        rs1 += __shfl_xor_sync(0xffffffffu, rs1, 2);
        l0 += rs0;
        l1 += rs1;

        // ---- O += P @ V (P from registers; V via ldmatrix.trans) ----
#pragma unroll
        for (int ks = 0; ks < 4; ks++) {
#pragma unroll
            for (int g = 0; g < 4; g++) {
                uint32_t vv[4];
                ldsm4t(vv, vb_adr + ks * 16 * LVH * 2 + g * 32);
                mma_f16(o[2 * g],     pa[ks], vv[0], vv[1]);
                mma_f16(o[2 * g + 1], pa[ks], vv[2], vv[3]);
            }
        }
    }

    // epilogue: normalize, fp16, write (b, n, h*64+hd)
    const int bb = bh / H_, hh = bh - bb * H_;
    const float i0 = 1.f / l0, i1 = 1.f / l1;
    const int row_a = qt * 128 + r0 + gid;
    const int row_b = row_a + 8;
#pragma unroll
    for (int nt = 0; nt < 8; nt++) {
        int col = hh * HD_ + nt * 8 + tg * 2;
        *(__half2*)&g_AOh[((size_t)(bb * N_ + row_a)) * D_ + col] =
            __floats2half2_rn(o[nt][0] * i0, o[nt][1] * i0);
        *(__half2*)&g_AOh[((size_t)(bb * N_ + row_b)) * D_ + col] =
            __floats2half2_rn(o[nt][2] * i1, o[nt][3] * i1);
    }
}

// ---------------------------------------------------------------------------
// q_attn: parallel two-pass; 16B K loads for 4x MLP.
// ---------------------------------------------------------------------------
__global__ void __launch_bounds__(256)
qattn_partial(float* __restrict__ out1)
{
    const int bh = blockIdx.y, kb = blockIdx.x;
    __shared__ float q0[64];
    __shared__ float red[256];
    const int tid = threadIdx.x;
    if (tid < 64) q0[tid] = __half2float(g_Qh[((size_t)bh * N_) * HD_ + tid]);
    __syncthreads();

    const int j = kb * 256 + tid;
    const uint4* kp = (const uint4*)&g_Kh[((size_t)bh * N_ + j) * HD_];
    float s = 0.f;
#pragma unroll
    for (int i = 0; i < 8; i++) {
        uint4 u = kp[i];
        const __half2* h = (const __half2*)&u;
#pragma unroll
        for (int q = 0; q < 4; q++) {
            float2 f = __half22float2(h[q]);
            s += f.x * q0[i * 8 + 2 * q] + f.y * q0[i * 8 + 2 * q + 1];
        }
    }
    float e = exp2f_fast(s);
    out1[(size_t)bh * N_ + j] = e;

    red[tid] = e; __syncthreads();
    for (int off = 128; off > 0; off >>= 1) {
        if (tid < off) red[tid] += red[tid + off];
        __syncthreads();
    }
    if (tid == 0) g_PS[bh * 8 + kb] = red[0];
}

__global__ void __launch_bounds__(256)
qattn_norm(float* __restrict__ out1)
{
    const int bh = blockIdx.x;
    __shared__ float inv_s;
    if (threadIdx.x == 0) {
        float s = 0.f;
#pragma unroll
        for (int i = 0; i < 8; i++) s += g_PS[bh * 8 + i];
        inv_s = 1.f / s;
    }
    __syncthreads();
    const float inv = inv_s;
#pragma unroll
    for (int it = 0; it < 8; it++)
        out1[(size_t)bh * N_ + threadIdx.x + it * 256] *= inv;
}

// ---------------------------------------------------------------------------
extern "C" void kernel_launch(void* const* d_in, const int* in_sizes, int n_in,
                              void* d_out, int out_size)
{
    const float* x      = (const float*)d_in[0];
    const float* w_qkv  = (const float*)d_in[1];
    const float* w_proj = (const float*)d_in[2];
    const float* b_proj = (const float*)d_in[3];
    float* out = (float*)d_out;
    float* out_qattn = out + ((size_t)out_size - (size_t)B_ * H_ * N_);

    const int gemm_smem  = 3 * GSTG_B;           // 61440
    const int flash_smem = FQP_B + 3 * FKV_B;    // 73728
    cudaFuncSetAttribute(mma_gemm<1>,
                         cudaFuncAttributeMaxDynamicSharedMemorySize, gemm_smem);
    cudaFuncSetAttribute(mma_gemm<0>,
                         cudaFuncAttributeMaxDynamicSharedMemorySize, gemm_smem);
    cudaFuncSetAttribute(flash_mma_kernel,
                         cudaFuncAttributeMaxDynamicSharedMemorySize, flash_smem);

    // 0) fp16 prepass
    round_x<<<1536, 256>>>(x);
    {
        dim3 g((3 * D_) / 32, D_ / 32, 2);
        transpose_w<<<g, 256>>>(w_qkv, w_proj);
    }
    // 1) QKV GEMM -> g_Qh(xQS_)/g_Kh/g_Vh
    {
        dim3 grid((3 * D_) / 128, (B_ * N_) / 128);
        mma_gemm<1><<<grid, 256, gemm_smem>>>(nullptr, nullptr,
                                              B_ * N_, D_, 3 * D_);
    }
    // 2) q=0 attention row
    {
        dim3 grid(8, 48);
        qattn_partial<<<grid, 256>>>(out_qattn);
        qattn_norm<<<48, 256>>>(out_qattn);
    }
    // 3) Flash attention -> g_AOh
    {
        dim3 grid(N_ / 128, B_ * H_);
        flash_mma_kernel<<<grid, 256, flash_smem>>>();
    }
    // 4) Projection GEMM + bias -> float out
    {
        dim3 grid(D_ / 128, (B_ * N_) / 128);
        mma_gemm<0><<<grid, 256, gemm_smem>>>(b_proj, out,
                                              B_ * N_, D_, D_);
    }
}

// round 13
// speedup vs baseline: 6.9299x; 1.1351x over previous
#include <cuda_runtime.h>
#include <cuda_fp16.h>
#include <math.h>
#include <stdint.h>

#define B_ 4
#define N_ 2048
#define D_ 768
#define H_ 12
#define HD_ 64
#define QS_ 0.18033688011112042f   // 0.125 * log2(e)
#define SAH 40   // GEMM A/B smem stride (halves)
#define LQH 72   // flash Q stride (halves)
#define LKH 72
#define LVH 72

// fp16 scratch (allocation-free __device__ globals)
__device__ __half g_Xh [(size_t)B_*N_*D_];
__device__ __half g_Wqh[(size_t)3*D_*D_];     // W_qkv^T [3D][D]
__device__ __half g_Wph[(size_t)D_*D_];       // W_proj^T [D][D]
__device__ __half g_Qh [(size_t)B_*H_*N_*HD_]; // pre-scaled by QS_
__device__ __half g_Kh [(size_t)B_*H_*N_*HD_];
__device__ __half g_Vh [(size_t)B_*H_*N_*HD_]; // natural [key][hd]
__device__ __half g_AOh[(size_t)B_*N_*D_];
__device__ float  g_PS [48 * 8];

// ============================ helpers ======================================
__device__ __forceinline__ uint32_t smem_u32(const void* p) {
    uint32_t a;
    asm("{ .reg .u64 t; cvta.to.shared.u64 t, %1; cvt.u32.u64 %0, t; }"
        : "=r"(a) : "l"(p));
    return a;
}
__device__ __forceinline__ void cp16(uint32_t dst, const void* src) {
    asm volatile("cp.async.cg.shared.global [%0], [%1], 16;"
                 :: "r"(dst), "l"(src));
}
__device__ __forceinline__ void cp_commit() {
    asm volatile("cp.async.commit_group;");
}
__device__ __forceinline__ void cp_wait1() {
    asm volatile("cp.async.wait_group 1;");
}
__device__ __forceinline__ void ldsm4(uint32_t r[4], uint32_t addr) {
    asm volatile("ldmatrix.sync.aligned.m8n8.x4.shared.b16 {%0,%1,%2,%3}, [%4];"
                 : "=r"(r[0]), "=r"(r[1]), "=r"(r[2]), "=r"(r[3]) : "r"(addr));
}
__device__ __forceinline__ void ldsm4t(uint32_t r[4], uint32_t addr) {
    asm volatile("ldmatrix.sync.aligned.m8n8.x4.trans.shared.b16 {%0,%1,%2,%3}, [%4];"
                 : "=r"(r[0]), "=r"(r[1]), "=r"(r[2]), "=r"(r[3]) : "r"(addr));
}
__device__ __forceinline__ void mma_f16(float c[4], const uint32_t a[4],
                                        uint32_t b0, uint32_t b1) {
    asm volatile(
        "mma.sync.aligned.m16n8k16.row.col.f32.f16.f16.f32 "
        "{%0,%1,%2,%3}, {%4,%5,%6,%7}, {%8,%9}, {%0,%1,%2,%3};"
        : "+f"(c[0]), "+f"(c[1]), "+f"(c[2]), "+f"(c[3])
        : "r"(a[0]), "r"(a[1]), "r"(a[2]), "r"(a[3]), "r"(b0), "r"(b1));
}
// MUFU exp2: logits already in log2 domain. rel err ~2^-22, runs on MUFU pipe
// (0.5 warp-instr/cyc/SM) overlapped with tensor — frees the FMA pipe.
__device__ __forceinline__ float exp2_mufu(float x) {
    float r;
    asm("ex2.approx.f32 %0, %1;" : "=f"(r) : "f"(x));
    return r;
}
__device__ __forceinline__ uint32_t pack_h2(float a, float b) {
    __half2 h = __floats2half2_rn(a, b);
    return *(uint32_t*)&h;
}

// ===========================================================================
// Pre-pass A: convert x -> fp16
// ===========================================================================
__global__ void __launch_bounds__(256)
round_x(const float* __restrict__ x)
{
    const int total = (B_ * N_ * D_) / 4;
    for (int i = blockIdx.x * blockDim.x + threadIdx.x; i < total;
         i += gridDim.x * blockDim.x) {
        float4 v = ((const float4*)x)[i];
        __half2* d = (__half2*)&g_Xh[(size_t)i * 4];
        d[0] = __floats2half2_rn(v.x, v.y);
        d[1] = __floats2half2_rn(v.z, v.w);
    }
}

// ===========================================================================
// Pre-pass B: transpose + fp16 both weights in one launch.
// ===========================================================================
__global__ void __launch_bounds__(256)
transpose_w(const float* __restrict__ wq, const float* __restrict__ wp)
{
    const int z = blockIdx.z;
    if (z == 1 && blockIdx.x >= D_ / 32) return;
    const float* src = z ? wp : wq;
    __half* dst = z ? g_Wph : g_Wqh;
    const int ND = z ? D_ : 3 * D_;
    __shared__ float t[32][33];
    const int tid = threadIdx.x;
    const int tx = tid & 31, ty = tid >> 5;
    const int bx = blockIdx.x * 32, by = blockIdx.y * 32;
#pragma unroll
    for (int i = 0; i < 4; i++) {
        int k = by + ty + i * 8;
        t[ty + i * 8][tx] = src[(size_t)k * ND + bx + tx];
    }
    __syncthreads();
#pragma unroll
    for (int i = 0; i < 4; i++) {
        int n = bx + ty + i * 8;
        dst[(size_t)n * D_ + by + tx] = __float2half_rn(t[tx][ty + i * 8]);
    }
}

// ===========================================================================
// fp16 mma.sync GEMM (m16n8k16), 3-stage cp.async, ldmatrix frags. (passing)
// ===========================================================================
#define GSTG_B (2 * 128 * SAH * 2)   // stage bytes = 20480
template<int EPI>
__global__ void __launch_bounds__(256, 2)
mma_gemm(const float* __restrict__ bias, float* __restrict__ C,
         int M, int Kd, int Nn)
{
    const __half* A  = (EPI == 0) ? (const __half*)g_AOh : (const __half*)g_Xh;
    const __half* Bw = (EPI == 0) ? (const __half*)g_Wph : (const __half*)g_Wqh;
    extern __shared__ __half smh[];
    const uint32_t s_u32 = smem_u32(smh);
    const int tid = threadIdx.x;
    const int wid = tid >> 5, lane = tid & 31;
    const int gid = lane >> 2, tg = lane & 3;
    const int warp_m = wid & 3, warp_n = wid >> 2;
    const int m0 = blockIdx.y * 128, n0 = blockIdx.x * 128;

    float c[2][8][4];
#pragma unroll
    for (int mt = 0; mt < 2; mt++)
#pragma unroll
        for (int nt = 0; nt < 8; nt++)
#pragma unroll
            for (int j = 0; j < 4; j++) c[mt][nt][j] = 0.f;

    auto prefetch = [&](int stg, int k0) {
        uint32_t as = s_u32 + stg * GSTG_B;
        uint32_t bs = as + 128 * SAH * 2;
#pragma unroll
        for (int it = 0; it < 2; it++) {
            int idx = tid + it * 256;
            int row = idx >> 2, seg = idx & 3;
            cp16(as + (row * SAH + seg * 8) * 2,
                 &A[(size_t)(m0 + row) * Kd + k0 + seg * 8]);
            cp16(bs + (row * SAH + seg * 8) * 2,
                 &Bw[(size_t)(n0 + row) * Kd + k0 + seg * 8]);
        }
        cp_commit();
    };

    const int ntiles = Kd / 32;
    prefetch(0, 0);
    prefetch(1, 32);
#pragma unroll 1
    for (int t = 0; t < ntiles; t++) {
        cp_wait1();
        __syncthreads();
        if (t + 2 < ntiles) prefetch((t + 2) % 3, (t + 2) * 32);
        else cp_commit();
        const uint32_t as_u = s_u32 + (t % 3) * GSTG_B;
        const uint32_t bs_u = as_u + 128 * SAH * 2;
        const uint32_t a_adr = as_u + ((warp_m * 32 + (lane & 15)) * SAH + (lane >> 4) * 8) * 2;
        const uint32_t b_adr = bs_u + ((warp_n * 64 + (lane & 15)) * SAH + (lane >> 4) * 8) * 2;
#pragma unroll
        for (int ks = 0; ks < 2; ks++) {
            const int kb = ks * 32;
            uint32_t a0[4], a1[4];
            ldsm4(a0, a_adr + kb);
            ldsm4(a1, a_adr + 16 * SAH * 2 + kb);
#pragma unroll
            for (int j = 0; j < 4; j++) {
                uint32_t bb[4];
                ldsm4(bb, b_adr + j * 16 * SAH * 2 + kb);
                mma_f16(c[0][2 * j],     a0, bb[0], bb[2]);
                mma_f16(c[0][2 * j + 1], a0, bb[1], bb[3]);
                mma_f16(c[1][2 * j],     a1, bb[0], bb[2]);
                mma_f16(c[1][2 * j + 1], a1, bb[1], bb[3]);
            }
        }
    }

#pragma unroll
    for (int mt = 0; mt < 2; mt++) {
#pragma unroll
        for (int nt = 0; nt < 8; nt++) {
            int r0 = m0 + warp_m * 32 + mt * 16 + gid;
            int col = n0 + warp_n * 64 + nt * 8 + tg * 2;
#pragma unroll
            for (int h = 0; h < 2; h++) {
                int r = r0 + h * 8;
                float vx = c[mt][nt][h * 2 + 0];
                float vy = c[mt][nt][h * 2 + 1];
                if (EPI == 0) {
                    float2 v; v.x = vx + bias[col]; v.y = vy + bias[col + 1];
                    *(float2*)&C[(size_t)r * Nn + col] = v;
                } else {
                    int bb = r >> 11, tok = r & 2047;
                    int which = col / D_;
                    int rem = col - which * D_;
                    int hh = rem >> 6, hd = rem & 63;
                    __half* dst = (which == 0) ? g_Qh : (which == 1) ? g_Kh : g_Vh;
                    float sc = (which == 0) ? QS_ : 1.f;
                    *(__half2*)&dst[(((size_t)(bb * H_ + hh)) * N_ + tok) * HD_ + hd] =
                        __floats2half2_rn(vx * sc, vy * sc);
                }
            }
        }
    }
}

// ===========================================================================
// Flash attention fp16: Br=128, Bc=64, 3-stage K/V, P in registers (FA-2
// repack), softmax exp on the MUFU pipe.
// ===========================================================================
#define FQP_B (128 * LQH * 2)        // 18432 bytes (Q staging)
#define FKV_B (2 * 64 * LKH * 2)     // K+V per stage = 18432 bytes
__global__ void __launch_bounds__(256, 2)
flash_mma_kernel()
{
    extern __shared__ __half smf[];
    const uint32_t qps_u = smem_u32(smf);
    const uint32_t kv_u  = qps_u + FQP_B;    // 3 stages of (K, V)

    const int tid = threadIdx.x;
    const int wid = tid >> 5, lane = tid & 31;
    const int gid = lane >> 2, tg = lane & 3;
    const int bh = blockIdx.y, qt = blockIdx.x;
    const int r0 = wid * 16;
    const __half* Qg = g_Qh + ((size_t)bh * N_ + qt * 128) * HD_;
    const __half* Kg = g_Kh + (size_t)bh * N_ * HD_;
    const __half* Vg = g_Vh + (size_t)bh * N_ * HD_;

    auto prefetch_kv = [&](int stg, int kt) {
        uint32_t ks = kv_u + stg * FKV_B;
        uint32_t vs = ks + 64 * LKH * 2;
#pragma unroll
        for (int it = 0; it < 2; it++) {
            int idx = tid + it * 256;
            int row = idx >> 3, seg = idx & 7;
            cp16(ks + (row * LKH + seg * 8) * 2,
                 &Kg[(size_t)(kt * 64 + row) * HD_ + seg * 8]);
            cp16(vs + (row * LVH + seg * 8) * 2,
                 &Vg[(size_t)(kt * 64 + row) * HD_ + seg * 8]);
        }
        cp_commit();
    };

    // stage Q
#pragma unroll
    for (int it = 0; it < 4; it++) {
        int idx = tid + it * 256;
        int row = idx >> 3, seg = idx & 7;
        cp16(qps_u + (row * LQH + seg * 8) * 2, &Qg[row * HD_ + seg * 8]);
    }
    cp_commit();
    prefetch_kv(0, 0);
    prefetch_kv(1, 1);
    cp_wait1();            // Q + KV0 complete (KV1 may be in flight)
    __syncthreads();

    // Q fragments (4 k16 steps), live whole kernel
    const uint32_t qa_adr = qps_u + ((r0 + (lane & 15)) * LQH + (lane >> 4) * 8) * 2;
    uint32_t qf[4][4];
#pragma unroll
    for (int ks = 0; ks < 4; ks++) ldsm4(qf[ks], qa_adr + ks * 32);

    float o[8][4];
#pragma unroll
    for (int nt = 0; nt < 8; nt++)
#pragma unroll
        for (int j = 0; j < 4; j++) o[nt][j] = 0.f;
    float l0 = 0.f, l1 = 0.f;

    const int NT = N_ / 64;
#pragma unroll 1
    for (int kt = 0; kt < NT; kt++) {
        if (kt > 0) { cp_wait1(); __syncthreads(); }
        if (kt + 2 < NT) prefetch_kv((kt + 2) % 3, kt + 2);
        else cp_commit();
        const uint32_t ks_u = kv_u + (kt % 3) * FKV_B;
        const uint32_t vs_u = ks_u + 64 * LKH * 2;
        const uint32_t kb_adr = ks_u + ((lane & 15) * LKH + (lane >> 4) * 8) * 2;
        const uint32_t vb_adr = vs_u +
            (((lane & 7) + ((lane >> 3) & 1) * 8) * LVH + ((lane >> 4) & 1) * 8) * 2;

        // ---- S = Q K^T ----
        float cc[8][4];
#pragma unroll
        for (int nt = 0; nt < 8; nt++)
#pragma unroll
            for (int q = 0; q < 4; q++) cc[nt][q] = 0.f;
#pragma unroll
        for (int ks = 0; ks < 4; ks++) {
            const int kb = ks * 32;
#pragma unroll
            for (int g = 0; g < 4; g++) {
                uint32_t kk[4];
                ldsm4(kk, kb_adr + g * 16 * LKH * 2 + kb);
                mma_f16(cc[2 * g],     qf[ks], kk[0], kk[2]);
                mma_f16(cc[2 * g + 1], qf[ks], kk[1], kk[3]);
            }
        }

        // ---- P = exp2(S) on MUFU; pack to A-fragments; row sums ----
        uint32_t pa[4][4];
        float rs0 = 0.f, rs1 = 0.f;
#pragma unroll
        for (int nt = 0; nt < 8; nt++) {
            float e0 = exp2_mufu(cc[nt][0]);
            float e1 = exp2_mufu(cc[nt][1]);
            float e2 = exp2_mufu(cc[nt][2]);
            float e3 = exp2_mufu(cc[nt][3]);
            rs0 += e0 + e1;
            rs1 += e2 + e3;
            const int ks = nt >> 1, hf = nt & 1;
            pa[ks][hf * 2 + 0] = pack_h2(e0, e1);   // row gid
            pa[ks][hf * 2 + 1] = pack_h2(e2, e3);   // row gid+8
        }
        rs0 += __shfl_xor_sync(0xffffffffu, rs0, 1);
        rs0 += __shfl_xor_sync(0xffffffffu, rs0, 2);
        rs1 += __shfl_xor_sync(0xffffffffu, rs1, 1);
        rs1 += __shfl_xor_sync(0xffffffffu, rs1, 2);
        l0 += rs0;
        l1 += rs1;

        // ---- O += P @ V (P from registers; V via ldmatrix.trans) ----
#pragma unroll
        for (int ks = 0; ks < 4; ks++) {
#pragma unroll
            for (int g = 0; g < 4; g++) {
                uint32_t vv[4];
                ldsm4t(vv, vb_adr + ks * 16 * LVH * 2 + g * 32);
                mma_f16(o[2 * g],     pa[ks], vv[0], vv[1]);
                mma_f16(o[2 * g + 1], pa[ks], vv[2], vv[3]);
            }
        }
    }

    // epilogue: normalize, fp16, write (b, n, h*64+hd)
    const int bb = bh / H_, hh = bh - bb * H_;
    const float i0 = 1.f / l0, i1 = 1.f / l1;
    const int row_a = qt * 128 + r0 + gid;
    const int row_b = row_a + 8;
#pragma unroll
    for (int nt = 0; nt < 8; nt++) {
        int col = hh * HD_ + nt * 8 + tg * 2;
        *(__half2*)&g_AOh[((size_t)(bb * N_ + row_a)) * D_ + col] =
            __floats2half2_rn(o[nt][0] * i0, o[nt][1] * i0);
        *(__half2*)&g_AOh[((size_t)(bb * N_ + row_b)) * D_ + col] =
            __floats2half2_rn(o[nt][2] * i1, o[nt][3] * i1);
    }
}

// ---------------------------------------------------------------------------
// q_attn: parallel two-pass; 16B K loads; MUFU exp2.
// ---------------------------------------------------------------------------
__global__ void __launch_bounds__(256)
qattn_partial(float* __restrict__ out1)
{
    const int bh = blockIdx.y, kb = blockIdx.x;
    __shared__ float q0[64];
    __shared__ float red[256];
    const int tid = threadIdx.x;
    if (tid < 64) q0[tid] = __half2float(g_Qh[((size_t)bh * N_) * HD_ + tid]);
    __syncthreads();

    const int j = kb * 256 + tid;
    const uint4* kp = (const uint4*)&g_Kh[((size_t)bh * N_ + j) * HD_];
    float s = 0.f;
#pragma unroll
    for (int i = 0; i < 8; i++) {
        uint4 u = kp[i];
        const __half2* h = (const __half2*)&u;
#pragma unroll
        for (int q = 0; q < 4; q++) {
            float2 f = __half22float2(h[q]);
            s += f.x * q0[i * 8 + 2 * q] + f.y * q0[i * 8 + 2 * q + 1];
        }
    }
    float e = exp2_mufu(s);
    out1[(size_t)bh * N_ + j] = e;

    red[tid] = e; __syncthreads();
    for (int off = 128; off > 0; off >>= 1) {
        if (tid < off) red[tid] += red[tid + off];
        __syncthreads();
    }
    if (tid == 0) g_PS[bh * 8 + kb] = red[0];
}

__global__ void __launch_bounds__(256)
qattn_norm(float* __restrict__ out1)
{
    const int bh = blockIdx.x;
    __shared__ float inv_s;
    if (threadIdx.x == 0) {
        float s = 0.f;
#pragma unroll
        for (int i = 0; i < 8; i++) s += g_PS[bh * 8 + i];
        inv_s = 1.f / s;
    }
    __syncthreads();
    const float inv = inv_s;
#pragma unroll
    for (int it = 0; it < 8; it++)
        out1[(size_t)bh * N_ + threadIdx.x + it * 256] *= inv;
}

// ---------------------------------------------------------------------------
extern "C" void kernel_launch(void* const* d_in, const int* in_sizes, int n_in,
                              void* d_out, int out_size)
{
    const float* x      = (const float*)d_in[0];
    const float* w_qkv  = (const float*)d_in[1];
    const float* w_proj = (const float*)d_in[2];
    const float* b_proj = (const float*)d_in[3];
    float* out = (float*)d_out;
    float* out_qattn = out + ((size_t)out_size - (size_t)B_ * H_ * N_);

    const int gemm_smem  = 3 * GSTG_B;           // 61440
    const int flash_smem = FQP_B + 3 * FKV_B;    // 73728
    cudaFuncSetAttribute(mma_gemm<1>,
                         cudaFuncAttributeMaxDynamicSharedMemorySize, gemm_smem);
    cudaFuncSetAttribute(mma_gemm<0>,
                         cudaFuncAttributeMaxDynamicSharedMemorySize, gemm_smem);
    cudaFuncSetAttribute(flash_mma_kernel,
                         cudaFuncAttributeMaxDynamicSharedMemorySize, flash_smem);

    // 0) fp16 prepass
    round_x<<<1536, 256>>>(x);
    {
        dim3 g((3 * D_) / 32, D_ / 32, 2);
        transpose_w<<<g, 256>>>(w_qkv, w_proj);
    }
    // 1) QKV GEMM -> g_Qh(xQS_)/g_Kh/g_Vh
    {
        dim3 grid((3 * D_) / 128, (B_ * N_) / 128);
        mma_gemm<1><<<grid, 256, gemm_smem>>>(nullptr, nullptr,
                                              B_ * N_, D_, 3 * D_);
    }
    // 2) q=0 attention row
    {
        dim3 grid(8, 48);
        qattn_partial<<<grid, 256>>>(out_qattn);
        qattn_norm<<<48, 256>>>(out_qattn);
    }
    // 3) Flash attention -> g_AOh
    {
        dim3 grid(N_ / 128, B_ * H_);
        flash_mma_kernel<<<grid, 256, flash_smem>>>();
    }
    // 4) Projection GEMM + bias -> float out
    {
        dim3 grid(D_ / 128, (B_ * N_) / 128);
        mma_gemm<0><<<grid, 256, gemm_smem>>>(b_proj, out,
                                              B_ * N_, D_, D_);
    }
}

// round 14
// speedup vs baseline: 7.0386x; 1.0157x over previous
#include <cuda_runtime.h>
#include <cuda_fp16.h>
#include <math.h>
#include <stdint.h>

#define B_ 4
#define N_ 2048
#define D_ 768
#define H_ 12
#define HD_ 64
#define QS_ 0.18033688011112042f   // 0.125 * log2(e)
#define SAH 40   // GEMM A/B smem stride (halves)
#define LQH 72   // flash Q stride (halves)
#define LKH 72
#define LVH 72

// fp16 scratch (allocation-free __device__ globals)
__device__ __half g_Xh [(size_t)B_*N_*D_];
__device__ __half g_Wqh[(size_t)3*D_*D_];     // W_qkv^T [3D][D]
__device__ __half g_Wph[(size_t)D_*D_];       // W_proj^T [D][D]
__device__ __half g_Qh [(size_t)B_*H_*N_*HD_]; // pre-scaled by QS_
__device__ __half g_Kh [(size_t)B_*H_*N_*HD_];
__device__ __half g_Vh [(size_t)B_*H_*N_*HD_]; // natural [key][hd]
__device__ __half g_AOh[(size_t)B_*N_*D_];

// ============================ helpers ======================================
__device__ __forceinline__ uint32_t smem_u32(const void* p) {
    uint32_t a;
    asm("{ .reg .u64 t; cvta.to.shared.u64 t, %1; cvt.u32.u64 %0, t; }"
        : "=r"(a) : "l"(p));
    return a;
}
__device__ __forceinline__ void cp16(uint32_t dst, const void* src) {
    asm volatile("cp.async.cg.shared.global [%0], [%1], 16;"
                 :: "r"(dst), "l"(src));
}
__device__ __forceinline__ void cp_commit() {
    asm volatile("cp.async.commit_group;");
}
__device__ __forceinline__ void cp_wait2() {
    asm volatile("cp.async.wait_group 2;");
}
__device__ __forceinline__ void ldsm4(uint32_t r[4], uint32_t addr) {
    asm volatile("ldmatrix.sync.aligned.m8n8.x4.shared.b16 {%0,%1,%2,%3}, [%4];"
                 : "=r"(r[0]), "=r"(r[1]), "=r"(r[2]), "=r"(r[3]) : "r"(addr));
}
__device__ __forceinline__ void ldsm4t(uint32_t r[4], uint32_t addr) {
    asm volatile("ldmatrix.sync.aligned.m8n8.x4.trans.shared.b16 {%0,%1,%2,%3}, [%4];"
                 : "=r"(r[0]), "=r"(r[1]), "=r"(r[2]), "=r"(r[3]) : "r"(addr));
}
__device__ __forceinline__ void mma_f16(float c[4], const uint32_t a[4],
                                        uint32_t b0, uint32_t b1) {
    asm volatile(
        "mma.sync.aligned.m16n8k16.row.col.f32.f16.f16.f32 "
        "{%0,%1,%2,%3}, {%4,%5,%6,%7}, {%8,%9}, {%0,%1,%2,%3};"
        : "+f"(c[0]), "+f"(c[1]), "+f"(c[2]), "+f"(c[3])
        : "r"(a[0]), "r"(a[1]), "r"(a[2]), "r"(a[3]), "r"(b0), "r"(b1));
}
__device__ __forceinline__ float exp2_mufu(float x) {
    float r;
    asm("ex2.approx.f32 %0, %1;" : "=f"(r) : "f"(x));
    return r;
}
__device__ __forceinline__ uint32_t pack_h2(float a, float b) {
    __half2 h = __floats2half2_rn(a, b);
    return *(uint32_t*)&h;
}

// ===========================================================================
// Fused pre-pass (one launch, grid (72, 24, 3)):
//   z==0: transpose+fp16 w_qkv -> g_Wqh   (72 x 24 tiles of 32x32)
//   z==1: transpose+fp16 w_proj -> g_Wph  (24 x 24 tiles; guard x)
//   z==2: x -> fp16 straight copy (flattened grid-stride)
// ===========================================================================
__global__ void __launch_bounds__(256)
prepass(const float* __restrict__ x, const float* __restrict__ wq,
        const float* __restrict__ wp)
{
    const int z = blockIdx.z;
    const int tid = threadIdx.x;
    if (z == 2) {
        const int total = (B_ * N_ * D_) / 4;
        const int stride = 72 * 24 * 256;
        for (int i = (blockIdx.x + blockIdx.y * 72) * 256 + tid; i < total;
             i += stride) {
            float4 v = ((const float4*)x)[i];
            __half2* d = (__half2*)&g_Xh[(size_t)i * 4];
            d[0] = __floats2half2_rn(v.x, v.y);
            d[1] = __floats2half2_rn(v.z, v.w);
        }
        return;
    }
    if (z == 1 && blockIdx.x >= D_ / 32) return;
    const float* src = z ? wp : wq;
    __half* dst = z ? g_Wph : g_Wqh;
    const int ND = z ? D_ : 3 * D_;
    __shared__ float t[32][33];
    const int tx = tid & 31, ty = tid >> 5;
    const int bx = blockIdx.x * 32, by = blockIdx.y * 32;
#pragma unroll
    for (int i = 0; i < 4; i++) {
        int k = by + ty + i * 8;
        t[ty + i * 8][tx] = src[(size_t)k * ND + bx + tx];
    }
    __syncthreads();
#pragma unroll
    for (int i = 0; i < 4; i++) {
        int n = bx + ty + i * 8;
        dst[(size_t)n * D_ + by + tx] = __float2half_rn(t[tx][ty + i * 8]);
    }
}

// ===========================================================================
// fp16 mma.sync GEMM (m16n8k16), 4-stage cp.async (wait_group 2), ldsm frags.
// ===========================================================================
#define GSTG_B (2 * 128 * SAH * 2)   // stage bytes = 20480
template<int EPI>
__global__ void __launch_bounds__(256, 2)
mma_gemm(const float* __restrict__ bias, float* __restrict__ C,
         int M, int Kd, int Nn)
{
    const __half* A  = (EPI == 0) ? (const __half*)g_AOh : (const __half*)g_Xh;
    const __half* Bw = (EPI == 0) ? (const __half*)g_Wph : (const __half*)g_Wqh;
    extern __shared__ __half smh[];
    const uint32_t s_u32 = smem_u32(smh);
    const int tid = threadIdx.x;
    const int wid = tid >> 5, lane = tid & 31;
    const int gid = lane >> 2, tg = lane & 3;
    const int warp_m = wid & 3, warp_n = wid >> 2;
    const int m0 = blockIdx.y * 128, n0 = blockIdx.x * 128;

    float c[2][8][4];
#pragma unroll
    for (int mt = 0; mt < 2; mt++)
#pragma unroll
        for (int nt = 0; nt < 8; nt++)
#pragma unroll
            for (int j = 0; j < 4; j++) c[mt][nt][j] = 0.f;

    auto prefetch = [&](int stg, int k0) {
        uint32_t as = s_u32 + stg * GSTG_B;
        uint32_t bs = as + 128 * SAH * 2;
#pragma unroll
        for (int it = 0; it < 2; it++) {
            int idx = tid + it * 256;
            int row = idx >> 2, seg = idx & 3;
            cp16(as + (row * SAH + seg * 8) * 2,
                 &A[(size_t)(m0 + row) * Kd + k0 + seg * 8]);
            cp16(bs + (row * SAH + seg * 8) * 2,
                 &Bw[(size_t)(n0 + row) * Kd + k0 + seg * 8]);
        }
        cp_commit();
    };

    const int ntiles = Kd / 32;          // 24
    prefetch(0, 0);
    prefetch(1, 32);
    prefetch(2, 64);
#pragma unroll 1
    for (int t = 0; t < ntiles; t++) {
        cp_wait2();                      // tile t's group complete
        __syncthreads();                 // all warps done with buffer (t+3)&3
        if (t + 3 < ntiles) prefetch((t + 3) & 3, (t + 3) * 32);
        else cp_commit();
        const uint32_t as_u = s_u32 + (t & 3) * GSTG_B;
        const uint32_t bs_u = as_u + 128 * SAH * 2;
        const uint32_t a_adr = as_u + ((warp_m * 32 + (lane & 15)) * SAH + (lane >> 4) * 8) * 2;
        const uint32_t b_adr = bs_u + ((warp_n * 64 + (lane & 15)) * SAH + (lane >> 4) * 8) * 2;
#pragma unroll
        for (int ks = 0; ks < 2; ks++) {
            const int kb = ks * 32;
            uint32_t a0[4], a1[4];
            ldsm4(a0, a_adr + kb);
            ldsm4(a1, a_adr + 16 * SAH * 2 + kb);
#pragma unroll
            for (int j = 0; j < 4; j++) {
                uint32_t bb[4];
                ldsm4(bb, b_adr + j * 16 * SAH * 2 + kb);
                mma_f16(c[0][2 * j],     a0, bb[0], bb[2]);
                mma_f16(c[0][2 * j + 1], a0, bb[1], bb[3]);
                mma_f16(c[1][2 * j],     a1, bb[0], bb[2]);
                mma_f16(c[1][2 * j + 1], a1, bb[1], bb[3]);
            }
        }
    }

#pragma unroll
    for (int mt = 0; mt < 2; mt++) {
#pragma unroll
        for (int nt = 0; nt < 8; nt++) {
            int r0 = m0 + warp_m * 32 + mt * 16 + gid;
            int col = n0 + warp_n * 64 + nt * 8 + tg * 2;
#pragma unroll
            for (int h = 0; h < 2; h++) {
                int r = r0 + h * 8;
                float vx = c[mt][nt][h * 2 + 0];
                float vy = c[mt][nt][h * 2 + 1];
                if (EPI == 0) {
                    float2 v; v.x = vx + bias[col]; v.y = vy + bias[col + 1];
                    *(float2*)&C[(size_t)r * Nn + col] = v;
                } else {
                    int bb = r >> 11, tok = r & 2047;
                    int which = col / D_;
                    int rem = col - which * D_;
                    int hh = rem >> 6, hd = rem & 63;
                    __half* dst = (which == 0) ? g_Qh : (which == 1) ? g_Kh : g_Vh;
                    float sc = (which == 0) ? QS_ : 1.f;
                    *(__half2*)&dst[(((size_t)(bb * H_ + hh)) * N_ + tok) * HD_ + hd] =
                        __floats2half2_rn(vx * sc, vy * sc);
                }
            }
        }
    }
}

// ===========================================================================
// Flash attention fp16: Br=128, Bc=64, 4-stage K/V (wait_group 2),
// P in registers (FA-2 repack), softmax exp on MUFU.
// ===========================================================================
#define FQP_B (128 * LQH * 2)        // 18432 bytes (Q staging)
#define FKV_B (2 * 64 * LKH * 2)     // K+V per stage = 18432 bytes
__global__ void __launch_bounds__(256, 2)
flash_mma_kernel()
{
    extern __shared__ __half smf[];
    const uint32_t qps_u = smem_u32(smf);
    const uint32_t kv_u  = qps_u + FQP_B;    // 4 stages of (K, V)

    const int tid = threadIdx.x;
    const int wid = tid >> 5, lane = tid & 31;
    const int gid = lane >> 2, tg = lane & 3;
    const int bh = blockIdx.y, qt = blockIdx.x;
    const int r0 = wid * 16;
    const __half* Qg = g_Qh + ((size_t)bh * N_ + qt * 128) * HD_;
    const __half* Kg = g_Kh + (size_t)bh * N_ * HD_;
    const __half* Vg = g_Vh + (size_t)bh * N_ * HD_;

    auto prefetch_kv = [&](int stg, int kt) {
        uint32_t ks = kv_u + stg * FKV_B;
        uint32_t vs = ks + 64 * LKH * 2;
#pragma unroll
        for (int it = 0; it < 2; it++) {
            int idx = tid + it * 256;
            int row = idx >> 3, seg = idx & 7;
            cp16(ks + (row * LKH + seg * 8) * 2,
                 &Kg[(size_t)(kt * 64 + row) * HD_ + seg * 8]);
            cp16(vs + (row * LVH + seg * 8) * 2,
                 &Vg[(size_t)(kt * 64 + row) * HD_ + seg * 8]);
        }
        cp_commit();
    };

    // stage Q + first 3 KV tiles
#pragma unroll
    for (int it = 0; it < 4; it++) {
        int idx = tid + it * 256;
        int row = idx >> 3, seg = idx & 7;
        cp16(qps_u + (row * LQH + seg * 8) * 2, &Qg[row * HD_ + seg * 8]);
    }
    cp_commit();
    prefetch_kv(0, 0);
    prefetch_kv(1, 1);
    prefetch_kv(2, 2);
    cp_wait2();            // Q + KV0 complete (KV1/KV2 in flight)
    __syncthreads();

    // Q fragments (4 k16 steps), live whole kernel
    const uint32_t qa_adr = qps_u + ((r0 + (lane & 15)) * LQH + (lane >> 4) * 8) * 2;
    uint32_t qf[4][4];
#pragma unroll
    for (int ks = 0; ks < 4; ks++) ldsm4(qf[ks], qa_adr + ks * 32);

    float o[8][4];
#pragma unroll
    for (int nt = 0; nt < 8; nt++)
#pragma unroll
        for (int j = 0; j < 4; j++) o[nt][j] = 0.f;
    float l0 = 0.f, l1 = 0.f;

    const int NT = N_ / 64;              // 32
#pragma unroll 1
    for (int kt = 0; kt < NT; kt++) {
        if (kt > 0) { cp_wait2(); __syncthreads(); }
        if (kt + 3 < NT) prefetch_kv((kt + 3) & 3, kt + 3);
        else cp_commit();
        const uint32_t ks_u = kv_u + (kt & 3) * FKV_B;
        const uint32_t vs_u = ks_u + 64 * LKH * 2;
        const uint32_t kb_adr = ks_u + ((lane & 15) * LKH + (lane >> 4) * 8) * 2;
        const uint32_t vb_adr = vs_u +
            (((lane & 7) + ((lane >> 3) & 1) * 8) * LVH + ((lane >> 4) & 1) * 8) * 2;

        // ---- S = Q K^T ----
        float cc[8][4];
#pragma unroll
        for (int nt = 0; nt < 8; nt++)
#pragma unroll
            for (int q = 0; q < 4; q++) cc[nt][q] = 0.f;
#pragma unroll
        for (int ks = 0; ks < 4; ks++) {
            const int kb = ks * 32;
#pragma unroll
            for (int g = 0; g < 4; g++) {
                uint32_t kk[4];
                ldsm4(kk, kb_adr + g * 16 * LKH * 2 + kb);
                mma_f16(cc[2 * g],     qf[ks], kk[0], kk[2]);
                mma_f16(cc[2 * g + 1], qf[ks], kk[1], kk[3]);
            }
        }

        // ---- P = exp2(S) on MUFU; pack to A-fragments; row sums ----
        uint32_t pa[4][4];
        float rs0 = 0.f, rs1 = 0.f;
#pragma unroll
        for (int nt = 0; nt < 8; nt++) {
            float e0 = exp2_mufu(cc[nt][0]);
            float e1 = exp2_mufu(cc[nt][1]);
            float e2 = exp2_mufu(cc[nt][2]);
            float e3 = exp2_mufu(cc[nt][3]);
            rs0 += e0 + e1;
            rs1 += e2 + e3;
            const int ks = nt >> 1, hf = nt & 1;
            pa[ks][hf * 2 + 0] = pack_h2(e0, e1);   // row gid
            pa[ks][hf * 2 + 1] = pack_h2(e2, e3);   // row gid+8
        }
        rs0 += __shfl_xor_sync(0xffffffffu, rs0, 1);
        rs0 += __shfl_xor_sync(0xffffffffu, rs0, 2);
        rs1 += __shfl_xor_sync(0xffffffffu, rs1, 1);
        rs1 += __shfl_xor_sync(0xffffffffu, rs1, 2);
        l0 += rs0;
        l1 += rs1;

        // ---- O += P @ V (P from registers; V via ldmatrix.trans) ----
#pragma unroll
        for (int ks = 0; ks < 4; ks++) {
#pragma unroll
            for (int g = 0; g < 4; g++) {
                uint32_t vv[4];
                ldsm4t(vv, vb_adr + ks * 16 * LVH * 2 + g * 32);
                mma_f16(o[2 * g],     pa[ks], vv[0], vv[1]);
                mma_f16(o[2 * g + 1], pa[ks], vv[2], vv[3]);
            }
        }
    }

    // epilogue: normalize, fp16, write (b, n, h*64+hd)
    const int bb = bh / H_, hh = bh - bb * H_;
    const float i0 = 1.f / l0, i1 = 1.f / l1;
    const int row_a = qt * 128 + r0 + gid;
    const int row_b = row_a + 8;
#pragma unroll
    for (int nt = 0; nt < 8; nt++) {
        int col = hh * HD_ + nt * 8 + tg * 2;
        *(__half2*)&g_AOh[((size_t)(bb * N_ + row_a)) * D_ + col] =
            __floats2half2_rn(o[nt][0] * i0, o[nt][1] * i0);
        *(__half2*)&g_AOh[((size_t)(bb * N_ + row_b)) * D_ + col] =
            __floats2half2_rn(o[nt][2] * i1, o[nt][3] * i1);
    }
}

// ---------------------------------------------------------------------------
// q_attn: single kernel, one block per (b,h), 1024 threads x 2 keys.
// ---------------------------------------------------------------------------
__global__ void __launch_bounds__(1024)
qattn_kernel(float* __restrict__ out1)
{
    const int bh = blockIdx.x;
    __shared__ float q0[64];
    __shared__ float red[1024];
    const int tid = threadIdx.x;
    if (tid < 64) q0[tid] = __half2float(g_Qh[((size_t)bh * N_) * HD_ + tid]);
    __syncthreads();

    float e[2];
    float sum = 0.f;
#pragma unroll
    for (int r = 0; r < 2; r++) {
        const int j = tid + r * 1024;
        const uint4* kp = (const uint4*)&g_Kh[((size_t)bh * N_ + j) * HD_];
        float s = 0.f;
#pragma unroll
        for (int i = 0; i < 8; i++) {
            uint4 u = kp[i];
            const __half2* h = (const __half2*)&u;
#pragma unroll
            for (int q = 0; q < 4; q++) {
                float2 f = __half22float2(h[q]);
                s += f.x * q0[i * 8 + 2 * q] + f.y * q0[i * 8 + 2 * q + 1];
            }
        }
        e[r] = exp2_mufu(s);
        sum += e[r];
    }
    red[tid] = sum; __syncthreads();
    for (int off = 512; off > 0; off >>= 1) {
        if (tid < off) red[tid] += red[tid + off];
        __syncthreads();
    }
    const float inv = 1.f / red[0];
    out1[(size_t)bh * N_ + tid]        = e[0] * inv;
    out1[(size_t)bh * N_ + tid + 1024] = e[1] * inv;
}

// ---------------------------------------------------------------------------
extern "C" void kernel_launch(void* const* d_in, const int* in_sizes, int n_in,
                              void* d_out, int out_size)
{
    const float* x      = (const float*)d_in[0];
    const float* w_qkv  = (const float*)d_in[1];
    const float* w_proj = (const float*)d_in[2];
    const float* b_proj = (const float*)d_in[3];
    float* out = (float*)d_out;
    float* out_qattn = out + ((size_t)out_size - (size_t)B_ * H_ * N_);

    const int gemm_smem  = 4 * GSTG_B;           // 81920
    const int flash_smem = FQP_B + 4 * FKV_B;    // 92160
    cudaFuncSetAttribute(mma_gemm<1>,
                         cudaFuncAttributeMaxDynamicSharedMemorySize, gemm_smem);
    cudaFuncSetAttribute(mma_gemm<0>,
                         cudaFuncAttributeMaxDynamicSharedMemorySize, gemm_smem);
    cudaFuncSetAttribute(flash_mma_kernel,
                         cudaFuncAttributeMaxDynamicSharedMemorySize, flash_smem);

    // 0) fused fp16 prepass (x convert + both weight transposes)
    {
        dim3 g(72, 24, 3);
        prepass<<<g, 256>>>(x, w_qkv, w_proj);
    }
    // 1) QKV GEMM -> g_Qh(xQS_)/g_Kh/g_Vh
    {
        dim3 grid((3 * D_) / 128, (B_ * N_) / 128);
        mma_gemm<1><<<grid, 256, gemm_smem>>>(nullptr, nullptr,
                                              B_ * N_, D_, 3 * D_);
    }
    // 2) q=0 attention row (single kernel)
    qattn_kernel<<<48, 1024>>>(out_qattn);
    // 3) Flash attention -> g_AOh
    {
        dim3 grid(N_ / 128, B_ * H_);
        flash_mma_kernel<<<grid, 256, flash_smem>>>();
    }
    // 4) Projection GEMM + bias -> float out
    {
        dim3 grid(D_ / 128, (B_ * N_) / 128);
        mma_gemm<0><<<grid, 256, gemm_smem>>>(b_proj, out,
                                              B_ * N_, D_, D_);
    }
}

// round 15
// speedup vs baseline: 7.1753x; 1.0194x over previous
#include <cuda_runtime.h>
#include <cuda_fp16.h>
#include <math.h>
#include <stdint.h>

#define B_ 4
#define N_ 2048
#define D_ 768
#define H_ 12
#define HD_ 64
#define QS_ 0.18033688011112042f   // 0.125 * log2(e)
#define SAH 40   // GEMM A/B smem stride (halves)
#define LQH 72   // flash Q stride (halves)
#define LKH 72
#define LVH 72

// fp16 scratch (allocation-free __device__ globals)
__device__ __half g_Xh [(size_t)B_*N_*D_];
__device__ __half g_Wqh[(size_t)3*D_*D_];     // W_qkv^T [3D][D]
__device__ __half g_Wph[(size_t)D_*D_];       // W_proj^T [D][D]
__device__ __half g_Qh [(size_t)B_*H_*N_*HD_]; // pre-scaled by QS_
__device__ __half g_Kh [(size_t)B_*H_*N_*HD_];
__device__ __half g_Vh [(size_t)B_*H_*N_*HD_]; // natural [key][hd]
__device__ __half g_AOh[(size_t)B_*N_*D_];

// ============================ helpers ======================================
__device__ __forceinline__ uint32_t smem_u32(const void* p) {
    uint32_t a;
    asm("{ .reg .u64 t; cvta.to.shared.u64 t, %1; cvt.u32.u64 %0, t; }"
        : "=r"(a) : "l"(p));
    return a;
}
__device__ __forceinline__ void cp16(uint32_t dst, const void* src) {
    asm volatile("cp.async.cg.shared.global [%0], [%1], 16;"
                 :: "r"(dst), "l"(src));
}
__device__ __forceinline__ void cp_commit() {
    asm volatile("cp.async.commit_group;");
}
__device__ __forceinline__ void cp_wait2() {
    asm volatile("cp.async.wait_group 2;");
}
__device__ __forceinline__ void ldsm4(uint32_t r[4], uint32_t addr) {
    asm volatile("ldmatrix.sync.aligned.m8n8.x4.shared.b16 {%0,%1,%2,%3}, [%4];"
                 : "=r"(r[0]), "=r"(r[1]), "=r"(r[2]), "=r"(r[3]) : "r"(addr));
}
__device__ __forceinline__ void ldsm4t(uint32_t r[4], uint32_t addr) {
    asm volatile("ldmatrix.sync.aligned.m8n8.x4.trans.shared.b16 {%0,%1,%2,%3}, [%4];"
                 : "=r"(r[0]), "=r"(r[1]), "=r"(r[2]), "=r"(r[3]) : "r"(addr));
}
__device__ __forceinline__ void mma_f16(float c[4], const uint32_t a[4],
                                        uint32_t b0, uint32_t b1) {
    asm volatile(
        "mma.sync.aligned.m16n8k16.row.col.f32.f16.f16.f32 "
        "{%0,%1,%2,%3}, {%4,%5,%6,%7}, {%8,%9}, {%0,%1,%2,%3};"
        : "+f"(c[0]), "+f"(c[1]), "+f"(c[2]), "+f"(c[3])
        : "r"(a[0]), "r"(a[1]), "r"(a[2]), "r"(a[3]), "r"(b0), "r"(b1));
}
__device__ __forceinline__ float exp2_mufu(float x) {
    float r;
    asm("ex2.approx.f32 %0, %1;" : "=f"(r) : "f"(x));
    return r;
}
__device__ __forceinline__ uint32_t pack_h2(float a, float b) {
    __half2 h = __floats2half2_rn(a, b);
    return *(uint32_t*)&h;
}

// ===========================================================================
// Fused pre-pass (grid (72, 24, 3)): z0/z1 weight transposes, z2 x convert.
// ===========================================================================
__global__ void __launch_bounds__(256)
prepass(const float* __restrict__ x, const float* __restrict__ wq,
        const float* __restrict__ wp)
{
    const int z = blockIdx.z;
    const int tid = threadIdx.x;
    if (z == 2) {
        const int total = (B_ * N_ * D_) / 4;
        const int stride = 72 * 24 * 256;
        for (int i = (blockIdx.x + blockIdx.y * 72) * 256 + tid; i < total;
             i += stride) {
            float4 v = ((const float4*)x)[i];
            __half2* d = (__half2*)&g_Xh[(size_t)i * 4];
            d[0] = __floats2half2_rn(v.x, v.y);
            d[1] = __floats2half2_rn(v.z, v.w);
        }
        return;
    }
    if (z == 1 && blockIdx.x >= D_ / 32) return;
    const float* src = z ? wp : wq;
    __half* dst = z ? g_Wph : g_Wqh;
    const int ND = z ? D_ : 3 * D_;
    __shared__ float t[32][33];
    const int tx = tid & 31, ty = tid >> 5;
    const int bx = blockIdx.x * 32, by = blockIdx.y * 32;
#pragma unroll
    for (int i = 0; i < 4; i++) {
        int k = by + ty + i * 8;
        t[ty + i * 8][tx] = src[(size_t)k * ND + bx + tx];
    }
    __syncthreads();
#pragma unroll
    for (int i = 0; i < 4; i++) {
        int n = bx + ty + i * 8;
        dst[(size_t)n * D_ + by + tx] = __float2half_rn(t[tx][ty + i * 8]);
    }
}

// ===========================================================================
// fp16 mma.sync GEMM (m16n8k16), 4-stage cp.async, ldsm frags. (passing)
// ===========================================================================
#define GSTG_B (2 * 128 * SAH * 2)   // stage bytes = 20480
template<int EPI>
__global__ void __launch_bounds__(256, 2)
mma_gemm(const float* __restrict__ bias, float* __restrict__ C,
         int M, int Kd, int Nn)
{
    const __half* A  = (EPI == 0) ? (const __half*)g_AOh : (const __half*)g_Xh;
    const __half* Bw = (EPI == 0) ? (const __half*)g_Wph : (const __half*)g_Wqh;
    extern __shared__ __half smh[];
    const uint32_t s_u32 = smem_u32(smh);
    const int tid = threadIdx.x;
    const int wid = tid >> 5, lane = tid & 31;
    const int gid = lane >> 2, tg = lane & 3;
    const int warp_m = wid & 3, warp_n = wid >> 2;
    const int m0 = blockIdx.y * 128, n0 = blockIdx.x * 128;

    float c[2][8][4];
#pragma unroll
    for (int mt = 0; mt < 2; mt++)
#pragma unroll
        for (int nt = 0; nt < 8; nt++)
#pragma unroll
            for (int j = 0; j < 4; j++) c[mt][nt][j] = 0.f;

    auto prefetch = [&](int stg, int k0) {
        uint32_t as = s_u32 + stg * GSTG_B;
        uint32_t bs = as + 128 * SAH * 2;
#pragma unroll
        for (int it = 0; it < 2; it++) {
            int idx = tid + it * 256;
            int row = idx >> 2, seg = idx & 3;
            cp16(as + (row * SAH + seg * 8) * 2,
                 &A[(size_t)(m0 + row) * Kd + k0 + seg * 8]);
            cp16(bs + (row * SAH + seg * 8) * 2,
                 &Bw[(size_t)(n0 + row) * Kd + k0 + seg * 8]);
        }
        cp_commit();
    };

    const int ntiles = Kd / 32;          // 24
    prefetch(0, 0);
    prefetch(1, 32);
    prefetch(2, 64);
#pragma unroll 1
    for (int t = 0; t < ntiles; t++) {
        cp_wait2();
        __syncthreads();
        if (t + 3 < ntiles) prefetch((t + 3) & 3, (t + 3) * 32);
        else cp_commit();
        const uint32_t as_u = s_u32 + (t & 3) * GSTG_B;
        const uint32_t bs_u = as_u + 128 * SAH * 2;
        const uint32_t a_adr = as_u + ((warp_m * 32 + (lane & 15)) * SAH + (lane >> 4) * 8) * 2;
        const uint32_t b_adr = bs_u + ((warp_n * 64 + (lane & 15)) * SAH + (lane >> 4) * 8) * 2;
#pragma unroll
        for (int ks = 0; ks < 2; ks++) {
            const int kb = ks * 32;
            uint32_t a0[4], a1[4];
            ldsm4(a0, a_adr + kb);
            ldsm4(a1, a_adr + 16 * SAH * 2 + kb);
#pragma unroll
            for (int j = 0; j < 4; j++) {
                uint32_t bb[4];
                ldsm4(bb, b_adr + j * 16 * SAH * 2 + kb);
                mma_f16(c[0][2 * j],     a0, bb[0], bb[2]);
                mma_f16(c[0][2 * j + 1], a0, bb[1], bb[3]);
                mma_f16(c[1][2 * j],     a1, bb[0], bb[2]);
                mma_f16(c[1][2 * j + 1], a1, bb[1], bb[3]);
            }
        }
    }

#pragma unroll
    for (int mt = 0; mt < 2; mt++) {
#pragma unroll
        for (int nt = 0; nt < 8; nt++) {
            int r0 = m0 + warp_m * 32 + mt * 16 + gid;
            int col = n0 + warp_n * 64 + nt * 8 + tg * 2;
#pragma unroll
            for (int h = 0; h < 2; h++) {
                int r = r0 + h * 8;
                float vx = c[mt][nt][h * 2 + 0];
                float vy = c[mt][nt][h * 2 + 1];
                if (EPI == 0) {
                    float2 v; v.x = vx + bias[col]; v.y = vy + bias[col + 1];
                    *(float2*)&C[(size_t)r * Nn + col] = v;
                } else {
                    int bb = r >> 11, tok = r & 2047;
                    int which = col / D_;
                    int rem = col - which * D_;
                    int hh = rem >> 6, hd = rem & 63;
                    __half* dst = (which == 0) ? g_Qh : (which == 1) ? g_Kh : g_Vh;
                    float sc = (which == 0) ? QS_ : 1.f;
                    *(__half2*)&dst[(((size_t)(bb * H_ + hh)) * N_ + tok) * HD_ + hd] =
                        __floats2half2_rn(vx * sc, vy * sc);
                }
            }
        }
    }
}

// ===========================================================================
// Flash attention fp16: Br=128, Bc=64, 4-stage K/V, P in registers,
// row sums via tensor-core ones-trick (no shuffles/FADDs), static stage addrs.
// ===========================================================================
#define FQP_B (128 * LQH * 2)        // 18432 bytes (Q staging)
#define FKV_B (2 * 64 * LKH * 2)     // K+V per stage = 18432 bytes
#define ONES_H2 0x3C003C00u          // half2(1.0, 1.0)
__global__ void __launch_bounds__(256, 2)
flash_mma_kernel()
{
    extern __shared__ __half smf[];
    const uint32_t qps_u = smem_u32(smf);
    const uint32_t kv_u  = qps_u + FQP_B;    // 4 stages of (K, V)

    const int tid = threadIdx.x;
    const int wid = tid >> 5, lane = tid & 31;
    const int gid = lane >> 2, tg = lane & 3;
    const int bh = blockIdx.y, qt = blockIdx.x;
    const int r0 = wid * 16;
    const __half* Qg = g_Qh + ((size_t)bh * N_ + qt * 128) * HD_;
    const __half* Kg = g_Kh + (size_t)bh * N_ * HD_;
    const __half* Vg = g_Vh + (size_t)bh * N_ * HD_;

    auto prefetch_kv = [&](int stg, int kt) {
        uint32_t ks = kv_u + stg * FKV_B;
        uint32_t vs = ks + 64 * LKH * 2;
#pragma unroll
        for (int it = 0; it < 2; it++) {
            int idx = tid + it * 256;
            int row = idx >> 3, seg = idx & 7;
            cp16(ks + (row * LKH + seg * 8) * 2,
                 &Kg[(size_t)(kt * 64 + row) * HD_ + seg * 8]);
            cp16(vs + (row * LVH + seg * 8) * 2,
                 &Vg[(size_t)(kt * 64 + row) * HD_ + seg * 8]);
        }
        cp_commit();
    };

    // stage Q + first 3 KV tiles
#pragma unroll
    for (int it = 0; it < 4; it++) {
        int idx = tid + it * 256;
        int row = idx >> 3, seg = idx & 7;
        cp16(qps_u + (row * LQH + seg * 8) * 2, &Qg[row * HD_ + seg * 8]);
    }
    cp_commit();
    prefetch_kv(0, 0);
    prefetch_kv(1, 1);
    prefetch_kv(2, 2);
    cp_wait2();
    __syncthreads();

    // Q fragments (4 k16 steps), live whole kernel
    const uint32_t qa_adr = qps_u + ((r0 + (lane & 15)) * LQH + (lane >> 4) * 8) * 2;
    uint32_t qf[4][4];
#pragma unroll
    for (int ks = 0; ks < 4; ks++) ldsm4(qf[ks], qa_adr + ks * 32);

    // static per-stage ldsm base addresses
    uint32_t kb_base[4], vb_base[4];
#pragma unroll
    for (int st = 0; st < 4; st++) {
        uint32_t ks_u = kv_u + st * FKV_B;
        uint32_t vs_u = ks_u + 64 * LKH * 2;
        kb_base[st] = ks_u + ((lane & 15) * LKH + (lane >> 4) * 8) * 2;
        vb_base[st] = vs_u +
            (((lane & 7) + ((lane >> 3) & 1) * 8) * LVH + ((lane >> 4) & 1) * 8) * 2;
    }

    float o[8][4];
#pragma unroll
    for (int nt = 0; nt < 8; nt++)
#pragma unroll
        for (int j = 0; j < 4; j++) o[nt][j] = 0.f;
    float lacc[4] = {0.f, 0.f, 0.f, 0.f};   // row sums via P @ ones

    const int NT = N_ / 64;              // 32
#pragma unroll 4
    for (int kt = 0; kt < NT; kt++) {
        if (kt > 0) { cp_wait2(); __syncthreads(); }
        if (kt + 3 < NT) prefetch_kv((kt + 3) & 3, kt + 3);
        else cp_commit();
        const uint32_t kb_adr = kb_base[kt & 3];
        const uint32_t vb_adr = vb_base[kt & 3];

        // ---- S = Q K^T ----
        float cc[8][4];
#pragma unroll
        for (int nt = 0; nt < 8; nt++)
#pragma unroll
            for (int q = 0; q < 4; q++) cc[nt][q] = 0.f;
#pragma unroll
        for (int ks = 0; ks < 4; ks++) {
            const int kb = ks * 32;
#pragma unroll
            for (int g = 0; g < 4; g++) {
                uint32_t kk[4];
                ldsm4(kk, kb_adr + g * 16 * LKH * 2 + kb);
                mma_f16(cc[2 * g],     qf[ks], kk[0], kk[2]);
                mma_f16(cc[2 * g + 1], qf[ks], kk[1], kk[3]);
            }
        }

        // ---- P = exp2(S) on MUFU; pack to A-fragments ----
        uint32_t pa[4][4];
#pragma unroll
        for (int nt = 0; nt < 8; nt++) {
            float e0 = exp2_mufu(cc[nt][0]);
            float e1 = exp2_mufu(cc[nt][1]);
            float e2 = exp2_mufu(cc[nt][2]);
            float e3 = exp2_mufu(cc[nt][3]);
            const int ks = nt >> 1, hf = nt & 1;
            pa[ks][hf * 2 + 0] = pack_h2(e0, e1);   // row gid
            pa[ks][hf * 2 + 1] = pack_h2(e2, e3);   // row gid+8
        }

        // ---- O += P @ V;  lacc += P @ ones (row sums on tensor pipe) ----
#pragma unroll
        for (int ks = 0; ks < 4; ks++) {
            mma_f16(lacc, pa[ks], ONES_H2, ONES_H2);
#pragma unroll
            for (int g = 0; g < 4; g++) {
                uint32_t vv[4];
                ldsm4t(vv, vb_adr + ks * 16 * LVH * 2 + g * 32);
                mma_f16(o[2 * g],     pa[ks], vv[0], vv[1]);
                mma_f16(o[2 * g + 1], pa[ks], vv[2], vv[3]);
            }
        }
    }

    // epilogue: normalize (lacc[0]=row gid, lacc[2]=row gid+8), fp16, write
    const int bb = bh / H_, hh = bh - bb * H_;
    const float i0 = 1.f / lacc[0], i1 = 1.f / lacc[2];
    const int row_a = qt * 128 + r0 + gid;
    const int row_b = row_a + 8;
#pragma unroll
    for (int nt = 0; nt < 8; nt++) {
        int col = hh * HD_ + nt * 8 + tg * 2;
        *(__half2*)&g_AOh[((size_t)(bb * N_ + row_a)) * D_ + col] =
            __floats2half2_rn(o[nt][0] * i0, o[nt][1] * i0);
        *(__half2*)&g_AOh[((size_t)(bb * N_ + row_b)) * D_ + col] =
            __floats2half2_rn(o[nt][2] * i1, o[nt][3] * i1);
    }
}

// ---------------------------------------------------------------------------
// q_attn: single kernel, one block per (b,h), 1024 threads x 2 keys.
// ---------------------------------------------------------------------------
__global__ void __launch_bounds__(1024)
qattn_kernel(float* __restrict__ out1)
{
    const int bh = blockIdx.x;
    __shared__ float q0[64];
    __shared__ float red[1024];
    const int tid = threadIdx.x;
    if (tid < 64) q0[tid] = __half2float(g_Qh[((size_t)bh * N_) * HD_ + tid]);
    __syncthreads();

    float e[2];
    float sum = 0.f;
#pragma unroll
    for (int r = 0; r < 2; r++) {
        const int j = tid + r * 1024;
        const uint4* kp = (const uint4*)&g_Kh[((size_t)bh * N_ + j) * HD_];
        float s = 0.f;
#pragma unroll
        for (int i = 0; i < 8; i++) {
            uint4 u = kp[i];
            const __half2* h = (const __half2*)&u;
#pragma unroll
            for (int q = 0; q < 4; q++) {
                float2 f = __half22float2(h[q]);
                s += f.x * q0[i * 8 + 2 * q] + f.y * q0[i * 8 + 2 * q + 1];
            }
        }
        e[r] = exp2_mufu(s);
        sum += e[r];
    }
    red[tid] = sum; __syncthreads();
    for (int off = 512; off > 0; off >>= 1) {
        if (tid < off) red[tid] += red[tid + off];
        __syncthreads();
    }
    const float inv = 1.f / red[0];
    out1[(size_t)bh * N_ + tid]        = e[0] * inv;
    out1[(size_t)bh * N_ + tid + 1024] = e[1] * inv;
}

// ---------------------------------------------------------------------------
extern "C" void kernel_launch(void* const* d_in, const int* in_sizes, int n_in,
                              void* d_out, int out_size)
{
    const float* x      = (const float*)d_in[0];
    const float* w_qkv  = (const float*)d_in[1];
    const float* w_proj = (const float*)d_in[2];
    const float* b_proj = (const float*)d_in[3];
    float* out = (float*)d_out;
    float* out_qattn = out + ((size_t)out_size - (size_t)B_ * H_ * N_);

    const int gemm_smem  = 4 * GSTG_B;           // 81920
    const int flash_smem = FQP_B + 4 * FKV_B;    // 92160
    cudaFuncSetAttribute(mma_gemm<1>,
                         cudaFuncAttributeMaxDynamicSharedMemorySize, gemm_smem);
    cudaFuncSetAttribute(mma_gemm<0>,
                         cudaFuncAttributeMaxDynamicSharedMemorySize, gemm_smem);
    cudaFuncSetAttribute(flash_mma_kernel,
                         cudaFuncAttributeMaxDynamicSharedMemorySize, flash_smem);

    // 0) fused fp16 prepass
    {
        dim3 g(72, 24, 3);
        prepass<<<g, 256>>>(x, w_qkv, w_proj);
    }
    // 1) QKV GEMM -> g_Qh(xQS_)/g_Kh/g_Vh
    {
        dim3 grid((3 * D_) / 128, (B_ * N_) / 128);
        mma_gemm<1><<<grid, 256, gemm_smem>>>(nullptr, nullptr,
                                              B_ * N_, D_, 3 * D_);
    }
    // 2) q=0 attention row
    qattn_kernel<<<48, 1024>>>(out_qattn);
    // 3) Flash attention -> g_AOh
    {
        dim3 grid(N_ / 128, B_ * H_);
        flash_mma_kernel<<<grid, 256, flash_smem>>>();
    }
    // 4) Projection GEMM + bias -> float out
    {
        dim3 grid(D_ / 128, (B_ * N_) / 128);
        mma_gemm<0><<<grid, 256, gemm_smem>>>(b_proj, out,
                                              B_ * N_, D_, D_);
    }
}

// round 16
// speedup vs baseline: 7.3085x; 1.0186x over previous
#include <cuda_runtime.h>
#include <cuda_fp16.h>
#include <math.h>
#include <stdint.h>

#define B_ 4
#define N_ 2048
#define D_ 768
#define H_ 12
#define HD_ 64
#define QS_ 0.18033688011112042f   // 0.125 * log2(e)
#define SAH 40   // GEMM A/B smem stride (halves)
#define LQH 72   // flash Q stride (halves)
#define LKH 72
#define LVH 72

// fp16 scratch (allocation-free __device__ globals)
__device__ __half g_Xh [(size_t)B_*N_*D_];
__device__ __half g_Wqh[(size_t)3*D_*D_];     // W_qkv^T [3D][D]
__device__ __half g_Wph[(size_t)D_*D_];       // W_proj^T [D][D]
__device__ __half g_Qh [(size_t)B_*H_*N_*HD_]; // pre-scaled by QS_
__device__ __half g_Kh [(size_t)B_*H_*N_*HD_];
__device__ __half g_Vh [(size_t)B_*H_*N_*HD_]; // natural [key][hd]
__device__ __half g_AOh[(size_t)B_*N_*D_];

// ============================ helpers ======================================
__device__ __forceinline__ uint32_t smem_u32(const void* p) {
    uint32_t a;
    asm("{ .reg .u64 t; cvta.to.shared.u64 t, %1; cvt.u32.u64 %0, t; }"
        : "=r"(a) : "l"(p));
    return a;
}
__device__ __forceinline__ void cp16(uint32_t dst, const void* src) {
    asm volatile("cp.async.cg.shared.global [%0], [%1], 16;"
                 :: "r"(dst), "l"(src));
}
__device__ __forceinline__ void cp_commit() {
    asm volatile("cp.async.commit_group;");
}
__device__ __forceinline__ void cp_wait2() {
    asm volatile("cp.async.wait_group 2;");
}
__device__ __forceinline__ void ldsm4(uint32_t r[4], uint32_t addr) {
    asm volatile("ldmatrix.sync.aligned.m8n8.x4.shared.b16 {%0,%1,%2,%3}, [%4];"
                 : "=r"(r[0]), "=r"(r[1]), "=r"(r[2]), "=r"(r[3]) : "r"(addr));
}
__device__ __forceinline__ void ldsm4t(uint32_t r[4], uint32_t addr) {
    asm volatile("ldmatrix.sync.aligned.m8n8.x4.trans.shared.b16 {%0,%1,%2,%3}, [%4];"
                 : "=r"(r[0]), "=r"(r[1]), "=r"(r[2]), "=r"(r[3]) : "r"(addr));
}
__device__ __forceinline__ void mma_f16(float c[4], const uint32_t a[4],
                                        uint32_t b0, uint32_t b1) {
    asm volatile(
        "mma.sync.aligned.m16n8k16.row.col.f32.f16.f16.f32 "
        "{%0,%1,%2,%3}, {%4,%5,%6,%7}, {%8,%9}, {%0,%1,%2,%3};"
        : "+f"(c[0]), "+f"(c[1]), "+f"(c[2]), "+f"(c[3])
        : "r"(a[0]), "r"(a[1]), "r"(a[2]), "r"(a[3]), "r"(b0), "r"(b1));
}
__device__ __forceinline__ float exp2_mufu(float x) {
    float r;
    asm("ex2.approx.f32 %0, %1;" : "=f"(r) : "f"(x));
    return r;
}
__device__ __forceinline__ uint32_t pack_h2(float a, float b) {
    __half2 h = __floats2half2_rn(a, b);
    return *(uint32_t*)&h;
}

// ===========================================================================
// Fused pre-pass (grid (72, 24, 3)): z0/z1 weight transposes, z2 x convert.
// ===========================================================================
__global__ void __launch_bounds__(256)
prepass(const float* __restrict__ x, const float* __restrict__ wq,
        const float* __restrict__ wp)
{
    const int z = blockIdx.z;
    const int tid = threadIdx.x;
    if (z == 2) {
        const int total = (B_ * N_ * D_) / 4;
        const int stride = 72 * 24 * 256;
        for (int i = (blockIdx.x + blockIdx.y * 72) * 256 + tid; i < total;
             i += stride) {
            float4 v = ((const float4*)x)[i];
            __half2* d = (__half2*)&g_Xh[(size_t)i * 4];
            d[0] = __floats2half2_rn(v.x, v.y);
            d[1] = __floats2half2_rn(v.z, v.w);
        }
        return;
    }
    if (z == 1 && blockIdx.x >= D_ / 32) return;
    const float* src = z ? wp : wq;
    __half* dst = z ? g_Wph : g_Wqh;
    const int ND = z ? D_ : 3 * D_;
    __shared__ float t[32][33];
    const int tx = tid & 31, ty = tid >> 5;
    const int bx = blockIdx.x * 32, by = blockIdx.y * 32;
#pragma unroll
    for (int i = 0; i < 4; i++) {
        int k = by + ty + i * 8;
        t[ty + i * 8][tx] = src[(size_t)k * ND + bx + tx];
    }
    __syncthreads();
#pragma unroll
    for (int i = 0; i < 4; i++) {
        int n = bx + ty + i * 8;
        dst[(size_t)n * D_ + by + tx] = __float2half_rn(t[tx][ty + i * 8]);
    }
}

// ===========================================================================
// fp16 mma.sync GEMM (m16n8k16), 4-stage cp.async, ldsm frags. (passing)
// ===========================================================================
#define GSTG_B (2 * 128 * SAH * 2)   // stage bytes = 20480
template<int EPI>
__global__ void __launch_bounds__(256, 2)
mma_gemm(const float* __restrict__ bias, float* __restrict__ C,
         int M, int Kd, int Nn)
{
    const __half* A  = (EPI == 0) ? (const __half*)g_AOh : (const __half*)g_Xh;
    const __half* Bw = (EPI == 0) ? (const __half*)g_Wph : (const __half*)g_Wqh;
    extern __shared__ __half smh[];
    const uint32_t s_u32 = smem_u32(smh);
    const int tid = threadIdx.x;
    const int wid = tid >> 5, lane = tid & 31;
    const int gid = lane >> 2, tg = lane & 3;
    const int warp_m = wid & 3, warp_n = wid >> 2;
    const int m0 = blockIdx.y * 128, n0 = blockIdx.x * 128;

    float c[2][8][4];
#pragma unroll
    for (int mt = 0; mt < 2; mt++)
#pragma unroll
        for (int nt = 0; nt < 8; nt++)
#pragma unroll
            for (int j = 0; j < 4; j++) c[mt][nt][j] = 0.f;

    auto prefetch = [&](int stg, int k0) {
        uint32_t as = s_u32 + stg * GSTG_B;
        uint32_t bs = as + 128 * SAH * 2;
#pragma unroll
        for (int it = 0; it < 2; it++) {
            int idx = tid + it * 256;
            int row = idx >> 2, seg = idx & 3;
            cp16(as + (row * SAH + seg * 8) * 2,
                 &A[(size_t)(m0 + row) * Kd + k0 + seg * 8]);
            cp16(bs + (row * SAH + seg * 8) * 2,
                 &Bw[(size_t)(n0 + row) * Kd + k0 + seg * 8]);
        }
        cp_commit();
    };

    const int ntiles = Kd / 32;          // 24
    prefetch(0, 0);
    prefetch(1, 32);
    prefetch(2, 64);
#pragma unroll 1
    for (int t = 0; t < ntiles; t++) {
        cp_wait2();
        __syncthreads();
        if (t + 3 < ntiles) prefetch((t + 3) & 3, (t + 3) * 32);
        else cp_commit();
        const uint32_t as_u = s_u32 + (t & 3) * GSTG_B;
        const uint32_t bs_u = as_u + 128 * SAH * 2;
        const uint32_t a_adr = as_u + ((warp_m * 32 + (lane & 15)) * SAH + (lane >> 4) * 8) * 2;
        const uint32_t b_adr = bs_u + ((warp_n * 64 + (lane & 15)) * SAH + (lane >> 4) * 8) * 2;
#pragma unroll
        for (int ks = 0; ks < 2; ks++) {
            const int kb = ks * 32;
            uint32_t a0[4], a1[4];
            ldsm4(a0, a_adr + kb);
            ldsm4(a1, a_adr + 16 * SAH * 2 + kb);
#pragma unroll
            for (int j = 0; j < 4; j++) {
                uint32_t bb[4];
                ldsm4(bb, b_adr + j * 16 * SAH * 2 + kb);
                mma_f16(c[0][2 * j],     a0, bb[0], bb[2]);
                mma_f16(c[0][2 * j + 1], a0, bb[1], bb[3]);
                mma_f16(c[1][2 * j],     a1, bb[0], bb[2]);
                mma_f16(c[1][2 * j + 1], a1, bb[1], bb[3]);
            }
        }
    }

#pragma unroll
    for (int mt = 0; mt < 2; mt++) {
#pragma unroll
        for (int nt = 0; nt < 8; nt++) {
            int r0 = m0 + warp_m * 32 + mt * 16 + gid;
            int col = n0 + warp_n * 64 + nt * 8 + tg * 2;
#pragma unroll
            for (int h = 0; h < 2; h++) {
                int r = r0 + h * 8;
                float vx = c[mt][nt][h * 2 + 0];
                float vy = c[mt][nt][h * 2 + 1];
                if (EPI == 0) {
                    float2 v; v.x = vx + bias[col]; v.y = vy + bias[col + 1];
                    *(float2*)&C[(size_t)r * Nn + col] = v;
                } else {
                    int bb = r >> 11, tok = r & 2047;
                    int which = col / D_;
                    int rem = col - which * D_;
                    int hh = rem >> 6, hd = rem & 63;
                    __half* dst = (which == 0) ? g_Qh : (which == 1) ? g_Kh : g_Vh;
                    float sc = (which == 0) ? QS_ : 1.f;
                    *(__half2*)&dst[(((size_t)(bb * H_ + hh)) * N_ + tok) * HD_ + hd] =
                        __floats2half2_rn(vx * sc, vy * sc);
                }
            }
        }
    }
}

// ===========================================================================
// Flash attention fp16: Br=256 (32 q-rows/warp, K/V fragments shared across
// both 16-row groups -> LDSM bytes per q-row halve), Bc=64, 4-stage K/V,
// P in registers, row sums via tensor ones-trick. 1 CTA/SM.
// ===========================================================================
#define FQP_B (256 * LQH * 2)        // 36864 bytes (Q staging)
#define FKV_B (2 * 64 * LKH * 2)     // K+V per stage = 18432 bytes
#define ONES_H2 0x3C003C00u          // half2(1.0, 1.0)
__global__ void __launch_bounds__(256, 1)
flash_mma_kernel()
{
    extern __shared__ __half smf[];
    const uint32_t qps_u = smem_u32(smf);
    const uint32_t kv_u  = qps_u + FQP_B;    // 4 stages of (K, V)

    const int tid = threadIdx.x;
    const int wid = tid >> 5, lane = tid & 31;
    const int gid = lane >> 2, tg = lane & 3;
    const int bh = blockIdx.y, qt = blockIdx.x;
    const int r0 = wid * 32;
    const __half* Qg = g_Qh + ((size_t)bh * N_ + qt * 256) * HD_;
    const __half* Kg = g_Kh + (size_t)bh * N_ * HD_;
    const __half* Vg = g_Vh + (size_t)bh * N_ * HD_;

    auto prefetch_kv = [&](int stg, int kt) {
        uint32_t ks = kv_u + stg * FKV_B;
        uint32_t vs = ks + 64 * LKH * 2;
#pragma unroll
        for (int it = 0; it < 2; it++) {
            int idx = tid + it * 256;
            int row = idx >> 3, seg = idx & 7;
            cp16(ks + (row * LKH + seg * 8) * 2,
                 &Kg[(size_t)(kt * 64 + row) * HD_ + seg * 8]);
            cp16(vs + (row * LVH + seg * 8) * 2,
                 &Vg[(size_t)(kt * 64 + row) * HD_ + seg * 8]);
        }
        cp_commit();
    };

    // stage Q (256 rows) + first 3 KV tiles
#pragma unroll
    for (int it = 0; it < 8; it++) {
        int idx = tid + it * 256;
        int row = idx >> 3, seg = idx & 7;
        cp16(qps_u + (row * LQH + seg * 8) * 2, &Qg[row * HD_ + seg * 8]);
    }
    cp_commit();
    prefetch_kv(0, 0);
    prefetch_kv(1, 1);
    prefetch_kv(2, 2);
    cp_wait2();
    __syncthreads();

    // Q fragments: 2 row groups x 4 k16 steps, register-resident
    const uint32_t qa_adr = qps_u + ((r0 + (lane & 15)) * LQH + (lane >> 4) * 8) * 2;
    uint32_t qf[2][4][4];
#pragma unroll
    for (int mt = 0; mt < 2; mt++)
#pragma unroll
        for (int ks = 0; ks < 4; ks++)
            ldsm4(qf[mt][ks], qa_adr + mt * 16 * LQH * 2 + ks * 32);

    // static per-stage ldsm base addresses
    uint32_t kb_base[4], vb_base[4];
#pragma unroll
    for (int st = 0; st < 4; st++) {
        uint32_t ks_u = kv_u + st * FKV_B;
        uint32_t vs_u = ks_u + 64 * LKH * 2;
        kb_base[st] = ks_u + ((lane & 15) * LKH + (lane >> 4) * 8) * 2;
        vb_base[st] = vs_u +
            (((lane & 7) + ((lane >> 3) & 1) * 8) * LVH + ((lane >> 4) & 1) * 8) * 2;
    }

    float o[2][8][4];
#pragma unroll
    for (int mt = 0; mt < 2; mt++)
#pragma unroll
        for (int nt = 0; nt < 8; nt++)
#pragma unroll
            for (int j = 0; j < 4; j++) o[mt][nt][j] = 0.f;
    float lacc[2][4] = {{0.f,0.f,0.f,0.f},{0.f,0.f,0.f,0.f}};

    const int NT = N_ / 64;              // 32
#pragma unroll 4
    for (int kt = 0; kt < NT; kt++) {
        if (kt > 0) { cp_wait2(); __syncthreads(); }
        if (kt + 3 < NT) prefetch_kv((kt + 3) & 3, kt + 3);
        else cp_commit();
        const uint32_t kb_adr = kb_base[kt & 3];
        const uint32_t vb_adr = vb_base[kt & 3];

        // ---- S = Q K^T for both row groups (K fragments loaded ONCE) ----
        float cc[2][8][4];
#pragma unroll
        for (int mt = 0; mt < 2; mt++)
#pragma unroll
            for (int nt = 0; nt < 8; nt++)
#pragma unroll
                for (int q = 0; q < 4; q++) cc[mt][nt][q] = 0.f;
#pragma unroll
        for (int ks = 0; ks < 4; ks++) {
            const int kb = ks * 32;
#pragma unroll
            for (int g = 0; g < 4; g++) {
                uint32_t kk[4];
                ldsm4(kk, kb_adr + g * 16 * LKH * 2 + kb);
                mma_f16(cc[0][2 * g],     qf[0][ks], kk[0], kk[2]);
                mma_f16(cc[0][2 * g + 1], qf[0][ks], kk[1], kk[3]);
                mma_f16(cc[1][2 * g],     qf[1][ks], kk[0], kk[2]);
                mma_f16(cc[1][2 * g + 1], qf[1][ks], kk[1], kk[3]);
            }
        }

        // ---- P = exp2(S) on MUFU; pack to A-fragments ----
        uint32_t pa[2][4][4];
#pragma unroll
        for (int mt = 0; mt < 2; mt++)
#pragma unroll
            for (int nt = 0; nt < 8; nt++) {
                float e0 = exp2_mufu(cc[mt][nt][0]);
                float e1 = exp2_mufu(cc[mt][nt][1]);
                float e2 = exp2_mufu(cc[mt][nt][2]);
                float e3 = exp2_mufu(cc[mt][nt][3]);
                const int ks = nt >> 1, hf = nt & 1;
                pa[mt][ks][hf * 2 + 0] = pack_h2(e0, e1);
                pa[mt][ks][hf * 2 + 1] = pack_h2(e2, e3);
            }

        // ---- O += P @ V; lacc += P @ ones (V fragments loaded ONCE) ----
#pragma unroll
        for (int ks = 0; ks < 4; ks++) {
            mma_f16(lacc[0], pa[0][ks], ONES_H2, ONES_H2);
            mma_f16(lacc[1], pa[1][ks], ONES_H2, ONES_H2);
#pragma unroll
            for (int g = 0; g < 4; g++) {
                uint32_t vv[4];
                ldsm4t(vv, vb_adr + ks * 16 * LVH * 2 + g * 32);
                mma_f16(o[0][2 * g],     pa[0][ks], vv[0], vv[1]);
                mma_f16(o[0][2 * g + 1], pa[0][ks], vv[2], vv[3]);
                mma_f16(o[1][2 * g],     pa[1][ks], vv[0], vv[1]);
                mma_f16(o[1][2 * g + 1], pa[1][ks], vv[2], vv[3]);
            }
        }
    }

    // epilogue: normalize per row group, fp16, write (b, n, h*64+hd)
    const int bb = bh / H_, hh = bh - bb * H_;
#pragma unroll
    for (int mt = 0; mt < 2; mt++) {
        const float i0 = 1.f / lacc[mt][0], i1 = 1.f / lacc[mt][2];
        const int row_a = qt * 256 + r0 + mt * 16 + gid;
        const int row_b = row_a + 8;
#pragma unroll
        for (int nt = 0; nt < 8; nt++) {
            int col = hh * HD_ + nt * 8 + tg * 2;
            *(__half2*)&g_AOh[((size_t)(bb * N_ + row_a)) * D_ + col] =
                __floats2half2_rn(o[mt][nt][0] * i0, o[mt][nt][1] * i0);
            *(__half2*)&g_AOh[((size_t)(bb * N_ + row_b)) * D_ + col] =
                __floats2half2_rn(o[mt][nt][2] * i1, o[mt][nt][3] * i1);
        }
    }
}

// ---------------------------------------------------------------------------
// q_attn: single kernel, one block per (b,h), 1024 threads x 2 keys.
// ---------------------------------------------------------------------------
__global__ void __launch_bounds__(1024)
qattn_kernel(float* __restrict__ out1)
{
    const int bh = blockIdx.x;
    __shared__ float q0[64];
    __shared__ float red[1024];
    const int tid = threadIdx.x;
    if (tid < 64) q0[tid] = __half2float(g_Qh[((size_t)bh * N_) * HD_ + tid]);
    __syncthreads();

    float e[2];
    float sum = 0.f;
#pragma unroll
    for (int r = 0; r < 2; r++) {
        const int j = tid + r * 1024;
        const uint4* kp = (const uint4*)&g_Kh[((size_t)bh * N_ + j) * HD_];
        float s = 0.f;
#pragma unroll
        for (int i = 0; i < 8; i++) {
            uint4 u = kp[i];
            const __half2* h = (const __half2*)&u;
#pragma unroll
            for (int q = 0; q < 4; q++) {
                float2 f = __half22float2(h[q]);
                s += f.x * q0[i * 8 + 2 * q] + f.y * q0[i * 8 + 2 * q + 1];
            }
        }
        e[r] = exp2_mufu(s);
        sum += e[r];
    }
    red[tid] = sum; __syncthreads();
    for (int off = 512; off > 0; off >>= 1) {
        if (tid < off) red[tid] += red[tid + off];
        __syncthreads();
    }
    const float inv = 1.f / red[0];
    out1[(size_t)bh * N_ + tid]        = e[0] * inv;
    out1[(size_t)bh * N_ + tid + 1024] = e[1] * inv;
}

// ---------------------------------------------------------------------------
extern "C" void kernel_launch(void* const* d_in, const int* in_sizes, int n_in,
                              void* d_out, int out_size)
{
    const float* x      = (const float*)d_in[0];
    const float* w_qkv  = (const float*)d_in[1];
    const float* w_proj = (const float*)d_in[2];
    const float* b_proj = (const float*)d_in[3];
    float* out = (float*)d_out;
    float* out_qattn = out + ((size_t)out_size - (size_t)B_ * H_ * N_);

    const int gemm_smem  = 4 * GSTG_B;           // 81920
    const int flash_smem = FQP_B + 4 * FKV_B;    // 110592
    cudaFuncSetAttribute(mma_gemm<1>,
                         cudaFuncAttributeMaxDynamicSharedMemorySize, gemm_smem);
    cudaFuncSetAttribute(mma_gemm<0>,
                         cudaFuncAttributeMaxDynamicSharedMemorySize, gemm_smem);
    cudaFuncSetAttribute(flash_mma_kernel,
                         cudaFuncAttributeMaxDynamicSharedMemorySize, flash_smem);

    // 0) fused fp16 prepass
    {
        dim3 g(72, 24, 3);
        prepass<<<g, 256>>>(x, w_qkv, w_proj);
    }
    // 1) QKV GEMM -> g_Qh(xQS_)/g_Kh/g_Vh
    {
        dim3 grid((3 * D_) / 128, (B_ * N_) / 128);
        mma_gemm<1><<<grid, 256, gemm_smem>>>(nullptr, nullptr,
                                              B_ * N_, D_, 3 * D_);
    }
    // 2) q=0 attention row
    qattn_kernel<<<48, 1024>>>(out_qattn);
    // 3) Flash attention (Br=256) -> g_AOh
    {
        dim3 grid(N_ / 256, B_ * H_);
        flash_mma_kernel<<<grid, 256, flash_smem>>>();
    }
    // 4) Projection GEMM + bias -> float out
    {
        dim3 grid(D_ / 128, (B_ * N_) / 128);
        mma_gemm<0><<<grid, 256, gemm_smem>>>(b_proj, out,
                                              B_ * N_, D_, D_);
    }
}